// round 1
// baseline (speedup 1.0000x reference)
#include <cuda_runtime.h>

#define HEADS  8
#define DIMH   64
#define BATCH  16
#define CDIM   512
#define HW     4096
#define HIDDEN 512
#define OQKV   1536
#define SPLIT  8

// ---------------- scratch (no allocations allowed) ----------------
__device__ float g_qkv[(size_t)BATCH * OQKV * HW];            // 402 MB
__device__ float g_ctx_part[(size_t)SPLIT * BATCH * HEADS * DIMH * DIMH]; // 16.8 MB
__device__ float g_ctx[(size_t)BATCH * HEADS * DIMH * DIMH];  // 2.1 MB
__device__ float g_out[(size_t)BATCH * HIDDEN * HW];          // 134 MB

// ---------------- packed f32x2 helpers (2x fp32 FMA rate on sm_103a) ----
__device__ __forceinline__ unsigned long long f32x2_dup(float a) {
    unsigned long long r;
    asm("mov.b64 %0, {%1, %1};" : "=l"(r) : "f"(a));
    return r;
}
__device__ __forceinline__ unsigned long long f32x2_fma(unsigned long long a,
                                                        unsigned long long b,
                                                        unsigned long long c) {
    unsigned long long d;
    asm("fma.rn.f32x2 %0, %1, %2, %3;" : "=l"(d) : "l"(a), "l"(b), "l"(c));
    return d;
}
__device__ __forceinline__ float2 f32x2_unpack(unsigned long long v) {
    float2 f;
    asm("mov.b64 {%0, %1}, %2;" : "=f"(f.x), "=f"(f.y) : "l"(v));
    return f;
}

// ---------------- batched SGEMM: C[z] = A @ B[z] (+bias) ----------------
// A: [M,K] row-major, shared across batch. B: [K,N] per batch. C: [M,N].
// BM=BN=128, BK=16, 256 threads, 8x8 per thread via f32x2 pairs.
__global__ __launch_bounds__(256) void sgemm_kernel(
    const float* __restrict__ A, const float* __restrict__ B,
    float* __restrict__ C, const float* __restrict__ bias,
    int M, int N, int K, long strideB, long strideC)
{
    __shared__ float As[16][132];   // [k][m], pad 4 keeps float4 alignment
    __shared__ float Bs[16][128];   // [k][n]

    const int t  = threadIdx.x;
    const int tx = t & 15;          // n-group
    const int ty = t >> 4;          // m-group
    const long zb = blockIdx.z;
    const float* Bp = B + zb * strideB;
    float*       Cp = C + zb * strideC;
    const int m0 = blockIdx.y * 128;
    const int n0 = blockIdx.x * 128;

    unsigned long long acc[8][4];
    #pragma unroll
    for (int i = 0; i < 8; i++)
        #pragma unroll
        for (int j = 0; j < 4; j++) acc[i][j] = 0ull;   // (+0.0f, +0.0f)

    for (int k0 = 0; k0 < K; k0 += 16) {
        #pragma unroll
        for (int i = 0; i < 2; i++) {               // A tile 128x16
            int idx = t + i * 256;
            int row = idx >> 2;
            int kc  = (idx & 3) << 2;
            float4 v = *(const float4*)(A + (long)(m0 + row) * K + (k0 + kc));
            As[kc + 0][row] = v.x; As[kc + 1][row] = v.y;
            As[kc + 2][row] = v.z; As[kc + 3][row] = v.w;
        }
        #pragma unroll
        for (int i = 0; i < 2; i++) {               // B tile 16x128
            int idx = t + i * 256;
            int row = idx >> 5;
            int col = (idx & 31) << 2;
            *(float4*)&Bs[row][col] =
                *(const float4*)(Bp + (long)(k0 + row) * N + (n0 + col));
        }
        __syncthreads();

        #pragma unroll
        for (int kk = 0; kk < 16; kk++) {
            float4 a0 = *(const float4*)&As[kk][ty * 4];
            float4 a1 = *(const float4*)&As[kk][64 + ty * 4];
            const unsigned long long* b0 =
                (const unsigned long long*)&Bs[kk][tx * 4];
            const unsigned long long* b1 =
                (const unsigned long long*)&Bs[kk][64 + tx * 4];
            unsigned long long bp0 = b0[0], bp1 = b0[1];
            unsigned long long bp2 = b1[0], bp3 = b1[1];
            float av[8] = {a0.x, a0.y, a0.z, a0.w, a1.x, a1.y, a1.z, a1.w};
            #pragma unroll
            for (int i = 0; i < 8; i++) {
                unsigned long long ap = f32x2_dup(av[i]);
                acc[i][0] = f32x2_fma(ap, bp0, acc[i][0]);
                acc[i][1] = f32x2_fma(ap, bp1, acc[i][1]);
                acc[i][2] = f32x2_fma(ap, bp2, acc[i][2]);
                acc[i][3] = f32x2_fma(ap, bp3, acc[i][3]);
            }
        }
        __syncthreads();
    }

    #pragma unroll
    for (int i = 0; i < 8; i++) {
        int mr = (i < 4) ? (ty * 4 + i) : (64 + ty * 4 + (i - 4));
        int m  = m0 + mr;
        float bv = bias ? bias[m] : 0.0f;
        float2 p0 = f32x2_unpack(acc[i][0]);
        float2 p1 = f32x2_unpack(acc[i][1]);
        float2 p2 = f32x2_unpack(acc[i][2]);
        float2 p3 = f32x2_unpack(acc[i][3]);
        float* cr = Cp + (long)m * N + n0;
        *(float4*)(cr + tx * 4)      = make_float4(p0.x + bv, p0.y + bv, p1.x + bv, p1.y + bv);
        *(float4*)(cr + 64 + tx * 4) = make_float4(p2.x + bv, p2.y + bv, p3.x + bv, p3.y + bv);
    }
}

// ---------------- softmax over k rows (length 4096) ----------------
__device__ __forceinline__ float warp_rmax(float v) {
    #pragma unroll
    for (int o = 16; o; o >>= 1) v = fmaxf(v, __shfl_xor_sync(0xffffffffu, v, o));
    return v;
}
__device__ __forceinline__ float warp_rsum(float v) {
    #pragma unroll
    for (int o = 16; o; o >>= 1) v += __shfl_xor_sync(0xffffffffu, v, o);
    return v;
}

__global__ __launch_bounds__(256) void softmax_kernel(float* __restrict__ qkv)
{
    int row = blockIdx.x;          // 0..8191 = b*512 + ch
    int b   = row >> 9;
    int ch  = row & 511;
    float4* p = (float4*)(qkv + (long)b * OQKV * HW + (long)(HIDDEN + ch) * HW);
    int t = threadIdx.x;

    float4 v[4];
    float m = -1e30f;
    #pragma unroll
    for (int i = 0; i < 4; i++) {
        v[i] = p[t + i * 256];
        m = fmaxf(m, fmaxf(fmaxf(v[i].x, v[i].y), fmaxf(v[i].z, v[i].w)));
    }
    __shared__ float red[8];
    m = warp_rmax(m);
    if ((t & 31) == 0) red[t >> 5] = m;
    __syncthreads();
    float bm = red[0];
    #pragma unroll
    for (int i = 1; i < 8; i++) bm = fmaxf(bm, red[i]);

    float s = 0.f;
    #pragma unroll
    for (int i = 0; i < 4; i++) {
        v[i].x = __expf(v[i].x - bm); v[i].y = __expf(v[i].y - bm);
        v[i].z = __expf(v[i].z - bm); v[i].w = __expf(v[i].w - bm);
        s += v[i].x + v[i].y + v[i].z + v[i].w;
    }
    s = warp_rsum(s);
    __syncthreads();                 // red reuse
    if ((t & 31) == 0) red[t >> 5] = s;
    __syncthreads();
    float bs = 0.f;
    #pragma unroll
    for (int i = 0; i < 8; i++) bs += red[i];
    float inv = 1.0f / bs;
    #pragma unroll
    for (int i = 0; i < 4; i++) {
        v[i].x *= inv; v[i].y *= inv; v[i].z *= inv; v[i].w *= inv;
        p[t + i * 256] = v[i];
    }
}

// ---------------- context[c,d] = sum_n k[c,n] * v[d,n] (split-K, no atomics) ----
__global__ __launch_bounds__(256) void ctx_kernel(const float* __restrict__ qkv,
                                                  float* __restrict__ part)
{
    __shared__ float Ks[64][65];
    __shared__ float Vs[64][65];
    int bh = blockIdx.y;             // b*8 + h
    int b = bh >> 3, h = bh & 7;
    int split = blockIdx.x;          // 0..7
    const float* kb = qkv + (long)b * OQKV * HW + (long)(HIDDEN + h * DIMH) * HW;
    const float* vb = qkv + (long)b * OQKV * HW + (long)(2 * HIDDEN + h * DIMH) * HW;
    int t = threadIdx.x, tx = t & 15, ty = t >> 4;

    float acc[4][4] = {};
    for (int chunk = 0; chunk < 8; chunk++) {
        int n0 = split * 512 + chunk * 64;
        #pragma unroll
        for (int i = 0; i < 4; i++) {
            int idx = t + i * 256;
            int row = idx >> 4;
            int col = (idx & 15) << 2;
            float4 kv = *(const float4*)(kb + (long)row * HW + n0 + col);
            Ks[row][col] = kv.x; Ks[row][col + 1] = kv.y;
            Ks[row][col + 2] = kv.z; Ks[row][col + 3] = kv.w;
            float4 vv = *(const float4*)(vb + (long)row * HW + n0 + col);
            Vs[row][col] = vv.x; Vs[row][col + 1] = vv.y;
            Vs[row][col + 2] = vv.z; Vs[row][col + 3] = vv.w;
        }
        __syncthreads();
        #pragma unroll
        for (int nn = 0; nn < 64; nn++) {
            float a[4], bb[4];
            #pragma unroll
            for (int i = 0; i < 4; i++) a[i]  = Ks[ty * 4 + i][nn];
            #pragma unroll
            for (int j = 0; j < 4; j++) bb[j] = Vs[tx * 4 + j][nn];
            #pragma unroll
            for (int i = 0; i < 4; i++)
                #pragma unroll
                for (int j = 0; j < 4; j++) acc[i][j] += a[i] * bb[j];
        }
        __syncthreads();
    }
    float* dst = part + ((long)split * 128 + bh) * 4096;
    #pragma unroll
    for (int i = 0; i < 4; i++)
        #pragma unroll
        for (int j = 0; j < 4; j++)
            dst[(ty * 4 + i) * 64 + (tx * 4 + j)] = acc[i][j];
}

__global__ __launch_bounds__(256) void ctx_reduce_kernel(const float* __restrict__ part,
                                                         float* __restrict__ ctx)
{
    long i = (long)blockIdx.x * 256 + threadIdx.x;   // 524288 total
    float s = 0.f;
    #pragma unroll
    for (int sp = 0; sp < SPLIT; sp++) s += part[(long)sp * 524288 + i];
    ctx[i] = s;
}

// ---------------- out[d,n] = sum_c ctx[c,d] * q[c,n] ----------------
__global__ __launch_bounds__(256) void attnout_kernel(const float* __restrict__ ctx,
                                                      const float* __restrict__ qkv,
                                                      float* __restrict__ out)
{
    __shared__ float Cs[32][65];     // [c][d]
    __shared__ float Qs[32][128];    // [c][n]
    int bh = blockIdx.y;
    int b = bh >> 3, h = bh & 7;
    int n0 = blockIdx.x * 128;
    const float* qb = qkv + (long)b * OQKV * HW + (long)(h * DIMH) * HW;
    const float* cb = ctx + (long)bh * 4096;
    float* ob = out + (long)b * HIDDEN * HW + (long)(h * DIMH) * HW;
    int t = threadIdx.x, tx = t & 15, ty = t >> 4;

    float acc[4][8] = {};
    for (int k0 = 0; k0 < 64; k0 += 32) {
        #pragma unroll
        for (int i = 0; i < 2; i++) {            // Cs 32x64
            int idx = t + i * 256;
            int row = idx >> 4;
            int col = (idx & 15) << 2;
            float4 cv = *(const float4*)(cb + (long)(k0 + row) * 64 + col);
            Cs[row][col] = cv.x; Cs[row][col + 1] = cv.y;
            Cs[row][col + 2] = cv.z; Cs[row][col + 3] = cv.w;
        }
        #pragma unroll
        for (int i = 0; i < 4; i++) {            // Qs 32x128
            int idx = t + i * 256;
            int row = idx >> 5;
            int col = (idx & 31) << 2;
            *(float4*)&Qs[row][col] =
                *(const float4*)(qb + (long)(k0 + row) * HW + n0 + col);
        }
        __syncthreads();
        #pragma unroll
        for (int kk = 0; kk < 32; kk++) {
            float a[4];
            #pragma unroll
            for (int i = 0; i < 4; i++) a[i] = Cs[kk][ty * 4 + i];
            float4 q0 = *(const float4*)&Qs[kk][tx * 4];
            float4 q1 = *(const float4*)&Qs[kk][64 + tx * 4];
            float bb[8] = {q0.x, q0.y, q0.z, q0.w, q1.x, q1.y, q1.z, q1.w};
            #pragma unroll
            for (int i = 0; i < 4; i++)
                #pragma unroll
                for (int j = 0; j < 8; j++) acc[i][j] += a[i] * bb[j];
        }
        __syncthreads();
    }
    #pragma unroll
    for (int i = 0; i < 4; i++) {
        float* orow = ob + (long)(ty * 4 + i) * HW + n0;
        *(float4*)(orow + tx * 4)      = make_float4(acc[i][0], acc[i][1], acc[i][2], acc[i][3]);
        *(float4*)(orow + 64 + tx * 4) = make_float4(acc[i][4], acc[i][5], acc[i][6], acc[i][7]);
    }
}

// ---------------- launch ----------------
extern "C" void kernel_launch(void* const* d_in, const int* in_sizes, int n_in,
                              void* d_out, int out_size)
{
    const float* x      = (const float*)d_in[0];   // (16,512,64,64)
    const float* w_qkv  = (const float*)d_in[1];   // (1536,512)
    const float* w_out  = (const float*)d_in[2];   // (512,512)
    const float* b_out  = (const float*)d_in[3];   // (512,)
    float* y = (float*)d_out;                      // (16,512,64,64)

    float *qkv, *part, *ctx, *outp;
    cudaGetSymbolAddress((void**)&qkv,  g_qkv);
    cudaGetSymbolAddress((void**)&part, g_ctx_part);
    cudaGetSymbolAddress((void**)&ctx,  g_ctx);
    cudaGetSymbolAddress((void**)&outp, g_out);

    // 1. qkv = w_qkv @ x   (per batch)
    sgemm_kernel<<<dim3(32, 12, 16), 256>>>(w_qkv, x, qkv, nullptr,
                                            OQKV, HW, CDIM,
                                            (long)CDIM * HW, (long)OQKV * HW);
    // 2. softmax over k rows
    softmax_kernel<<<8192, 256>>>(qkv);
    // 3. context = k @ v^T (split over n, then reduce)
    ctx_kernel<<<dim3(SPLIT, 128), 256>>>(qkv, part);
    ctx_reduce_kernel<<<2048, 256>>>(part, ctx);
    // 4. out = ctx^T @ q
    attnout_kernel<<<dim3(32, 128), 256>>>(ctx, qkv, outp);
    // 5. y = w_out @ out + b_out
    sgemm_kernel<<<dim3(32, 4, 16), 256>>>(w_out, outp, y, b_out,
                                           HIDDEN, HW, HIDDEN,
                                           (long)HIDDEN * HW, (long)HIDDEN * HW);
}

// round 3
// speedup vs baseline: 1.7861x; 1.7861x over previous
#include <cuda_runtime.h>
#include <cuda_bf16.h>
#include <cstdint>

#define HEADS  8
#define DIMH   64
#define BATCH  16
#define CDIM   512
#define HW     4096
#define HIDDEN 512
#define OQKV   1536
#define SPLIT  8

// ---------------- scratch (no allocations allowed) ----------------
__device__ float g_qkv[(size_t)BATCH * OQKV * HW];            // 402 MB
__device__ float g_ctx_part[(size_t)SPLIT * BATCH * HEADS * DIMH * DIMH];
__device__ float g_ctx[(size_t)BATCH * HEADS * DIMH * DIMH];
__device__ float g_out[(size_t)BATCH * HIDDEN * HW];          // 134 MB
__device__ __nv_bfloat16 g_xt_hi[(size_t)BATCH * HW * CDIM];  // 67 MB each
__device__ __nv_bfloat16 g_xt_lo[(size_t)BATCH * HW * CDIM];
__device__ __nv_bfloat16 g_ot_hi[(size_t)BATCH * HW * HIDDEN];
__device__ __nv_bfloat16 g_ot_lo[(size_t)BATCH * HW * HIDDEN];
__device__ __nv_bfloat16 g_wq_hi[(size_t)OQKV * CDIM];
__device__ __nv_bfloat16 g_wq_lo[(size_t)OQKV * CDIM];
__device__ __nv_bfloat16 g_wo_hi[(size_t)HIDDEN * HIDDEN];
__device__ __nv_bfloat16 g_wo_lo[(size_t)HIDDEN * HIDDEN];

// ================= PTX helpers (sm_80-era, sm_103-base-target safe) =====
__device__ __forceinline__ uint32_t smem_u32(const void* p) {
    uint32_t a;
    asm("{ .reg .u64 t; cvta.to.shared.u64 t, %1; cvt.u32.u64 %0, t; }"
        : "=r"(a) : "l"(p));
    return a;
}
__device__ __forceinline__ void cp_async16(uint32_t dst, const void* src) {
    asm volatile("cp.async.cg.shared.global [%0], [%1], 16;"
                 :: "r"(dst), "l"(src));
}
#define CP_COMMIT() asm volatile("cp.async.commit_group;")
#define CP_WAIT(n)  asm volatile("cp.async.wait_group %0;" :: "n"(n))

__device__ __forceinline__ void ldmx4(uint32_t* r, uint32_t addr) {
    asm volatile("ldmatrix.sync.aligned.m8n8.x4.shared.b16 {%0,%1,%2,%3}, [%4];"
                 : "=r"(r[0]), "=r"(r[1]), "=r"(r[2]), "=r"(r[3]) : "r"(addr));
}
__device__ __forceinline__ void mma16816(float* d, const uint32_t* a,
                                         uint32_t b0, uint32_t b1) {
    asm volatile(
        "mma.sync.aligned.m16n8k16.row.col.f32.bf16.bf16.f32 "
        "{%0,%1,%2,%3}, {%4,%5,%6,%7}, {%8,%9}, {%0,%1,%2,%3};"
        : "+f"(d[0]), "+f"(d[1]), "+f"(d[2]), "+f"(d[3])
        : "r"(a[0]), "r"(a[1]), "r"(a[2]), "r"(a[3]), "r"(b0), "r"(b1));
}

// ================= bf16x3 HMMA GEMM =================
// C[z][M,N] = A[M,K] @ B[z][N,K]^T,  A/B as bf16 hi/lo splits.
// CTA 128x128, BK=32, 256 threads (8 warps, warp tile 64x32).
// SMEM rows padded to 80B -> conflict-free ldmatrix (80 mod 128 hits all 8 segs).
#define ROWB 80
#define HALF_BYTES (128 * ROWB)         // 10240 per operand half
#define BUF_BYTES  (4 * HALF_BYTES)     // Ahi|Alo|Bhi|Blo = 40960
#define GEMM_SMEM  (2 * BUF_BYTES)      // 81920

__global__ __launch_bounds__(256) void gemm_bf16x3_kernel(
    const __nv_bfloat16* __restrict__ Ahi, const __nv_bfloat16* __restrict__ Alo,
    const __nv_bfloat16* __restrict__ Bhi, const __nv_bfloat16* __restrict__ Blo,
    float* __restrict__ C, const float* __restrict__ bias,
    int M, int N, int K, long strideB, long strideC)
{
    extern __shared__ char smem[];
    const uint32_t sb = smem_u32(smem);

    const int t = threadIdx.x;
    const int lane = t & 31, wid = t >> 5;
    const int wr = wid & 1, wc = wid >> 1;          // warp tile: m 64, n 32
    const int m_off = wr * 64, n_off = wc * 32;
    const int m0 = blockIdx.y * 128, n0 = blockIdx.x * 128;
    const long z = blockIdx.z;
    const __nv_bfloat16* Bh = Bhi + z * strideB;
    const __nv_bfloat16* Bl = Blo + z * strideB;

    // per-thread load coords: 512 (row,chunk) pairs per 128x32 half-tile
    const int lrow0 = t >> 2, lch = t & 3;          // pass0: rows 0..63
    // ldmatrix base offsets (within a buffer)
    const uint32_t aBase = sb + (uint32_t)((m_off + (lane & 15)) * ROWB + (lane >> 4) * 16);
    const uint32_t bBase = sb + 2 * HALF_BYTES +
        (uint32_t)((n_off + (lane & 7) + ((lane >> 4) << 3)) * ROWB + ((lane >> 3) & 1) * 16);

    float acc[4][4][4];
    #pragma unroll
    for (int i = 0; i < 4; i++)
        #pragma unroll
        for (int j = 0; j < 4; j++)
            #pragma unroll
            for (int r = 0; r < 4; r++) acc[i][j][r] = 0.f;

    const int nst = K / 32;

    // ---- async stage loader ----
    auto load_stage = [&](int s) {
        const int k0 = s * 32;
        const uint32_t bufb = sb + (uint32_t)((s & 1) * BUF_BYTES);
        #pragma unroll
        for (int p = 0; p < 2; p++) {
            int row = lrow0 + p * 64;
            uint32_t dA = bufb + (uint32_t)(row * ROWB + lch * 16);
            const long srcA = (long)(m0 + row) * K + k0 + lch * 8;
            cp_async16(dA,                  Ahi + srcA);
            cp_async16(dA + HALF_BYTES,     Alo + srcA);
            uint32_t dB = bufb + 2 * HALF_BYTES + (uint32_t)(row * ROWB + lch * 16);
            const long srcB = (long)(n0 + row) * K + k0 + lch * 8;
            cp_async16(dB,                  Bh + srcB);
            cp_async16(dB + HALF_BYTES,     Bl + srcB);
        }
        CP_COMMIT();
    };

    load_stage(0);

    for (int s = 0; s < nst; s++) {
        if (s + 1 < nst) { load_stage(s + 1); CP_WAIT(1); }
        else             { CP_WAIT(0); }
        __syncthreads();

        const uint32_t bufo = (uint32_t)((s & 1) * BUF_BYTES);
        #pragma unroll
        for (int ks = 0; ks < 2; ks++) {
            // B fragments: 2 x4 per half (n16 each)
            uint32_t bh[8], bl[8];
            #pragma unroll
            for (int nj = 0; nj < 2; nj++) {
                uint32_t ba = bBase + bufo + (uint32_t)(nj * 16 * ROWB + ks * 32);
                ldmx4(&bh[nj * 4], ba);
                ldmx4(&bl[nj * 4], ba + HALF_BYTES);
            }
            #pragma unroll
            for (int mi = 0; mi < 4; mi++) {
                uint32_t ah[4], al[4];
                uint32_t aa = aBase + bufo + (uint32_t)(mi * 16 * ROWB + ks * 32);
                ldmx4(ah, aa);
                ldmx4(al, aa + HALF_BYTES);
                #pragma unroll
                for (int j = 0; j < 4; j++) {
                    uint32_t b0h = bh[(j >> 1) * 4 + (j & 1) * 2];
                    uint32_t b1h = bh[(j >> 1) * 4 + (j & 1) * 2 + 1];
                    uint32_t b0l = bl[(j >> 1) * 4 + (j & 1) * 2];
                    uint32_t b1l = bl[(j >> 1) * 4 + (j & 1) * 2 + 1];
                    mma16816(acc[mi][j], ah, b0h, b1h);   // hi*hi
                    mma16816(acc[mi][j], ah, b0l, b1l);   // hi*lo
                    mma16816(acc[mi][j], al, b0h, b1h);   // lo*hi
                }
            }
        }
        __syncthreads();
    }

    // ---- epilogue ----
    float* Cz = C + z * strideC;
    const int mrow = m0 + m_off + (lane >> 2);
    const int ncol = n0 + n_off + (lane & 3) * 2;
    #pragma unroll
    for (int mi = 0; mi < 4; mi++) {
        int r0 = mrow + mi * 16;
        float bv0 = bias ? bias[r0] : 0.f;
        float bv1 = bias ? bias[r0 + 8] : 0.f;
        #pragma unroll
        for (int j = 0; j < 4; j++) {
            int cc = ncol + j * 8;
            *(float2*)(Cz + (long)r0 * N + cc) =
                make_float2(acc[mi][j][0] + bv0, acc[mi][j][1] + bv0);
            *(float2*)(Cz + (long)(r0 + 8) * N + cc) =
                make_float2(acc[mi][j][2] + bv1, acc[mi][j][3] + bv1);
        }
    }
}

// ================= conversion kernels =================
__global__ __launch_bounds__(256) void conv_split_kernel(
    const float* __restrict__ w, __nv_bfloat16* __restrict__ hi,
    __nv_bfloat16* __restrict__ lo, int n)
{
    int i = blockIdx.x * 256 + threadIdx.x;
    if (i < n) {
        float v = w[i];
        __nv_bfloat16 h = __float2bfloat16_rn(v);
        hi[i] = h;
        lo[i] = __float2bfloat16_rn(v - __bfloat162float(h));
    }
}

// in: [z][R][Cc] f32 -> out hi/lo: [z][Cc][R] bf16 (transpose + split)
__global__ __launch_bounds__(256) void trans_split_kernel(
    const float* __restrict__ in, __nv_bfloat16* __restrict__ ohi,
    __nv_bfloat16* __restrict__ olo, int R, int Cc)
{
    __shared__ float tile[32][33];
    const int z = blockIdx.z;
    const int c0 = blockIdx.x * 32, r0 = blockIdx.y * 32;
    const int tx = threadIdx.x & 31, ty = threadIdx.x >> 5;
    const float* ip = in + (long)z * R * Cc;
    #pragma unroll
    for (int i = 0; i < 4; i++)
        tile[ty + 8 * i][tx] = ip[(long)(r0 + ty + 8 * i) * Cc + c0 + tx];
    __syncthreads();
    #pragma unroll
    for (int i = 0; i < 4; i++) {
        float v = tile[tx][ty + 8 * i];
        __nv_bfloat16 h = __float2bfloat16_rn(v);
        __nv_bfloat16 l = __float2bfloat16_rn(v - __bfloat162float(h));
        long o = ((long)z * Cc + c0 + ty + 8 * i) * R + r0 + tx;
        ohi[o] = h;
        olo[o] = l;
    }
}

// ================= softmax over k rows (length 4096) =================
__device__ __forceinline__ float warp_rmax(float v) {
    #pragma unroll
    for (int o = 16; o; o >>= 1) v = fmaxf(v, __shfl_xor_sync(0xffffffffu, v, o));
    return v;
}
__device__ __forceinline__ float warp_rsum(float v) {
    #pragma unroll
    for (int o = 16; o; o >>= 1) v += __shfl_xor_sync(0xffffffffu, v, o);
    return v;
}

__global__ __launch_bounds__(256) void softmax_kernel(float* __restrict__ qkv)
{
    int row = blockIdx.x;
    int b = row >> 9, ch = row & 511;
    float4* p = (float4*)(qkv + (long)b * OQKV * HW + (long)(HIDDEN + ch) * HW);
    int t = threadIdx.x;

    float4 v[4];
    float m = -1e30f;
    #pragma unroll
    for (int i = 0; i < 4; i++) {
        v[i] = p[t + i * 256];
        m = fmaxf(m, fmaxf(fmaxf(v[i].x, v[i].y), fmaxf(v[i].z, v[i].w)));
    }
    __shared__ float red[8];
    m = warp_rmax(m);
    if ((t & 31) == 0) red[t >> 5] = m;
    __syncthreads();
    float bm = red[0];
    #pragma unroll
    for (int i = 1; i < 8; i++) bm = fmaxf(bm, red[i]);

    float s = 0.f;
    #pragma unroll
    for (int i = 0; i < 4; i++) {
        v[i].x = __expf(v[i].x - bm); v[i].y = __expf(v[i].y - bm);
        v[i].z = __expf(v[i].z - bm); v[i].w = __expf(v[i].w - bm);
        s += v[i].x + v[i].y + v[i].z + v[i].w;
    }
    s = warp_rsum(s);
    __syncthreads();
    if ((t & 31) == 0) red[t >> 5] = s;
    __syncthreads();
    float bs = 0.f;
    #pragma unroll
    for (int i = 0; i < 8; i++) bs += red[i];
    float inv = 1.0f / bs;
    #pragma unroll
    for (int i = 0; i < 4; i++) {
        v[i].x *= inv; v[i].y *= inv; v[i].z *= inv; v[i].w *= inv;
        p[t + i * 256] = v[i];
    }
}

// ================= context = k @ v^T (split-K) =================
__global__ __launch_bounds__(256) void ctx_kernel(const float* __restrict__ qkv,
                                                  float* __restrict__ part)
{
    __shared__ float Ks[64][65];
    __shared__ float Vs[64][65];
    int bh = blockIdx.y;
    int b = bh >> 3, h = bh & 7;
    int split = blockIdx.x;
    const float* kb = qkv + (long)b * OQKV * HW + (long)(HIDDEN + h * DIMH) * HW;
    const float* vb = qkv + (long)b * OQKV * HW + (long)(2 * HIDDEN + h * DIMH) * HW;
    int t = threadIdx.x, tx = t & 15, ty = t >> 4;

    float acc[4][4] = {};
    for (int chunk = 0; chunk < 8; chunk++) {
        int n0 = split * 512 + chunk * 64;
        #pragma unroll
        for (int i = 0; i < 4; i++) {
            int idx = t + i * 256;
            int row = idx >> 4;
            int col = (idx & 15) << 2;
            float4 kv = *(const float4*)(kb + (long)row * HW + n0 + col);
            Ks[row][col] = kv.x; Ks[row][col + 1] = kv.y;
            Ks[row][col + 2] = kv.z; Ks[row][col + 3] = kv.w;
            float4 vv = *(const float4*)(vb + (long)row * HW + n0 + col);
            Vs[row][col] = vv.x; Vs[row][col + 1] = vv.y;
            Vs[row][col + 2] = vv.z; Vs[row][col + 3] = vv.w;
        }
        __syncthreads();
        #pragma unroll
        for (int nn = 0; nn < 64; nn++) {
            float a[4], bb[4];
            #pragma unroll
            for (int i = 0; i < 4; i++) a[i] = Ks[ty * 4 + i][nn];
            #pragma unroll
            for (int j = 0; j < 4; j++) bb[j] = Vs[tx * 4 + j][nn];
            #pragma unroll
            for (int i = 0; i < 4; i++)
                #pragma unroll
                for (int j = 0; j < 4; j++) acc[i][j] += a[i] * bb[j];
        }
        __syncthreads();
    }
    float* dst = part + ((long)split * 128 + bh) * 4096;
    #pragma unroll
    for (int i = 0; i < 4; i++)
        #pragma unroll
        for (int j = 0; j < 4; j++)
            dst[(ty * 4 + i) * 64 + (tx * 4 + j)] = acc[i][j];
}

__global__ __launch_bounds__(256) void ctx_reduce_kernel(const float* __restrict__ part,
                                                         float* __restrict__ ctx)
{
    long i = (long)blockIdx.x * 256 + threadIdx.x;
    float s = 0.f;
    #pragma unroll
    for (int sp = 0; sp < SPLIT; sp++) s += part[(long)sp * 524288 + i];
    ctx[i] = s;
}

// ================= out[d,n] = sum_c ctx[c,d] * q[c,n] =================
__global__ __launch_bounds__(256) void attnout_kernel(const float* __restrict__ ctx,
                                                      const float* __restrict__ qkv,
                                                      float* __restrict__ out)
{
    __shared__ float Cs[32][65];
    __shared__ float Qs[32][128];
    int bh = blockIdx.y;
    int b = bh >> 3, h = bh & 7;
    int n0 = blockIdx.x * 128;
    const float* qb = qkv + (long)b * OQKV * HW + (long)(h * DIMH) * HW;
    const float* cb = ctx + (long)bh * 4096;
    float* ob = out + (long)b * HIDDEN * HW + (long)(h * DIMH) * HW;
    int t = threadIdx.x, tx = t & 15, ty = t >> 4;

    float acc[4][8] = {};
    for (int k0 = 0; k0 < 64; k0 += 32) {
        #pragma unroll
        for (int i = 0; i < 2; i++) {
            int idx = t + i * 256;
            int row = idx >> 4;
            int col = (idx & 15) << 2;
            float4 cv = *(const float4*)(cb + (long)(k0 + row) * 64 + col);
            Cs[row][col] = cv.x; Cs[row][col + 1] = cv.y;
            Cs[row][col + 2] = cv.z; Cs[row][col + 3] = cv.w;
        }
        #pragma unroll
        for (int i = 0; i < 4; i++) {
            int idx = t + i * 256;
            int row = idx >> 5;
            int col = (idx & 31) << 2;
            *(float4*)&Qs[row][col] =
                *(const float4*)(qb + (long)(k0 + row) * HW + n0 + col);
        }
        __syncthreads();
        #pragma unroll
        for (int kk = 0; kk < 32; kk++) {
            float a[4];
            #pragma unroll
            for (int i = 0; i < 4; i++) a[i] = Cs[kk][ty * 4 + i];
            float4 q0 = *(const float4*)&Qs[kk][tx * 4];
            float4 q1 = *(const float4*)&Qs[kk][64 + tx * 4];
            float bb[8] = {q0.x, q0.y, q0.z, q0.w, q1.x, q1.y, q1.z, q1.w};
            #pragma unroll
            for (int i = 0; i < 4; i++)
                #pragma unroll
                for (int j = 0; j < 8; j++) acc[i][j] += a[i] * bb[j];
        }
        __syncthreads();
    }
    #pragma unroll
    for (int i = 0; i < 4; i++) {
        float* orow = ob + (long)(ty * 4 + i) * HW + n0;
        *(float4*)(orow + tx * 4)      = make_float4(acc[i][0], acc[i][1], acc[i][2], acc[i][3]);
        *(float4*)(orow + 64 + tx * 4) = make_float4(acc[i][4], acc[i][5], acc[i][6], acc[i][7]);
    }
}

// ================= launch =================
extern "C" void kernel_launch(void* const* d_in, const int* in_sizes, int n_in,
                              void* d_out, int out_size)
{
    const float* x     = (const float*)d_in[0];   // (16,512,64,64)
    const float* w_qkv = (const float*)d_in[1];   // (1536,512)
    const float* w_out = (const float*)d_in[2];   // (512,512)
    const float* b_out = (const float*)d_in[3];   // (512,)
    float* y = (float*)d_out;

    float *qkv, *part, *ctx, *outp;
    __nv_bfloat16 *xth, *xtl, *oth, *otl, *wqh, *wql, *woh, *wol;
    cudaGetSymbolAddress((void**)&qkv,  g_qkv);
    cudaGetSymbolAddress((void**)&part, g_ctx_part);
    cudaGetSymbolAddress((void**)&ctx,  g_ctx);
    cudaGetSymbolAddress((void**)&outp, g_out);
    cudaGetSymbolAddress((void**)&xth,  g_xt_hi);
    cudaGetSymbolAddress((void**)&xtl,  g_xt_lo);
    cudaGetSymbolAddress((void**)&oth,  g_ot_hi);
    cudaGetSymbolAddress((void**)&otl,  g_ot_lo);
    cudaGetSymbolAddress((void**)&wqh,  g_wq_hi);
    cudaGetSymbolAddress((void**)&wql,  g_wq_lo);
    cudaGetSymbolAddress((void**)&woh,  g_wo_hi);
    cudaGetSymbolAddress((void**)&wol,  g_wo_lo);

    cudaFuncSetAttribute(gemm_bf16x3_kernel,
                         cudaFuncAttributeMaxDynamicSharedMemorySize, GEMM_SMEM);

    // 0. weight + input split-conversions
    conv_split_kernel<<<(OQKV * CDIM + 255) / 256, 256>>>(w_qkv, wqh, wql, OQKV * CDIM);
    conv_split_kernel<<<(HIDDEN * HIDDEN + 255) / 256, 256>>>(w_out, woh, wol, HIDDEN * HIDDEN);
    trans_split_kernel<<<dim3(HW / 32, CDIM / 32, BATCH), 256>>>(x, xth, xtl, CDIM, HW);

    // 1. qkv = w_qkv @ x   (HMMA bf16x3)
    gemm_bf16x3_kernel<<<dim3(HW / 128, OQKV / 128, BATCH), 256, GEMM_SMEM>>>(
        wqh, wql, xth, xtl, qkv, nullptr,
        OQKV, HW, CDIM, (long)HW * CDIM, (long)OQKV * HW);

    // 2. softmax over k rows
    softmax_kernel<<<8192, 256>>>(qkv);
    // 3. context = k @ v^T
    ctx_kernel<<<dim3(SPLIT, 128), 256>>>(qkv, part);
    ctx_reduce_kernel<<<2048, 256>>>(part, ctx);
    // 4. out = ctx^T @ q
    attnout_kernel<<<dim3(32, 128), 256>>>(ctx, qkv, outp);

    // 5. transpose+split out, then y = w_out @ out + b_out (HMMA bf16x3)
    trans_split_kernel<<<dim3(HW / 32, HIDDEN / 32, BATCH), 256>>>(outp, oth, otl, HIDDEN, HW);
    gemm_bf16x3_kernel<<<dim3(HW / 128, HIDDEN / 128, BATCH), 256, GEMM_SMEM>>>(
        woh, wol, oth, otl, y, b_out,
        HIDDEN, HW, HIDDEN, (long)HW * HIDDEN, (long)HIDDEN * HW);
}

// round 5
// speedup vs baseline: 2.1810x; 1.2211x over previous
#include <cuda_runtime.h>
#include <cuda_fp16.h>
#include <cstdint>

#define HEADS  8
#define DIMH   64
#define BATCH  16
#define CDIM   512
#define HW     4096
#define HIDDEN 512
#define OQKV   1536
#define SPLIT  8

// ---------------- scratch (no allocations allowed) ----------------
__device__ float g_qkv[(size_t)BATCH * OQKV * HW];            // 402 MB
__device__ float g_ctx_part[(size_t)SPLIT * BATCH * HEADS * DIMH * DIMH];
__device__ float g_ctx[(size_t)BATCH * HEADS * DIMH * DIMH];
__device__ float g_out[(size_t)BATCH * HIDDEN * HW];          // 134 MB
__device__ __half g_xt_hi[(size_t)BATCH * HW * CDIM];         // 67 MB each
__device__ __half g_xt_lo[(size_t)BATCH * HW * CDIM];
__device__ __half g_ot_hi[(size_t)BATCH * HW * HIDDEN];
__device__ __half g_ot_lo[(size_t)BATCH * HW * HIDDEN];
__device__ __half g_wq_hi[(size_t)OQKV * CDIM];
__device__ __half g_wo_hi[(size_t)HIDDEN * HIDDEN];

// ================= PTX helpers (sm_80-era, base-target safe) =====
__device__ __forceinline__ uint32_t smem_u32(const void* p) {
    uint32_t a;
    asm("{ .reg .u64 t; cvta.to.shared.u64 t, %1; cvt.u32.u64 %0, t; }"
        : "=r"(a) : "l"(p));
    return a;
}
__device__ __forceinline__ void cp_async16(uint32_t dst, const void* src) {
    asm volatile("cp.async.cg.shared.global [%0], [%1], 16;"
                 :: "r"(dst), "l"(src));
}
#define CP_COMMIT() asm volatile("cp.async.commit_group;")
#define CP_WAIT(n)  asm volatile("cp.async.wait_group %0;" :: "n"(n))

__device__ __forceinline__ void ldmx4(uint32_t* r, uint32_t addr) {
    asm volatile("ldmatrix.sync.aligned.m8n8.x4.shared.b16 {%0,%1,%2,%3}, [%4];"
                 : "=r"(r[0]), "=r"(r[1]), "=r"(r[2]), "=r"(r[3]) : "r"(addr));
}
__device__ __forceinline__ void mma16816(float* d, const uint32_t* a,
                                         uint32_t b0, uint32_t b1) {
    asm volatile(
        "mma.sync.aligned.m16n8k16.row.col.f32.f16.f16.f32 "
        "{%0,%1,%2,%3}, {%4,%5,%6,%7}, {%8,%9}, {%0,%1,%2,%3};"
        : "+f"(d[0]), "+f"(d[1]), "+f"(d[2]), "+f"(d[3])
        : "r"(a[0]), "r"(a[1]), "r"(a[2]), "r"(a[3]), "r"(b0), "r"(b1));
}

// ================= fp16 2-pass HMMA GEMM =================
// C[z][M,N] = A[M,K] @ B[z][N,K]^T
// A given as fp16 (truncated); B as fp16 hi/lo split: A@B ~= A@Bhi + A@Blo.
// CTA 128x128, BK=32, 256 threads (8 warps, warp tile 64x32), 3-stage cp.async.
// SMEM rows padded to 80B -> conflict-free ldmatrix.
#define ROWB 80
#define HALF_BYTES (128 * ROWB)          // 10240 per 128x32 fp16 half-tile
#define STAGE_BYTES (3 * HALF_BYTES)     // A | Bhi | Blo = 30720
#define NSTAGE 3
#define GEMM_SMEM (NSTAGE * STAGE_BYTES) // 92160

__global__ __launch_bounds__(256) void gemm_fp16x2_kernel(
    const __half* __restrict__ Ah,
    const __half* __restrict__ Bhi, const __half* __restrict__ Blo,
    float* __restrict__ C, const float* __restrict__ bias,
    int M, int N, int K, long strideB, long strideC)
{
    extern __shared__ char smem[];
    const uint32_t sb = smem_u32(smem);

    const int t = threadIdx.x;
    const int lane = t & 31, wid = t >> 5;
    const int wr = wid & 1, wc = wid >> 1;          // warp tile: m 64, n 32
    const int m_off = wr * 64, n_off = wc * 32;
    const int m0 = blockIdx.y * 128, n0 = blockIdx.x * 128;
    const long z = blockIdx.z;
    const __half* Bh = Bhi + z * strideB;
    const __half* Bl = Blo + z * strideB;

    const int lrow0 = t >> 2, lch = t & 3;
    const uint32_t aBase = sb + (uint32_t)((m_off + (lane & 15)) * ROWB + (lane >> 4) * 16);
    const uint32_t bBase = sb + HALF_BYTES +
        (uint32_t)((n_off + (lane & 7) + ((lane >> 4) << 3)) * ROWB + ((lane >> 3) & 1) * 16);

    float acc[4][4][4];
    #pragma unroll
    for (int i = 0; i < 4; i++)
        #pragma unroll
        for (int j = 0; j < 4; j++)
            #pragma unroll
            for (int r = 0; r < 4; r++) acc[i][j][r] = 0.f;

    const int nst = K / 32;

    auto load_stage = [&](int s) {
        const int k0 = s * 32;
        const uint32_t bufb = sb + (uint32_t)((s % NSTAGE) * STAGE_BYTES);
        #pragma unroll
        for (int p = 0; p < 2; p++) {
            int row = lrow0 + p * 64;
            uint32_t d = bufb + (uint32_t)(row * ROWB + lch * 16);
            cp_async16(d, Ah + (long)(m0 + row) * K + k0 + lch * 8);
            const long srcB = (long)(n0 + row) * K + k0 + lch * 8;
            cp_async16(d + HALF_BYTES,     Bh + srcB);
            cp_async16(d + 2 * HALF_BYTES, Bl + srcB);
        }
        CP_COMMIT();
    };

    load_stage(0);
    load_stage(1);

    for (int s = 0; s < nst; s++) {
        if (s + 2 < nst) { load_stage(s + 2); CP_WAIT(2); }
        else if (s + 1 < nst) { CP_WAIT(1); }
        else { CP_WAIT(0); }
        __syncthreads();

        const uint32_t bufo = (uint32_t)((s % NSTAGE) * STAGE_BYTES);
        #pragma unroll
        for (int ks = 0; ks < 2; ks++) {
            uint32_t bh[8], bl[8];
            #pragma unroll
            for (int nj = 0; nj < 2; nj++) {
                uint32_t ba = bBase + bufo + (uint32_t)(nj * 16 * ROWB + ks * 32);
                ldmx4(&bh[nj * 4], ba);
                ldmx4(&bl[nj * 4], ba + HALF_BYTES);
            }
            #pragma unroll
            for (int mi = 0; mi < 4; mi++) {
                uint32_t ah[4];
                ldmx4(ah, aBase + bufo + (uint32_t)(mi * 16 * ROWB + ks * 32));
                #pragma unroll
                for (int j = 0; j < 4; j++) {
                    int bi = (j >> 1) * 4 + (j & 1) * 2;
                    mma16816(acc[mi][j], ah, bh[bi], bh[bi + 1]);   // A*Bhi
                    mma16816(acc[mi][j], ah, bl[bi], bl[bi + 1]);   // A*Blo
                }
            }
        }
        __syncthreads();
    }

    // ---- epilogue ----
    float* Cz = C + z * strideC;
    const int mrow = m0 + m_off + (lane >> 2);
    const int ncol = n0 + n_off + (lane & 3) * 2;
    #pragma unroll
    for (int mi = 0; mi < 4; mi++) {
        int r0 = mrow + mi * 16;
        float bv0 = bias ? bias[r0] : 0.f;
        float bv1 = bias ? bias[r0 + 8] : 0.f;
        #pragma unroll
        for (int j = 0; j < 4; j++) {
            int cc = ncol + j * 8;
            *(float2*)(Cz + (long)r0 * N + cc) =
                make_float2(acc[mi][j][0] + bv0, acc[mi][j][1] + bv0);
            *(float2*)(Cz + (long)(r0 + 8) * N + cc) =
                make_float2(acc[mi][j][2] + bv1, acc[mi][j][3] + bv1);
        }
    }
}

// ================= conversion kernels =================
__global__ __launch_bounds__(256) void conv_half_kernel(
    const float* __restrict__ w, __half* __restrict__ hi, int n)
{
    int i = blockIdx.x * 256 + threadIdx.x;
    if (i < n) hi[i] = __float2half_rn(w[i]);
}

// in: [z][R][Cc] f32 -> out hi/lo: [z][Cc][R] fp16 (transpose + split)
__global__ __launch_bounds__(256) void trans_split_kernel(
    const float* __restrict__ in, __half* __restrict__ ohi,
    __half* __restrict__ olo, int R, int Cc)
{
    __shared__ float tile[32][33];
    const int z = blockIdx.z;
    const int c0 = blockIdx.x * 32, r0 = blockIdx.y * 32;
    const int tx = threadIdx.x & 31, ty = threadIdx.x >> 5;
    const float* ip = in + (long)z * R * Cc;
    #pragma unroll
    for (int i = 0; i < 4; i++)
        tile[ty + 8 * i][tx] = ip[(long)(r0 + ty + 8 * i) * Cc + c0 + tx];
    __syncthreads();
    #pragma unroll
    for (int i = 0; i < 4; i++) {
        float v = tile[tx][ty + 8 * i];
        __half h = __float2half_rn(v);
        __half l = __float2half_rn(v - __half2float(h));
        long o = ((long)z * Cc + c0 + ty + 8 * i) * R + r0 + tx;
        ohi[o] = h;
        olo[o] = l;
    }
}

// ================= softmax over k rows (length 4096) =================
__device__ __forceinline__ float warp_rmax(float v) {
    #pragma unroll
    for (int o = 16; o; o >>= 1) v = fmaxf(v, __shfl_xor_sync(0xffffffffu, v, o));
    return v;
}
__device__ __forceinline__ float warp_rsum(float v) {
    #pragma unroll
    for (int o = 16; o; o >>= 1) v += __shfl_xor_sync(0xffffffffu, v, o);
    return v;
}

__global__ __launch_bounds__(256) void softmax_kernel(float* __restrict__ qkv)
{
    int row = blockIdx.x;
    int b = row >> 9, ch = row & 511;
    float4* p = (float4*)(qkv + (long)b * OQKV * HW + (long)(HIDDEN + ch) * HW);
    int t = threadIdx.x;

    float4 v[4];
    float m = -1e30f;
    #pragma unroll
    for (int i = 0; i < 4; i++) {
        v[i] = p[t + i * 256];
        m = fmaxf(m, fmaxf(fmaxf(v[i].x, v[i].y), fmaxf(v[i].z, v[i].w)));
    }
    __shared__ float red[8];
    m = warp_rmax(m);
    if ((t & 31) == 0) red[t >> 5] = m;
    __syncthreads();
    float bm = red[0];
    #pragma unroll
    for (int i = 1; i < 8; i++) bm = fmaxf(bm, red[i]);

    float s = 0.f;
    #pragma unroll
    for (int i = 0; i < 4; i++) {
        v[i].x = __expf(v[i].x - bm); v[i].y = __expf(v[i].y - bm);
        v[i].z = __expf(v[i].z - bm); v[i].w = __expf(v[i].w - bm);
        s += v[i].x + v[i].y + v[i].z + v[i].w;
    }
    s = warp_rsum(s);
    __syncthreads();
    if ((t & 31) == 0) red[t >> 5] = s;
    __syncthreads();
    float bs = 0.f;
    #pragma unroll
    for (int i = 0; i < 8; i++) bs += red[i];
    float inv = 1.0f / bs;
    #pragma unroll
    for (int i = 0; i < 4; i++) {
        v[i].x *= inv; v[i].y *= inv; v[i].z *= inv; v[i].w *= inv;
        p[t + i * 256] = v[i];
    }
}

// ================= context = k @ v^T (split-K) =================
__global__ __launch_bounds__(256) void ctx_kernel(const float* __restrict__ qkv,
                                                  float* __restrict__ part)
{
    __shared__ float Ks[64][65];
    __shared__ float Vs[64][65];
    int bh = blockIdx.y;
    int b = bh >> 3, h = bh & 7;
    int split = blockIdx.x;
    const float* kb = qkv + (long)b * OQKV * HW + (long)(HIDDEN + h * DIMH) * HW;
    const float* vb = qkv + (long)b * OQKV * HW + (long)(2 * HIDDEN + h * DIMH) * HW;
    int t = threadIdx.x, tx = t & 15, ty = t >> 4;

    float acc[4][4] = {};
    for (int chunk = 0; chunk < 8; chunk++) {
        int n0 = split * 512 + chunk * 64;
        #pragma unroll
        for (int i = 0; i < 4; i++) {
            int idx = t + i * 256;
            int row = idx >> 4;
            int col = (idx & 15) << 2;
            float4 kv = *(const float4*)(kb + (long)row * HW + n0 + col);
            Ks[row][col] = kv.x; Ks[row][col + 1] = kv.y;
            Ks[row][col + 2] = kv.z; Ks[row][col + 3] = kv.w;
            float4 vv = *(const float4*)(vb + (long)row * HW + n0 + col);
            Vs[row][col] = vv.x; Vs[row][col + 1] = vv.y;
            Vs[row][col + 2] = vv.z; Vs[row][col + 3] = vv.w;
        }
        __syncthreads();
        #pragma unroll
        for (int nn = 0; nn < 64; nn++) {
            float a[4], bb[4];
            #pragma unroll
            for (int i = 0; i < 4; i++) a[i] = Ks[ty * 4 + i][nn];
            #pragma unroll
            for (int j = 0; j < 4; j++) bb[j] = Vs[tx * 4 + j][nn];
            #pragma unroll
            for (int i = 0; i < 4; i++)
                #pragma unroll
                for (int j = 0; j < 4; j++) acc[i][j] += a[i] * bb[j];
        }
        __syncthreads();
    }
    float* dst = part + ((long)split * 128 + bh) * 4096;
    #pragma unroll
    for (int i = 0; i < 4; i++)
        #pragma unroll
        for (int j = 0; j < 4; j++)
            dst[(ty * 4 + i) * 64 + (tx * 4 + j)] = acc[i][j];
}

__global__ __launch_bounds__(256) void ctx_reduce_kernel(const float* __restrict__ part,
                                                         float* __restrict__ ctx)
{
    long i = (long)blockIdx.x * 256 + threadIdx.x;
    float s = 0.f;
    #pragma unroll
    for (int sp = 0; sp < SPLIT; sp++) s += part[(long)sp * 524288 + i];
    ctx[i] = s;
}

// ================= out[d,n] = sum_c ctx[c,d] * q[c,n] =================
__global__ __launch_bounds__(256) void attnout_kernel(const float* __restrict__ ctx,
                                                      const float* __restrict__ qkv,
                                                      float* __restrict__ out)
{
    __shared__ float Cs[32][65];
    __shared__ float Qs[32][128];
    int bh = blockIdx.y;
    int b = bh >> 3, h = bh & 7;
    int n0 = blockIdx.x * 128;
    const float* qb = qkv + (long)b * OQKV * HW + (long)(h * DIMH) * HW;
    const float* cb = ctx + (long)bh * 4096;
    float* ob = out + (long)b * HIDDEN * HW + (long)(h * DIMH) * HW;
    int t = threadIdx.x, tx = t & 15, ty = t >> 4;

    float acc[4][8] = {};
    for (int k0 = 0; k0 < 64; k0 += 32) {
        #pragma unroll
        for (int i = 0; i < 2; i++) {
            int idx = t + i * 256;
            int row = idx >> 4;
            int col = (idx & 15) << 2;
            float4 cv = *(const float4*)(cb + (long)(k0 + row) * 64 + col);
            Cs[row][col] = cv.x; Cs[row][col + 1] = cv.y;
            Cs[row][col + 2] = cv.z; Cs[row][col + 3] = cv.w;
        }
        #pragma unroll
        for (int i = 0; i < 4; i++) {
            int idx = t + i * 256;
            int row = idx >> 5;
            int col = (idx & 31) << 2;
            *(float4*)&Qs[row][col] =
                *(const float4*)(qb + (long)(k0 + row) * HW + n0 + col);
        }
        __syncthreads();
        #pragma unroll
        for (int kk = 0; kk < 32; kk++) {
            float a[4];
            #pragma unroll
            for (int i = 0; i < 4; i++) a[i] = Cs[kk][ty * 4 + i];
            float4 q0 = *(const float4*)&Qs[kk][tx * 4];
            float4 q1 = *(const float4*)&Qs[kk][64 + tx * 4];
            float bb[8] = {q0.x, q0.y, q0.z, q0.w, q1.x, q1.y, q1.z, q1.w};
            #pragma unroll
            for (int i = 0; i < 4; i++)
                #pragma unroll
                for (int j = 0; j < 8; j++) acc[i][j] += a[i] * bb[j];
        }
        __syncthreads();
    }
    #pragma unroll
    for (int i = 0; i < 4; i++) {
        float* orow = ob + (long)(ty * 4 + i) * HW + n0;
        *(float4*)(orow + tx * 4)      = make_float4(acc[i][0], acc[i][1], acc[i][2], acc[i][3]);
        *(float4*)(orow + 64 + tx * 4) = make_float4(acc[i][4], acc[i][5], acc[i][6], acc[i][7]);
    }
}

// ================= launch =================
extern "C" void kernel_launch(void* const* d_in, const int* in_sizes, int n_in,
                              void* d_out, int out_size)
{
    const float* x     = (const float*)d_in[0];   // (16,512,64,64)
    const float* w_qkv = (const float*)d_in[1];   // (1536,512)
    const float* w_out = (const float*)d_in[2];   // (512,512)
    const float* b_out = (const float*)d_in[3];   // (512,)
    float* y = (float*)d_out;

    float *qkv, *part, *ctx, *outp;
    __half *xth, *xtl, *oth, *otl, *wqh, *woh;
    cudaGetSymbolAddress((void**)&qkv,  g_qkv);
    cudaGetSymbolAddress((void**)&part, g_ctx_part);
    cudaGetSymbolAddress((void**)&ctx,  g_ctx);
    cudaGetSymbolAddress((void**)&outp, g_out);
    cudaGetSymbolAddress((void**)&xth,  g_xt_hi);
    cudaGetSymbolAddress((void**)&xtl,  g_xt_lo);
    cudaGetSymbolAddress((void**)&oth,  g_ot_hi);
    cudaGetSymbolAddress((void**)&otl,  g_ot_lo);
    cudaGetSymbolAddress((void**)&wqh,  g_wq_hi);
    cudaGetSymbolAddress((void**)&woh,  g_wo_hi);

    cudaFuncSetAttribute(gemm_fp16x2_kernel,
                         cudaFuncAttributeMaxDynamicSharedMemorySize, GEMM_SMEM);

    // 0. weight + input conversions
    conv_half_kernel<<<(OQKV * CDIM + 255) / 256, 256>>>(w_qkv, wqh, OQKV * CDIM);
    conv_half_kernel<<<(HIDDEN * HIDDEN + 255) / 256, 256>>>(w_out, woh, HIDDEN * HIDDEN);
    trans_split_kernel<<<dim3(HW / 32, CDIM / 32, BATCH), 256>>>(x, xth, xtl, CDIM, HW);

    // 1. qkv = w_qkv @ x   (fp16 2-pass HMMA)
    gemm_fp16x2_kernel<<<dim3(HW / 128, OQKV / 128, BATCH), 256, GEMM_SMEM>>>(
        wqh, xth, xtl, qkv, nullptr,
        OQKV, HW, CDIM, (long)HW * CDIM, (long)OQKV * HW);

    // 2. softmax over k rows
    softmax_kernel<<<8192, 256>>>(qkv);
    // 3. context = k @ v^T
    ctx_kernel<<<dim3(SPLIT, 128), 256>>>(qkv, part);
    ctx_reduce_kernel<<<2048, 256>>>(part, ctx);
    // 4. out = ctx^T @ q
    attnout_kernel<<<dim3(32, 128), 256>>>(ctx, qkv, outp);

    // 5. transpose+split out, then y = w_out @ out + b_out
    trans_split_kernel<<<dim3(HW / 32, HIDDEN / 32, BATCH), 256>>>(outp, oth, otl, HIDDEN, HW);
    gemm_fp16x2_kernel<<<dim3(HW / 128, HIDDEN / 128, BATCH), 256, GEMM_SMEM>>>(
        woh, oth, otl, y, b_out,
        HIDDEN, HW, HIDDEN, (long)HW * HIDDEN, (long)HIDDEN * HW);
}

// round 6
// speedup vs baseline: 2.2554x; 1.0341x over previous
#include <cuda_runtime.h>
#include <cuda_fp16.h>
#include <cstdint>

#define HEADS  8
#define DIMH   64
#define BATCH  16
#define CDIM   512
#define HW     4096
#define HIDDEN 512
#define OQKV   1536
#define SPLIT  8

// ---------------- scratch (no allocations allowed) ----------------
__device__ float g_qkv[(size_t)BATCH * OQKV * HW];            // 402 MB
__device__ float g_ctx_part[(size_t)SPLIT * BATCH * HEADS * DIMH * DIMH];
__device__ float g_ctx[(size_t)BATCH * HEADS * DIMH * DIMH];
__device__ float2 g_stats[(size_t)BATCH * HIDDEN];            // per k-row {max, 1/sum}
__device__ __half g_xt_hi[(size_t)BATCH * HW * CDIM];         // 67 MB each
__device__ __half g_xt_lo[(size_t)BATCH * HW * CDIM];
__device__ __half g_ot_hi[(size_t)BATCH * HW * HIDDEN];
__device__ __half g_ot_lo[(size_t)BATCH * HW * HIDDEN];
__device__ __half g_wq_hi[(size_t)OQKV * CDIM];
__device__ __half g_wo_hi[(size_t)HIDDEN * HIDDEN];

// ================= PTX helpers (sm_80-era, base-target safe) =====
__device__ __forceinline__ uint32_t smem_u32(const void* p) {
    uint32_t a;
    asm("{ .reg .u64 t; cvta.to.shared.u64 t, %1; cvt.u32.u64 %0, t; }"
        : "=r"(a) : "l"(p));
    return a;
}
__device__ __forceinline__ void cp_async16(uint32_t dst, const void* src) {
    asm volatile("cp.async.cg.shared.global [%0], [%1], 16;"
                 :: "r"(dst), "l"(src));
}
#define CP_COMMIT() asm volatile("cp.async.commit_group;")
#define CP_WAIT(n)  asm volatile("cp.async.wait_group %0;" :: "n"(n))

__device__ __forceinline__ void ldmx4(uint32_t* r, uint32_t addr) {
    asm volatile("ldmatrix.sync.aligned.m8n8.x4.shared.b16 {%0,%1,%2,%3}, [%4];"
                 : "=r"(r[0]), "=r"(r[1]), "=r"(r[2]), "=r"(r[3]) : "r"(addr));
}
__device__ __forceinline__ void mma16816(float* d, const uint32_t* a,
                                         uint32_t b0, uint32_t b1) {
    asm volatile(
        "mma.sync.aligned.m16n8k16.row.col.f32.f16.f16.f32 "
        "{%0,%1,%2,%3}, {%4,%5,%6,%7}, {%8,%9}, {%0,%1,%2,%3};"
        : "+f"(d[0]), "+f"(d[1]), "+f"(d[2]), "+f"(d[3])
        : "r"(a[0]), "r"(a[1]), "r"(a[2]), "r"(a[3]), "r"(b0), "r"(b1));
}

// ================= fp16 2-pass HMMA GEMM =================
// C[z][M,N] = A[M,K] @ B[z][N,K]^T;  A fp16 (truncated), B fp16 hi/lo split.
// CTA 256x128, BK=32, 256 threads (8 warps, warp tile 64x64), 3-stage cp.async.
// SMEM rows 80B -> conflict-free ldmatrix.
#define ROWB 80
#define A_BYTES (256 * ROWB)             // 20480
#define B_BYTES (128 * ROWB)             // 10240
#define STAGE_BYTES (A_BYTES + 2 * B_BYTES)  // 40960
#define NSTAGE 3
#define GEMM_SMEM (NSTAGE * STAGE_BYTES)     // 122880

__global__ __launch_bounds__(256, 1) void gemm_fp16x2_kernel(
    const __half* __restrict__ Ah,
    const __half* __restrict__ Bhi, const __half* __restrict__ Blo,
    float* __restrict__ C, const float* __restrict__ bias,
    int M, int N, int K, long strideB, long strideC)
{
    extern __shared__ char smem[];
    const uint32_t sb = smem_u32(smem);

    const int t = threadIdx.x;
    const int lane = t & 31, wid = t >> 5;
    const int m_off = (wid & 3) * 64, n_off = (wid >> 2) * 64;  // warp 64x64
    const int m0 = blockIdx.y * 256, n0 = blockIdx.x * 128;
    const long z = blockIdx.z;
    const __half* Bh = Bhi + z * strideB;
    const __half* Bl = Blo + z * strideB;

    const int lrow0 = t >> 2, lch = t & 3;
    const uint32_t aBase = sb + (uint32_t)((m_off + (lane & 15)) * ROWB + (lane >> 4) * 16);
    const uint32_t bBase = sb + A_BYTES +
        (uint32_t)((n_off + (lane & 7) + ((lane >> 4) << 3)) * ROWB + ((lane >> 3) & 1) * 16);

    float acc[4][8][4];
    #pragma unroll
    for (int i = 0; i < 4; i++)
        #pragma unroll
        for (int j = 0; j < 8; j++)
            #pragma unroll
            for (int r = 0; r < 4; r++) acc[i][j][r] = 0.f;

    const int nst = K / 32;

    auto load_stage = [&](int s) {
        const int k0 = s * 32;
        const uint32_t bufb = sb + (uint32_t)((s % NSTAGE) * STAGE_BYTES);
        #pragma unroll
        for (int p = 0; p < 4; p++) {           // A: 256 rows
            int row = lrow0 + p * 64;
            cp_async16(bufb + (uint32_t)(row * ROWB + lch * 16),
                       Ah + (long)(m0 + row) * K + k0 + lch * 8);
        }
        #pragma unroll
        for (int p = 0; p < 2; p++) {           // B: 128 rows, hi+lo
            int row = lrow0 + p * 64;
            uint32_t d = bufb + A_BYTES + (uint32_t)(row * ROWB + lch * 16);
            const long srcB = (long)(n0 + row) * K + k0 + lch * 8;
            cp_async16(d,           Bh + srcB);
            cp_async16(d + B_BYTES, Bl + srcB);
        }
        CP_COMMIT();
    };

    load_stage(0);
    load_stage(1);

    for (int s = 0; s < nst; s++) {
        if (s + 2 < nst) { load_stage(s + 2); CP_WAIT(2); }
        else if (s + 1 < nst) { CP_WAIT(1); }
        else { CP_WAIT(0); }
        __syncthreads();

        const uint32_t bufo = (uint32_t)((s % NSTAGE) * STAGE_BYTES);
        #pragma unroll
        for (int ks = 0; ks < 2; ks++) {
            uint32_t bh[16], bl[16];
            #pragma unroll
            for (int nj = 0; nj < 4; nj++) {
                uint32_t ba = bBase + bufo + (uint32_t)(nj * 16 * ROWB + ks * 32);
                ldmx4(&bh[nj * 4], ba);
                ldmx4(&bl[nj * 4], ba + B_BYTES);
            }
            #pragma unroll
            for (int mi = 0; mi < 4; mi++) {
                uint32_t ah[4];
                ldmx4(ah, aBase + bufo + (uint32_t)(mi * 16 * ROWB + ks * 32));
                #pragma unroll
                for (int j = 0; j < 8; j++) {
                    int bi = (j >> 1) * 4 + (j & 1) * 2;
                    mma16816(acc[mi][j], ah, bh[bi], bh[bi + 1]);   // A*Bhi
                    mma16816(acc[mi][j], ah, bl[bi], bl[bi + 1]);   // A*Blo
                }
            }
        }
        __syncthreads();
    }

    // ---- epilogue ----
    float* Cz = C + z * strideC;
    const int mrow = m0 + m_off + (lane >> 2);
    const int ncol = n0 + n_off + (lane & 3) * 2;
    #pragma unroll
    for (int mi = 0; mi < 4; mi++) {
        int r0 = mrow + mi * 16;
        float bv0 = bias ? bias[r0] : 0.f;
        float bv1 = bias ? bias[r0 + 8] : 0.f;
        #pragma unroll
        for (int j = 0; j < 8; j++) {
            int cc = ncol + j * 8;
            *(float2*)(Cz + (long)r0 * N + cc) =
                make_float2(acc[mi][j][0] + bv0, acc[mi][j][1] + bv0);
            *(float2*)(Cz + (long)(r0 + 8) * N + cc) =
                make_float2(acc[mi][j][2] + bv1, acc[mi][j][3] + bv1);
        }
    }
}

// ================= conversion kernels =================
__global__ __launch_bounds__(256) void conv_half_kernel(
    const float* __restrict__ w, __half* __restrict__ hi, int n)
{
    int i = blockIdx.x * 256 + threadIdx.x;
    if (i < n) hi[i] = __float2half_rn(w[i]);
}

// in: [z][R][Cc] f32 -> out hi/lo: [z][Cc][R] fp16 (transpose + split)
__global__ __launch_bounds__(256) void trans_split_kernel(
    const float* __restrict__ in, __half* __restrict__ ohi,
    __half* __restrict__ olo, int R, int Cc)
{
    __shared__ float tile[32][33];
    const int z = blockIdx.z;
    const int c0 = blockIdx.x * 32, r0 = blockIdx.y * 32;
    const int tx = threadIdx.x & 31, ty = threadIdx.x >> 5;
    const float* ip = in + (long)z * R * Cc;
    #pragma unroll
    for (int i = 0; i < 4; i++)
        tile[ty + 8 * i][tx] = ip[(long)(r0 + ty + 8 * i) * Cc + c0 + tx];
    __syncthreads();
    #pragma unroll
    for (int i = 0; i < 4; i++) {
        float v = tile[tx][ty + 8 * i];
        __half h = __float2half_rn(v);
        __half l = __float2half_rn(v - __half2float(h));
        long o = ((long)z * Cc + c0 + ty + 8 * i) * R + r0 + tx;
        ohi[o] = h;
        olo[o] = l;
    }
}

// ================= row stats for softmax(k): {max, 1/sumexp} =================
__device__ __forceinline__ float warp_rmax(float v) {
    #pragma unroll
    for (int o = 16; o; o >>= 1) v = fmaxf(v, __shfl_xor_sync(0xffffffffu, v, o));
    return v;
}
__device__ __forceinline__ float warp_rsum(float v) {
    #pragma unroll
    for (int o = 16; o; o >>= 1) v += __shfl_xor_sync(0xffffffffu, v, o);
    return v;
}

__global__ __launch_bounds__(256) void rowstat_kernel(const float* __restrict__ qkv,
                                                      float2* __restrict__ stats)
{
    int row = blockIdx.x;          // b*512 + ch
    int b = row >> 9, ch = row & 511;
    const float4* p = (const float4*)(qkv + (long)b * OQKV * HW + (long)(HIDDEN + ch) * HW);
    int t = threadIdx.x;

    float4 v[4];
    float m = -1e30f;
    #pragma unroll
    for (int i = 0; i < 4; i++) {
        v[i] = p[t + i * 256];
        m = fmaxf(m, fmaxf(fmaxf(v[i].x, v[i].y), fmaxf(v[i].z, v[i].w)));
    }
    __shared__ float red[8];
    m = warp_rmax(m);
    if ((t & 31) == 0) red[t >> 5] = m;
    __syncthreads();
    float bm = red[0];
    #pragma unroll
    for (int i = 1; i < 8; i++) bm = fmaxf(bm, red[i]);

    float s = 0.f;
    #pragma unroll
    for (int i = 0; i < 4; i++) {
        s += __expf(v[i].x - bm) + __expf(v[i].y - bm) +
             __expf(v[i].z - bm) + __expf(v[i].w - bm);
    }
    s = warp_rsum(s);
    __syncthreads();
    if ((t & 31) == 0) red[t >> 5] = s;
    __syncthreads();
    if (t == 0) {
        float bs = 0.f;
        #pragma unroll
        for (int i = 0; i < 8; i++) bs += red[i];
        stats[row] = make_float2(bm, 1.0f / bs);
    }
}

// ================= context = softmax(k) @ v^T (exp fused, split-K) =====
__global__ __launch_bounds__(256) void ctx_kernel(const float* __restrict__ qkv,
                                                  const float2* __restrict__ stats,
                                                  float* __restrict__ part)
{
    __shared__ float Ks[64][65];
    __shared__ float Vs[64][65];
    __shared__ float sm_m[64];
    int bh = blockIdx.y;
    int b = bh >> 3, hh = bh & 7;
    int split = blockIdx.x;
    const float* kb = qkv + (long)b * OQKV * HW + (long)(HIDDEN + hh * DIMH) * HW;
    const float* vb = qkv + (long)b * OQKV * HW + (long)(2 * HIDDEN + hh * DIMH) * HW;
    int t = threadIdx.x, tx = t & 15, ty = t >> 4;

    if (t < 64) sm_m[t] = stats[b * HIDDEN + hh * DIMH + t].x;
    __syncthreads();

    float acc[4][4] = {};
    for (int chunk = 0; chunk < 8; chunk++) {
        int n0 = split * 512 + chunk * 64;
        #pragma unroll
        for (int i = 0; i < 4; i++) {
            int idx = t + i * 256;
            int row = idx >> 4;
            int col = (idx & 15) << 2;
            float mrow = sm_m[row];
            float4 kv = *(const float4*)(kb + (long)row * HW + n0 + col);
            Ks[row][col] = __expf(kv.x - mrow); Ks[row][col + 1] = __expf(kv.y - mrow);
            Ks[row][col + 2] = __expf(kv.z - mrow); Ks[row][col + 3] = __expf(kv.w - mrow);
            float4 vv = *(const float4*)(vb + (long)row * HW + n0 + col);
            Vs[row][col] = vv.x; Vs[row][col + 1] = vv.y;
            Vs[row][col + 2] = vv.z; Vs[row][col + 3] = vv.w;
        }
        __syncthreads();
        #pragma unroll
        for (int nn = 0; nn < 64; nn++) {
            float a[4], bb[4];
            #pragma unroll
            for (int i = 0; i < 4; i++) a[i] = Ks[ty * 4 + i][nn];
            #pragma unroll
            for (int j = 0; j < 4; j++) bb[j] = Vs[tx * 4 + j][nn];
            #pragma unroll
            for (int i = 0; i < 4; i++)
                #pragma unroll
                for (int j = 0; j < 4; j++) acc[i][j] += a[i] * bb[j];
        }
        __syncthreads();
    }
    float* dst = part + ((long)split * 128 + bh) * 4096;
    #pragma unroll
    for (int i = 0; i < 4; i++)
        #pragma unroll
        for (int j = 0; j < 4; j++)
            dst[(ty * 4 + i) * 64 + (tx * 4 + j)] = acc[i][j];
}

__global__ __launch_bounds__(256) void ctx_reduce_kernel(const float* __restrict__ part,
                                                         const float2* __restrict__ stats,
                                                         float* __restrict__ ctx)
{
    long i = (long)blockIdx.x * 256 + threadIdx.x;
    float s = 0.f;
    #pragma unroll
    for (int sp = 0; sp < SPLIT; sp++) s += part[(long)sp * 524288 + i];
    int bh = (int)(i >> 12);
    int c  = (int)((i >> 6) & 63);
    float inv = stats[(bh >> 3) * HIDDEN + (bh & 7) * DIMH + c].y;
    ctx[i] = s * inv;
}

// ===== out[d,n] = sum_c ctx[c,d]*q[c,n]; fused transpose+split fp16 epilogue ====
__global__ __launch_bounds__(256) void attnout_kernel(const float* __restrict__ ctx,
                                                      const float* __restrict__ qkv,
                                                      __half* __restrict__ oth,
                                                      __half* __restrict__ otl)
{
    __shared__ union {
        struct { float Cs[32][65]; float Qs[32][128]; } a;
        float tb[64][68];
    } sm;
    int bh = blockIdx.y;
    int b = bh >> 3, hh = bh & 7;
    int n0 = blockIdx.x * 128;
    const float* qb = qkv + (long)b * OQKV * HW + (long)(hh * DIMH) * HW;
    const float* cb = ctx + (long)bh * 4096;
    int t = threadIdx.x, tx = t & 15, ty = t >> 4;

    float acc[4][8] = {};
    for (int k0 = 0; k0 < 64; k0 += 32) {
        #pragma unroll
        for (int i = 0; i < 2; i++) {
            int idx = t + i * 256;
            int row = idx >> 4;
            int col = (idx & 15) << 2;
            float4 cv = *(const float4*)(cb + (long)(k0 + row) * 64 + col);
            sm.a.Cs[row][col] = cv.x; sm.a.Cs[row][col + 1] = cv.y;
            sm.a.Cs[row][col + 2] = cv.z; sm.a.Cs[row][col + 3] = cv.w;
        }
        #pragma unroll
        for (int i = 0; i < 4; i++) {
            int idx = t + i * 256;
            int row = idx >> 5;
            int col = (idx & 31) << 2;
            *(float4*)&sm.a.Qs[row][col] =
                *(const float4*)(qb + (long)(k0 + row) * HW + n0 + col);
        }
        __syncthreads();
        #pragma unroll
        for (int kk = 0; kk < 32; kk++) {
            float a[4];
            #pragma unroll
            for (int i = 0; i < 4; i++) a[i] = sm.a.Cs[kk][ty * 4 + i];
            float4 q0 = *(const float4*)&sm.a.Qs[kk][tx * 4];
            float4 q1 = *(const float4*)&sm.a.Qs[kk][64 + tx * 4];
            float bb[8] = {q0.x, q0.y, q0.z, q0.w, q1.x, q1.y, q1.z, q1.w};
            #pragma unroll
            for (int i = 0; i < 4; i++)
                #pragma unroll
                for (int j = 0; j < 8; j++) acc[i][j] += a[i] * bb[j];
        }
        __syncthreads();
    }

    // fused epilogue: transpose 64d x 128n tile, emit fp16 hi/lo at [b][n][hidden]
    #pragma unroll
    for (int half = 0; half < 2; half++) {
        __syncthreads();
        #pragma unroll
        for (int i = 0; i < 4; i++)
            #pragma unroll
            for (int j = 0; j < 4; j++)
                sm.tb[ty * 4 + i][tx * 4 + j] = acc[i][half * 4 + j];
        __syncthreads();
        int n_local = t >> 2, dseg = (t & 3) * 16;
        alignas(16) __half hs[16];
        alignas(16) __half ls[16];
        #pragma unroll
        for (int dd = 0; dd < 16; dd++) {
            float v = sm.tb[dseg + dd][n_local];
            __half h = __float2half_rn(v);
            hs[dd] = h;
            ls[dd] = __float2half_rn(v - __half2float(h));
        }
        long base = ((long)b * HW + n0 + half * 64 + n_local) * HIDDEN + hh * DIMH + dseg;
        *(uint4*)(oth + base) = *(uint4*)&hs[0];
        *(uint4*)(oth + base + 8) = *(uint4*)&hs[8];
        *(uint4*)(otl + base) = *(uint4*)&ls[0];
        *(uint4*)(otl + base + 8) = *(uint4*)&ls[8];
    }
}

// ================= launch =================
extern "C" void kernel_launch(void* const* d_in, const int* in_sizes, int n_in,
                              void* d_out, int out_size)
{
    const float* x     = (const float*)d_in[0];   // (16,512,64,64)
    const float* w_qkv = (const float*)d_in[1];   // (1536,512)
    const float* w_out = (const float*)d_in[2];   // (512,512)
    const float* b_out = (const float*)d_in[3];   // (512,)
    float* y = (float*)d_out;

    float *qkv, *part, *ctx;
    float2* stats;
    __half *xth, *xtl, *oth, *otl, *wqh, *woh;
    cudaGetSymbolAddress((void**)&qkv,   g_qkv);
    cudaGetSymbolAddress((void**)&part,  g_ctx_part);
    cudaGetSymbolAddress((void**)&ctx,   g_ctx);
    cudaGetSymbolAddress((void**)&stats, g_stats);
    cudaGetSymbolAddress((void**)&xth,   g_xt_hi);
    cudaGetSymbolAddress((void**)&xtl,   g_xt_lo);
    cudaGetSymbolAddress((void**)&oth,   g_ot_hi);
    cudaGetSymbolAddress((void**)&otl,   g_ot_lo);
    cudaGetSymbolAddress((void**)&wqh,   g_wq_hi);
    cudaGetSymbolAddress((void**)&woh,   g_wo_hi);

    cudaFuncSetAttribute(gemm_fp16x2_kernel,
                         cudaFuncAttributeMaxDynamicSharedMemorySize, GEMM_SMEM);

    // 0. weight + input conversions
    conv_half_kernel<<<(OQKV * CDIM + 255) / 256, 256>>>(w_qkv, wqh, OQKV * CDIM);
    conv_half_kernel<<<(HIDDEN * HIDDEN + 255) / 256, 256>>>(w_out, woh, HIDDEN * HIDDEN);
    trans_split_kernel<<<dim3(HW / 32, CDIM / 32, BATCH), 256>>>(x, xth, xtl, CDIM, HW);

    // 1. qkv = w_qkv @ x   (fp16 2-pass HMMA, 256x128 tile)
    gemm_fp16x2_kernel<<<dim3(HW / 128, OQKV / 256, BATCH), 256, GEMM_SMEM>>>(
        wqh, xth, xtl, qkv, nullptr,
        OQKV, HW, CDIM, (long)HW * CDIM, (long)OQKV * HW);

    // 2. softmax row stats (max, 1/sumexp) — normalization fused downstream
    rowstat_kernel<<<8192, 256>>>(qkv, stats);
    // 3. context = softmax(k) @ v^T (exp fused into tile load)
    ctx_kernel<<<dim3(SPLIT, 128), 256>>>(qkv, stats, part);
    ctx_reduce_kernel<<<2048, 256>>>(part, stats, ctx);
    // 4. out = ctx^T @ q, writing transposed fp16 hi/lo directly (GEMM2 B operand)
    attnout_kernel<<<dim3(32, 128), 256>>>(ctx, qkv, oth, otl);

    // 5. y = w_out @ out + b_out
    gemm_fp16x2_kernel<<<dim3(HW / 128, HIDDEN / 256, BATCH), 256, GEMM_SMEM>>>(
        woh, oth, otl, y, b_out,
        HIDDEN, HW, HIDDEN, (long)HW * HIDDEN, (long)HIDDEN * HW);
}

// round 7
// speedup vs baseline: 3.0504x; 1.3525x over previous
#include <cuda_runtime.h>
#include <cuda_fp16.h>
#include <cstdint>

#define HEADS  8
#define DIMH   64
#define BATCH  16
#define CDIM   512
#define HW     4096
#define HIDDEN 512
#define OQKV   1536
#define SPLIT  8

// ---------------- scratch (no allocations allowed) ----------------
__device__ float g_qkv[(size_t)BATCH * OQKV * HW];            // 402 MB
__device__ float g_ctx_part[(size_t)SPLIT * BATCH * HEADS * DIMH * DIMH];
__device__ float g_ctx[(size_t)BATCH * HEADS * DIMH * DIMH];
__device__ float2 g_stats[(size_t)BATCH * HIDDEN];            // per k-row {max, 1/sum}
__device__ __half g_xt[(size_t)BATCH * HW * CDIM];            // 67 MB (fp16, single)
__device__ __half g_ot_hi[(size_t)BATCH * HW * HIDDEN];
__device__ __half g_ot_lo[(size_t)BATCH * HW * HIDDEN];
__device__ __half g_wq[(size_t)OQKV * CDIM];
__device__ __half g_wo[(size_t)HIDDEN * HIDDEN];

// ================= PTX helpers (sm_80-era, base-target safe) =====
__device__ __forceinline__ uint32_t smem_u32(const void* p) {
    uint32_t a;
    asm("{ .reg .u64 t; cvta.to.shared.u64 t, %1; cvt.u32.u64 %0, t; }"
        : "=r"(a) : "l"(p));
    return a;
}
__device__ __forceinline__ void cp_async16(uint32_t dst, const void* src) {
    asm volatile("cp.async.cg.shared.global [%0], [%1], 16;"
                 :: "r"(dst), "l"(src));
}
#define CP_COMMIT() asm volatile("cp.async.commit_group;")
#define CP_WAIT(n)  asm volatile("cp.async.wait_group %0;" :: "n"(n))

__device__ __forceinline__ void ldmx4(uint32_t* r, uint32_t addr) {
    asm volatile("ldmatrix.sync.aligned.m8n8.x4.shared.b16 {%0,%1,%2,%3}, [%4];"
                 : "=r"(r[0]), "=r"(r[1]), "=r"(r[2]), "=r"(r[3]) : "r"(addr));
}
__device__ __forceinline__ void mma16816(float* d, const uint32_t* a,
                                         uint32_t b0, uint32_t b1) {
    asm volatile(
        "mma.sync.aligned.m16n8k16.row.col.f32.f16.f16.f32 "
        "{%0,%1,%2,%3}, {%4,%5,%6,%7}, {%8,%9}, {%0,%1,%2,%3};"
        : "+f"(d[0]), "+f"(d[1]), "+f"(d[2]), "+f"(d[3])
        : "r"(a[0]), "r"(a[1]), "r"(a[2]), "r"(a[3]), "r"(b0), "r"(b1));
}

// ================= fp16 HMMA GEMM (1- or 2-pass) =================
// C[z][M,N] = A[M,K] @ B[z][N,K]^T;  A fp16; B fp16 (NPASS=1) or hi/lo (NPASS=2).
// CTA 128x128, 128 threads (4 warps, warp tile 64x64), BK=32, NSTAGES cp.async.
// 2 CTAs/SM by registers -> cross-CTA overlap fills sync bubbles.
#define ROWB 80
#define HALF_TILE (128 * ROWB)           // 10240 per 128x32 fp16 tile

template<int NPASS, int NSTAGES>
__global__ __launch_bounds__(128, 2) void gemm_fp16_kernel(
    const __half* __restrict__ Ah,
    const __half* __restrict__ Bhi, const __half* __restrict__ Blo,
    float* __restrict__ C, const float* __restrict__ bias,
    int M, int N, int K, long strideB, long strideC)
{
    constexpr int STAGE_BYTES = (1 + NPASS) * HALF_TILE;
    extern __shared__ char smem[];
    const uint32_t sb = smem_u32(smem);

    const int t = threadIdx.x;
    const int lane = t & 31, wid = t >> 5;
    const int m_off = (wid & 1) * 64, n_off = (wid >> 1) * 64;  // warp 64x64
    const int m0 = blockIdx.y * 128, n0 = blockIdx.x * 128;
    const long z = blockIdx.z;
    const __half* Bh = Bhi + z * strideB;
    const __half* Bl = Blo + z * strideB;

    const int lrow0 = t >> 2, lch = t & 3;   // 32 rows/pass, 4x16B per row
    const uint32_t aBase = sb + (uint32_t)((m_off + (lane & 15)) * ROWB + (lane >> 4) * 16);
    const uint32_t bBase = sb + HALF_TILE +
        (uint32_t)((n_off + (lane & 7) + ((lane >> 4) << 3)) * ROWB + ((lane >> 3) & 1) * 16);

    float acc[4][8][4];
    #pragma unroll
    for (int i = 0; i < 4; i++)
        #pragma unroll
        for (int j = 0; j < 8; j++)
            #pragma unroll
            for (int r = 0; r < 4; r++) acc[i][j][r] = 0.f;

    const int nst = K / 32;

    auto load_stage = [&](int s) {
        const int k0 = s * 32;
        const uint32_t bufb = sb + (uint32_t)((s % NSTAGES) * STAGE_BYTES);
        #pragma unroll
        for (int p = 0; p < 4; p++) {
            int row = lrow0 + p * 32;
            cp_async16(bufb + (uint32_t)(row * ROWB + lch * 16),
                       Ah + (long)(m0 + row) * K + k0 + lch * 8);
            uint32_t d = bufb + HALF_TILE + (uint32_t)(row * ROWB + lch * 16);
            const long srcB = (long)(n0 + row) * K + k0 + lch * 8;
            cp_async16(d, Bh + srcB);
            if constexpr (NPASS == 2)
                cp_async16(d + HALF_TILE, Bl + srcB);
        }
        CP_COMMIT();
    };

    #pragma unroll
    for (int s = 0; s < NSTAGES - 1; s++) load_stage(s);

    for (int s = 0; s < nst; s++) {
        if (s + NSTAGES - 1 < nst) { load_stage(s + NSTAGES - 1); CP_WAIT(NSTAGES - 2); }
        else                       { CP_WAIT(0); }
        __syncthreads();

        const uint32_t bufo = (uint32_t)((s % NSTAGES) * STAGE_BYTES);
        #pragma unroll
        for (int ks = 0; ks < 2; ks++) {
            uint32_t bh[16], bl[16];
            #pragma unroll
            for (int nj = 0; nj < 4; nj++) {
                uint32_t ba = bBase + bufo + (uint32_t)(nj * 16 * ROWB + ks * 32);
                ldmx4(&bh[nj * 4], ba);
                if constexpr (NPASS == 2) ldmx4(&bl[nj * 4], ba + HALF_TILE);
            }
            #pragma unroll
            for (int mi = 0; mi < 4; mi++) {
                uint32_t ah[4];
                ldmx4(ah, aBase + bufo + (uint32_t)(mi * 16 * ROWB + ks * 32));
                #pragma unroll
                for (int j = 0; j < 8; j++) {
                    int bi = (j >> 1) * 4 + (j & 1) * 2;
                    mma16816(acc[mi][j], ah, bh[bi], bh[bi + 1]);
                    if constexpr (NPASS == 2)
                        mma16816(acc[mi][j], ah, bl[bi], bl[bi + 1]);
                }
            }
        }
        __syncthreads();
    }

    // ---- epilogue ----
    float* Cz = C + z * strideC;
    const int mrow = m0 + m_off + (lane >> 2);
    const int ncol = n0 + n_off + (lane & 3) * 2;
    #pragma unroll
    for (int mi = 0; mi < 4; mi++) {
        int r0 = mrow + mi * 16;
        float bv0 = bias ? bias[r0] : 0.f;
        float bv1 = bias ? bias[r0 + 8] : 0.f;
        #pragma unroll
        for (int j = 0; j < 8; j++) {
            int cc = ncol + j * 8;
            *(float2*)(Cz + (long)r0 * N + cc) =
                make_float2(acc[mi][j][0] + bv0, acc[mi][j][1] + bv0);
            *(float2*)(Cz + (long)(r0 + 8) * N + cc) =
                make_float2(acc[mi][j][2] + bv1, acc[mi][j][3] + bv1);
        }
    }
}

#define GEMM1_SMEM (4 * 2 * HALF_TILE)   // 4-stage, single-pass  = 81920
#define GEMM2_SMEM (3 * 3 * HALF_TILE)   // 3-stage, two-pass     = 92160

// ================= conversion kernels =================
__global__ __launch_bounds__(256) void conv_half_kernel(
    const float* __restrict__ w, __half* __restrict__ hi, int n)
{
    int i = blockIdx.x * 256 + threadIdx.x;
    if (i < n) hi[i] = __float2half_rn(w[i]);
}

// in: [z][R][Cc] f32 -> out: [z][Cc][R] fp16 (transpose, no split)
__global__ __launch_bounds__(256) void trans_half_kernel(
    const float* __restrict__ in, __half* __restrict__ oh, int R, int Cc)
{
    __shared__ float tile[32][33];
    const int z = blockIdx.z;
    const int c0 = blockIdx.x * 32, r0 = blockIdx.y * 32;
    const int tx = threadIdx.x & 31, ty = threadIdx.x >> 5;
    const float* ip = in + (long)z * R * Cc;
    #pragma unroll
    for (int i = 0; i < 4; i++)
        tile[ty + 8 * i][tx] = ip[(long)(r0 + ty + 8 * i) * Cc + c0 + tx];
    __syncthreads();
    #pragma unroll
    for (int i = 0; i < 4; i++) {
        long o = ((long)z * Cc + c0 + ty + 8 * i) * R + r0 + tx;
        oh[o] = __float2half_rn(tile[tx][ty + 8 * i]);
    }
}

// ================= row stats for softmax(k): {max, 1/sumexp} =================
__device__ __forceinline__ float warp_rmax(float v) {
    #pragma unroll
    for (int o = 16; o; o >>= 1) v = fmaxf(v, __shfl_xor_sync(0xffffffffu, v, o));
    return v;
}
__device__ __forceinline__ float warp_rsum(float v) {
    #pragma unroll
    for (int o = 16; o; o >>= 1) v += __shfl_xor_sync(0xffffffffu, v, o);
    return v;
}

__global__ __launch_bounds__(256) void rowstat_kernel(const float* __restrict__ qkv,
                                                      float2* __restrict__ stats)
{
    int row = blockIdx.x;          // b*512 + ch
    int b = row >> 9, ch = row & 511;
    const float4* p = (const float4*)(qkv + (long)b * OQKV * HW + (long)(HIDDEN + ch) * HW);
    int t = threadIdx.x;

    float4 v[4];
    float m = -1e30f;
    #pragma unroll
    for (int i = 0; i < 4; i++) {
        v[i] = p[t + i * 256];
        m = fmaxf(m, fmaxf(fmaxf(v[i].x, v[i].y), fmaxf(v[i].z, v[i].w)));
    }
    __shared__ float red[8];
    m = warp_rmax(m);
    if ((t & 31) == 0) red[t >> 5] = m;
    __syncthreads();
    float bm = red[0];
    #pragma unroll
    for (int i = 1; i < 8; i++) bm = fmaxf(bm, red[i]);

    float s = 0.f;
    #pragma unroll
    for (int i = 0; i < 4; i++) {
        s += __expf(v[i].x - bm) + __expf(v[i].y - bm) +
             __expf(v[i].z - bm) + __expf(v[i].w - bm);
    }
    s = warp_rsum(s);
    __syncthreads();
    if ((t & 31) == 0) red[t >> 5] = s;
    __syncthreads();
    if (t == 0) {
        float bs = 0.f;
        #pragma unroll
        for (int i = 0; i < 8; i++) bs += red[i];
        stats[row] = make_float2(bm, 1.0f / bs);
    }
}

// ================= context = softmax(k) @ v^T (exp fused, split-K) =====
__global__ __launch_bounds__(256) void ctx_kernel(const float* __restrict__ qkv,
                                                  const float2* __restrict__ stats,
                                                  float* __restrict__ part)
{
    __shared__ float Ks[64][65];
    __shared__ float Vs[64][65];
    __shared__ float sm_m[64];
    int bh = blockIdx.y;
    int b = bh >> 3, hh = bh & 7;
    int split = blockIdx.x;
    const float* kb = qkv + (long)b * OQKV * HW + (long)(HIDDEN + hh * DIMH) * HW;
    const float* vb = qkv + (long)b * OQKV * HW + (long)(2 * HIDDEN + hh * DIMH) * HW;
    int t = threadIdx.x, tx = t & 15, ty = t >> 4;

    if (t < 64) sm_m[t] = stats[b * HIDDEN + hh * DIMH + t].x;
    __syncthreads();

    float acc[4][4] = {};
    for (int chunk = 0; chunk < 8; chunk++) {
        int n0 = split * 512 + chunk * 64;
        #pragma unroll
        for (int i = 0; i < 4; i++) {
            int idx = t + i * 256;
            int row = idx >> 4;
            int col = (idx & 15) << 2;
            float mrow = sm_m[row];
            float4 kv = *(const float4*)(kb + (long)row * HW + n0 + col);
            Ks[row][col] = __expf(kv.x - mrow); Ks[row][col + 1] = __expf(kv.y - mrow);
            Ks[row][col + 2] = __expf(kv.z - mrow); Ks[row][col + 3] = __expf(kv.w - mrow);
            float4 vv = *(const float4*)(vb + (long)row * HW + n0 + col);
            Vs[row][col] = vv.x; Vs[row][col + 1] = vv.y;
            Vs[row][col + 2] = vv.z; Vs[row][col + 3] = vv.w;
        }
        __syncthreads();
        #pragma unroll
        for (int nn = 0; nn < 64; nn++) {
            float a[4], bb[4];
            #pragma unroll
            for (int i = 0; i < 4; i++) a[i] = Ks[ty * 4 + i][nn];
            #pragma unroll
            for (int j = 0; j < 4; j++) bb[j] = Vs[tx * 4 + j][nn];
            #pragma unroll
            for (int i = 0; i < 4; i++)
                #pragma unroll
                for (int j = 0; j < 4; j++) acc[i][j] += a[i] * bb[j];
        }
        __syncthreads();
    }
    float* dst = part + ((long)split * 128 + bh) * 4096;
    #pragma unroll
    for (int i = 0; i < 4; i++)
        #pragma unroll
        for (int j = 0; j < 4; j++)
            dst[(ty * 4 + i) * 64 + (tx * 4 + j)] = acc[i][j];
}

__global__ __launch_bounds__(256) void ctx_reduce_kernel(const float* __restrict__ part,
                                                         const float2* __restrict__ stats,
                                                         float* __restrict__ ctx)
{
    long i = (long)blockIdx.x * 256 + threadIdx.x;
    float s = 0.f;
    #pragma unroll
    for (int sp = 0; sp < SPLIT; sp++) s += part[(long)sp * 524288 + i];
    int bh = (int)(i >> 12);
    int c  = (int)((i >> 6) & 63);
    float inv = stats[(bh >> 3) * HIDDEN + (bh & 7) * DIMH + c].y;
    ctx[i] = s * inv;
}

// ===== out[d,n] = sum_c ctx[c,d]*q[c,n]; fused transpose+split fp16 epilogue ====
__global__ __launch_bounds__(256) void attnout_kernel(const float* __restrict__ ctx,
                                                      const float* __restrict__ qkv,
                                                      __half* __restrict__ oth,
                                                      __half* __restrict__ otl)
{
    __shared__ union {
        struct { float Cs[32][65]; float Qs[32][128]; } a;
        float tb[64][68];
    } sm;
    int bh = blockIdx.y;
    int b = bh >> 3, hh = bh & 7;
    int n0 = blockIdx.x * 128;
    const float* qb = qkv + (long)b * OQKV * HW + (long)(hh * DIMH) * HW;
    const float* cb = ctx + (long)bh * 4096;
    int t = threadIdx.x, tx = t & 15, ty = t >> 4;

    float acc[4][8] = {};
    for (int k0 = 0; k0 < 64; k0 += 32) {
        #pragma unroll
        for (int i = 0; i < 2; i++) {
            int idx = t + i * 256;
            int row = idx >> 4;
            int col = (idx & 15) << 2;
            float4 cv = *(const float4*)(cb + (long)(k0 + row) * 64 + col);
            sm.a.Cs[row][col] = cv.x; sm.a.Cs[row][col + 1] = cv.y;
            sm.a.Cs[row][col + 2] = cv.z; sm.a.Cs[row][col + 3] = cv.w;
        }
        #pragma unroll
        for (int i = 0; i < 4; i++) {
            int idx = t + i * 256;
            int row = idx >> 5;
            int col = (idx & 31) << 2;
            *(float4*)&sm.a.Qs[row][col] =
                *(const float4*)(qb + (long)(k0 + row) * HW + n0 + col);
        }
        __syncthreads();
        #pragma unroll
        for (int kk = 0; kk < 32; kk++) {
            float a[4];
            #pragma unroll
            for (int i = 0; i < 4; i++) a[i] = sm.a.Cs[kk][ty * 4 + i];
            float4 q0 = *(const float4*)&sm.a.Qs[kk][tx * 4];
            float4 q1 = *(const float4*)&sm.a.Qs[kk][64 + tx * 4];
            float bb[8] = {q0.x, q0.y, q0.z, q0.w, q1.x, q1.y, q1.z, q1.w};
            #pragma unroll
            for (int i = 0; i < 4; i++)
                #pragma unroll
                for (int j = 0; j < 8; j++) acc[i][j] += a[i] * bb[j];
        }
        __syncthreads();
    }

    // fused epilogue: transpose 64d x 128n tile, emit fp16 hi/lo at [b][n][hidden]
    #pragma unroll
    for (int half = 0; half < 2; half++) {
        __syncthreads();
        #pragma unroll
        for (int i = 0; i < 4; i++)
            #pragma unroll
            for (int j = 0; j < 4; j++)
                sm.tb[ty * 4 + i][tx * 4 + j] = acc[i][half * 4 + j];
        __syncthreads();
        int n_local = t >> 2, dseg = (t & 3) * 16;
        alignas(16) __half hs[16];
        alignas(16) __half ls[16];
        #pragma unroll
        for (int dd = 0; dd < 16; dd++) {
            float v = sm.tb[dseg + dd][n_local];
            __half h = __float2half_rn(v);
            hs[dd] = h;
            ls[dd] = __float2half_rn(v - __half2float(h));
        }
        long base = ((long)b * HW + n0 + half * 64 + n_local) * HIDDEN + hh * DIMH + dseg;
        *(uint4*)(oth + base) = *(uint4*)&hs[0];
        *(uint4*)(oth + base + 8) = *(uint4*)&hs[8];
        *(uint4*)(otl + base) = *(uint4*)&ls[0];
        *(uint4*)(otl + base + 8) = *(uint4*)&ls[8];
    }
}

// ================= launch =================
extern "C" void kernel_launch(void* const* d_in, const int* in_sizes, int n_in,
                              void* d_out, int out_size)
{
    const float* x     = (const float*)d_in[0];   // (16,512,64,64)
    const float* w_qkv = (const float*)d_in[1];   // (1536,512)
    const float* w_out = (const float*)d_in[2];   // (512,512)
    const float* b_out = (const float*)d_in[3];   // (512,)
    float* y = (float*)d_out;

    float *qkv, *part, *ctx;
    float2* stats;
    __half *xt, *oth, *otl, *wq, *wo;
    cudaGetSymbolAddress((void**)&qkv,   g_qkv);
    cudaGetSymbolAddress((void**)&part,  g_ctx_part);
    cudaGetSymbolAddress((void**)&ctx,   g_ctx);
    cudaGetSymbolAddress((void**)&stats, g_stats);
    cudaGetSymbolAddress((void**)&xt,    g_xt);
    cudaGetSymbolAddress((void**)&oth,   g_ot_hi);
    cudaGetSymbolAddress((void**)&otl,   g_ot_lo);
    cudaGetSymbolAddress((void**)&wq,    g_wq);
    cudaGetSymbolAddress((void**)&wo,    g_wo);

    cudaFuncSetAttribute(gemm_fp16_kernel<1, 4>,
                         cudaFuncAttributeMaxDynamicSharedMemorySize, GEMM1_SMEM);
    cudaFuncSetAttribute(gemm_fp16_kernel<2, 3>,
                         cudaFuncAttributeMaxDynamicSharedMemorySize, GEMM2_SMEM);

    // 0. weight + input conversions
    conv_half_kernel<<<(OQKV * CDIM + 255) / 256, 256>>>(w_qkv, wq, OQKV * CDIM);
    conv_half_kernel<<<(HIDDEN * HIDDEN + 255) / 256, 256>>>(w_out, wo, HIDDEN * HIDDEN);
    trans_half_kernel<<<dim3(HW / 32, CDIM / 32, BATCH), 256>>>(x, xt, CDIM, HW);

    // 1. qkv = w_qkv @ x   (single-pass fp16 HMMA, 128x128 tile, 4 warps, 2 CTA/SM)
    gemm_fp16_kernel<1, 4><<<dim3(HW / 128, OQKV / 128, BATCH), 128, GEMM1_SMEM>>>(
        wq, xt, nullptr, qkv, nullptr,
        OQKV, HW, CDIM, (long)HW * CDIM, (long)OQKV * HW);

    // 2. softmax row stats (max, 1/sumexp) — normalization fused downstream
    rowstat_kernel<<<8192, 256>>>(qkv, stats);
    // 3. context = softmax(k) @ v^T (exp fused into tile load)
    ctx_kernel<<<dim3(SPLIT, 128), 256>>>(qkv, stats, part);
    ctx_reduce_kernel<<<2048, 256>>>(part, stats, ctx);
    // 4. out = ctx^T @ q, writing transposed fp16 hi/lo directly (GEMM2 B operand)
    attnout_kernel<<<dim3(32, 128), 256>>>(ctx, qkv, oth, otl);

    // 5. y = w_out @ out + b_out   (2-pass fp16 HMMA for output accuracy)
    gemm_fp16_kernel<2, 3><<<dim3(HW / 128, HIDDEN / 128, BATCH), 128, GEMM2_SMEM>>>(
        wo, oth, otl, y, b_out,
        HIDDEN, HW, HIDDEN, (long)HW * HIDDEN, (long)HIDDEN * HW);
}

// round 10
// speedup vs baseline: 3.2142x; 1.0537x over previous
#include <cuda_runtime.h>
#include <cuda_fp16.h>
#include <cstdint>

#define HEADS  8
#define DIMH   64
#define BATCH  16
#define CDIM   512
#define HW     4096
#define HIDDEN 512
#define OQKV   1536
#define SPLIT  8

// ---------------- scratch (no allocations allowed) ----------------
__device__ float g_qkv[(size_t)BATCH * OQKV * HW];            // 402 MB
__device__ float g_ctx_part[(size_t)SPLIT * BATCH * HEADS * DIMH * DIMH];
__device__ float g_ctx[(size_t)BATCH * HEADS * DIMH * DIMH];
__device__ float2 g_stats[(size_t)BATCH * HIDDEN];            // per k-row {max, 1/sum}
__device__ __half g_xt[(size_t)BATCH * HW * CDIM];            // 67 MB
__device__ __half g_ot[(size_t)BATCH * HW * HIDDEN];          // 67 MB
__device__ __half g_wq[(size_t)OQKV * CDIM];
__device__ __half g_wo[(size_t)HIDDEN * HIDDEN];

// ================= PTX helpers =================
__device__ __forceinline__ uint32_t smem_u32(const void* p) {
    uint32_t a;
    asm("{ .reg .u64 t; cvta.to.shared.u64 t, %1; cvt.u32.u64 %0, t; }"
        : "=r"(a) : "l"(p));
    return a;
}
__device__ __forceinline__ void cp_async16(uint32_t dst, const void* src) {
    asm volatile("cp.async.cg.shared.global [%0], [%1], 16;"
                 :: "r"(dst), "l"(src));
}
#define CP_COMMIT() asm volatile("cp.async.commit_group;")
#define CP_WAIT(n)  asm volatile("cp.async.wait_group %0;" :: "n"(n))

__device__ __forceinline__ void ldmx4(uint32_t* r, uint32_t addr) {
    asm volatile("ldmatrix.sync.aligned.m8n8.x4.shared.b16 {%0,%1,%2,%3}, [%4];"
                 : "=r"(r[0]), "=r"(r[1]), "=r"(r[2]), "=r"(r[3]) : "r"(addr));
}
__device__ __forceinline__ void mma16816(float* d, const uint32_t* a,
                                         uint32_t b0, uint32_t b1) {
    asm volatile(
        "mma.sync.aligned.m16n8k16.row.col.f32.f16.f16.f32 "
        "{%0,%1,%2,%3}, {%4,%5,%6,%7}, {%8,%9}, {%0,%1,%2,%3};"
        : "+f"(d[0]), "+f"(d[1]), "+f"(d[2]), "+f"(d[3])
        : "r"(a[0]), "r"(a[1]), "r"(a[2]), "r"(a[3]), "r"(b0), "r"(b1));
}

// packed f32x2 (2x fp32 FMA rate; proven on this harness in R1)
__device__ __forceinline__ unsigned long long f32x2_dup(float a) {
    unsigned long long r;
    asm("mov.b64 %0, {%1, %1};" : "=l"(r) : "f"(a));
    return r;
}
__device__ __forceinline__ unsigned long long f32x2_fma(unsigned long long a,
                                                        unsigned long long b,
                                                        unsigned long long c) {
    unsigned long long d;
    asm("fma.rn.f32x2 %0, %1, %2, %3;" : "=l"(d) : "l"(a), "l"(b), "l"(c));
    return d;
}
__device__ __forceinline__ float2 f32x2_unpack(unsigned long long v) {
    float2 f;
    asm("mov.b64 {%0, %1}, %2;" : "=f"(f.x), "=f"(f.y) : "l"(v));
    return f;
}

// ================= fp16 single-pass HMMA GEMM =================
// C[z][M,N] = A[M,K] @ B[z][N,K]^T; CTA 128x128, 128 threads (4 warps, 64x64),
// BK=32, 4-stage cp.async, 2 CTAs/SM.
#define ROWB 80
#define HALF_TILE (128 * ROWB)           // 10240 per 128x32 fp16 tile
#define NSTAGE 4
#define GEMM_SMEM (NSTAGE * 2 * HALF_TILE)   // 81920

__global__ __launch_bounds__(128, 2) void gemm_fp16_kernel(
    const __half* __restrict__ Ah, const __half* __restrict__ Bh_,
    float* __restrict__ C, const float* __restrict__ bias,
    int M, int N, int K, long strideB, long strideC)
{
    constexpr int STAGE_BYTES = 2 * HALF_TILE;
    extern __shared__ char smem[];
    const uint32_t sb = smem_u32(smem);

    const int t = threadIdx.x;
    const int lane = t & 31, wid = t >> 5;
    const int m_off = (wid & 1) * 64, n_off = (wid >> 1) * 64;
    const int m0 = blockIdx.y * 128, n0 = blockIdx.x * 128;
    const long z = blockIdx.z;
    const __half* Bh = Bh_ + z * strideB;

    const int lrow0 = t >> 2, lch = t & 3;
    const uint32_t aBase = sb + (uint32_t)((m_off + (lane & 15)) * ROWB + (lane >> 4) * 16);
    const uint32_t bBase = sb + HALF_TILE +
        (uint32_t)((n_off + (lane & 7) + ((lane >> 4) << 3)) * ROWB + ((lane >> 3) & 1) * 16);

    float acc[4][8][4];
    #pragma unroll
    for (int i = 0; i < 4; i++)
        #pragma unroll
        for (int j = 0; j < 8; j++)
            #pragma unroll
            for (int r = 0; r < 4; r++) acc[i][j][r] = 0.f;

    const int nst = K / 32;

    auto load_stage = [&](int s) {
        const int k0 = s * 32;
        const uint32_t bufb = sb + (uint32_t)((s % NSTAGE) * STAGE_BYTES);
        #pragma unroll
        for (int p = 0; p < 4; p++) {
            int row = lrow0 + p * 32;
            cp_async16(bufb + (uint32_t)(row * ROWB + lch * 16),
                       Ah + (long)(m0 + row) * K + k0 + lch * 8);
            cp_async16(bufb + HALF_TILE + (uint32_t)(row * ROWB + lch * 16),
                       Bh + (long)(n0 + row) * K + k0 + lch * 8);
        }
        CP_COMMIT();
    };

    #pragma unroll
    for (int s = 0; s < NSTAGE - 1; s++) load_stage(s);

    for (int s = 0; s < nst; s++) {
        if (s + NSTAGE - 1 < nst) { load_stage(s + NSTAGE - 1); CP_WAIT(NSTAGE - 2); }
        else                      { CP_WAIT(0); }
        __syncthreads();

        const uint32_t bufo = (uint32_t)((s % NSTAGE) * STAGE_BYTES);
        #pragma unroll
        for (int ks = 0; ks < 2; ks++) {
            uint32_t bh[16];
            #pragma unroll
            for (int nj = 0; nj < 4; nj++)
                ldmx4(&bh[nj * 4], bBase + bufo + (uint32_t)(nj * 16 * ROWB + ks * 32));
            #pragma unroll
            for (int mi = 0; mi < 4; mi++) {
                uint32_t ah[4];
                ldmx4(ah, aBase + bufo + (uint32_t)(mi * 16 * ROWB + ks * 32));
                #pragma unroll
                for (int j = 0; j < 8; j++) {
                    int bi = (j >> 1) * 4 + (j & 1) * 2;
                    mma16816(acc[mi][j], ah, bh[bi], bh[bi + 1]);
                }
            }
        }
        __syncthreads();
    }

    float* Cz = C + z * strideC;
    const int mrow = m0 + m_off + (lane >> 2);
    const int ncol = n0 + n_off + (lane & 3) * 2;
    #pragma unroll
    for (int mi = 0; mi < 4; mi++) {
        int r0 = mrow + mi * 16;
        float bv0 = bias ? bias[r0] : 0.f;
        float bv1 = bias ? bias[r0 + 8] : 0.f;
        #pragma unroll
        for (int j = 0; j < 8; j++) {
            int cc = ncol + j * 8;
            *(float2*)(Cz + (long)r0 * N + cc) =
                make_float2(acc[mi][j][0] + bv0, acc[mi][j][1] + bv0);
            *(float2*)(Cz + (long)(r0 + 8) * N + cc) =
                make_float2(acc[mi][j][2] + bv1, acc[mi][j][3] + bv1);
        }
    }
}

// ================= conversion kernels =================
__global__ __launch_bounds__(256) void conv_half_kernel(
    const float* __restrict__ w, __half* __restrict__ hi, int n)
{
    int i = blockIdx.x * 256 + threadIdx.x;
    if (i < n) hi[i] = __float2half_rn(w[i]);
}

__global__ __launch_bounds__(256) void trans_half_kernel(
    const float* __restrict__ in, __half* __restrict__ oh, int R, int Cc)
{
    __shared__ float tile[32][33];
    const int z = blockIdx.z;
    const int c0 = blockIdx.x * 32, r0 = blockIdx.y * 32;
    const int tx = threadIdx.x & 31, ty = threadIdx.x >> 5;
    const float* ip = in + (long)z * R * Cc;
    #pragma unroll
    for (int i = 0; i < 4; i++)
        tile[ty + 8 * i][tx] = ip[(long)(r0 + ty + 8 * i) * Cc + c0 + tx];
    __syncthreads();
    #pragma unroll
    for (int i = 0; i < 4; i++) {
        long o = ((long)z * Cc + c0 + ty + 8 * i) * R + r0 + tx;
        oh[o] = __float2half_rn(tile[tx][ty + 8 * i]);
    }
}

// ================= row stats for softmax(k): {max, 1/sumexp} ============
__device__ __forceinline__ float warp_rmax(float v) {
    #pragma unroll
    for (int o = 16; o; o >>= 1) v = fmaxf(v, __shfl_xor_sync(0xffffffffu, v, o));
    return v;
}
__device__ __forceinline__ float warp_rsum(float v) {
    #pragma unroll
    for (int o = 16; o; o >>= 1) v += __shfl_xor_sync(0xffffffffu, v, o);
    return v;
}

__global__ __launch_bounds__(256) void rowstat_kernel(const float* __restrict__ qkv,
                                                      float2* __restrict__ stats)
{
    int row = blockIdx.x;
    int b = row >> 9, ch = row & 511;
    const float4* p = (const float4*)(qkv + (long)b * OQKV * HW + (long)(HIDDEN + ch) * HW);
    int t = threadIdx.x;

    float4 v[4];
    float m = -1e30f;
    #pragma unroll
    for (int i = 0; i < 4; i++) {
        v[i] = p[t + i * 256];
        m = fmaxf(m, fmaxf(fmaxf(v[i].x, v[i].y), fmaxf(v[i].z, v[i].w)));
    }
    __shared__ float red[8];
    m = warp_rmax(m);
    if ((t & 31) == 0) red[t >> 5] = m;
    __syncthreads();
    float bm = red[0];
    #pragma unroll
    for (int i = 1; i < 8; i++) bm = fmaxf(bm, red[i]);

    float s = 0.f;
    #pragma unroll
    for (int i = 0; i < 4; i++) {
        s += __expf(v[i].x - bm) + __expf(v[i].y - bm) +
             __expf(v[i].z - bm) + __expf(v[i].w - bm);
    }
    s = warp_rsum(s);
    __syncthreads();
    if ((t & 31) == 0) red[t >> 5] = s;
    __syncthreads();
    if (t == 0) {
        float bs = 0.f;
        #pragma unroll
        for (int i = 0; i < 8; i++) bs += red[i];
        stats[row] = make_float2(bm, 1.0f / bs);
    }
}

// ====== context = softmax(k) @ v^T (exp fused, split-K, f32x2 core) ======
__global__ __launch_bounds__(256) void ctx_kernel(const float* __restrict__ qkv,
                                                  const float2* __restrict__ stats,
                                                  float* __restrict__ part)
{
    __shared__ float Ks[64][65];   // [d][n]
    __shared__ float Vs[64][66];   // [n][d]  (transposed; 66 -> 8B-aligned rows)
    __shared__ float sm_m[64];
    int bh = blockIdx.y;
    int b = bh >> 3, hh = bh & 7;
    int split = blockIdx.x;
    const float* kb = qkv + (long)b * OQKV * HW + (long)(HIDDEN + hh * DIMH) * HW;
    const float* vb = qkv + (long)b * OQKV * HW + (long)(2 * HIDDEN + hh * DIMH) * HW;
    int t = threadIdx.x, tx = t & 15, ty = t >> 4;

    if (t < 64) sm_m[t] = stats[b * HIDDEN + hh * DIMH + t].x;
    __syncthreads();

    unsigned long long acc2[4][2];
    #pragma unroll
    for (int i = 0; i < 4; i++) { acc2[i][0] = 0ull; acc2[i][1] = 0ull; }

    for (int chunk = 0; chunk < 8; chunk++) {
        int n0 = split * 512 + chunk * 64;
        #pragma unroll
        for (int i = 0; i < 4; i++) {
            int idx = t + i * 256;
            int row = idx >> 4;            // d
            int col = (idx & 15) << 2;     // n
            float mrow = sm_m[row];
            float4 kv = *(const float4*)(kb + (long)row * HW + n0 + col);
            Ks[row][col] = __expf(kv.x - mrow); Ks[row][col + 1] = __expf(kv.y - mrow);
            Ks[row][col + 2] = __expf(kv.z - mrow); Ks[row][col + 3] = __expf(kv.w - mrow);
            float4 vv = *(const float4*)(vb + (long)row * HW + n0 + col);
            Vs[col + 0][row] = vv.x; Vs[col + 1][row] = vv.y;
            Vs[col + 2][row] = vv.z; Vs[col + 3][row] = vv.w;
        }
        __syncthreads();
        #pragma unroll 4
        for (int nn = 0; nn < 64; nn++) {
            const unsigned long long* bp =
                (const unsigned long long*)&Vs[nn][tx * 4];
            unsigned long long b0 = bp[0], b1 = bp[1];
            #pragma unroll
            for (int i = 0; i < 4; i++) {
                unsigned long long ap = f32x2_dup(Ks[ty * 4 + i][nn]);
                acc2[i][0] = f32x2_fma(ap, b0, acc2[i][0]);
                acc2[i][1] = f32x2_fma(ap, b1, acc2[i][1]);
            }
        }
        __syncthreads();
    }
    float* dst = part + ((long)split * 128 + bh) * 4096;
    #pragma unroll
    for (int i = 0; i < 4; i++) {
        float2 p0 = f32x2_unpack(acc2[i][0]);
        float2 p1 = f32x2_unpack(acc2[i][1]);
        float* r = dst + (ty * 4 + i) * 64 + tx * 4;
        r[0] = p0.x; r[1] = p0.y; r[2] = p1.x; r[3] = p1.y;
    }
}

__global__ __launch_bounds__(256) void ctx_reduce_kernel(const float* __restrict__ part,
                                                         const float2* __restrict__ stats,
                                                         float* __restrict__ ctx)
{
    long i = (long)blockIdx.x * 256 + threadIdx.x;
    float s = 0.f;
    #pragma unroll
    for (int sp = 0; sp < SPLIT; sp++) s += part[(long)sp * 524288 + i];
    int bh = (int)(i >> 12);
    int c  = (int)((i >> 6) & 63);
    float inv = stats[(bh >> 3) * HIDDEN + (bh & 7) * DIMH + c].y;
    ctx[i] = s * inv;
}

// == out[d,n] = sum_c ctx[c,d]*q[c,n]; f32x2 core; fused transposed fp16 epi ==
__global__ __launch_bounds__(256) void attnout_kernel(const float* __restrict__ ctx,
                                                      const float* __restrict__ qkv,
                                                      __half* __restrict__ ot)
{
    __shared__ union {
        struct { float Cs[32][65]; float Qs[32][128]; } a;
        float tb[64][68];
    } sm;
    int bh = blockIdx.y;
    int b = bh >> 3, hh = bh & 7;
    int n0 = blockIdx.x * 128;
    const float* qb = qkv + (long)b * OQKV * HW + (long)(hh * DIMH) * HW;
    const float* cb = ctx + (long)bh * 4096;
    int t = threadIdx.x, tx = t & 15, ty = t >> 4;

    unsigned long long acc2[4][4];
    #pragma unroll
    for (int i = 0; i < 4; i++)
        #pragma unroll
        for (int j = 0; j < 4; j++) acc2[i][j] = 0ull;

    for (int k0 = 0; k0 < 64; k0 += 32) {
        #pragma unroll
        for (int i = 0; i < 2; i++) {
            int idx = t + i * 256;
            int row = idx >> 4;
            int col = (idx & 15) << 2;
            float4 cv = *(const float4*)(cb + (long)(k0 + row) * 64 + col);
            sm.a.Cs[row][col] = cv.x; sm.a.Cs[row][col + 1] = cv.y;
            sm.a.Cs[row][col + 2] = cv.z; sm.a.Cs[row][col + 3] = cv.w;
        }
        #pragma unroll
        for (int i = 0; i < 4; i++) {
            int idx = t + i * 256;
            int row = idx >> 5;
            int col = (idx & 31) << 2;
            *(float4*)&sm.a.Qs[row][col] =
                *(const float4*)(qb + (long)(k0 + row) * HW + n0 + col);
        }
        __syncthreads();
        #pragma unroll 4
        for (int kk = 0; kk < 32; kk++) {
            const unsigned long long* q0p =
                (const unsigned long long*)&sm.a.Qs[kk][tx * 4];
            const unsigned long long* q1p =
                (const unsigned long long*)&sm.a.Qs[kk][64 + tx * 4];
            unsigned long long b0 = q0p[0], b1 = q0p[1];
            unsigned long long b2 = q1p[0], b3 = q1p[1];
            #pragma unroll
            for (int i = 0; i < 4; i++) {
                unsigned long long ap = f32x2_dup(sm.a.Cs[kk][ty * 4 + i]);
                acc2[i][0] = f32x2_fma(ap, b0, acc2[i][0]);
                acc2[i][1] = f32x2_fma(ap, b1, acc2[i][1]);
                acc2[i][2] = f32x2_fma(ap, b2, acc2[i][2]);
                acc2[i][3] = f32x2_fma(ap, b3, acc2[i][3]);
            }
        }
        __syncthreads();
    }

    // epilogue: transpose 64d x 128n tile, emit fp16 at [b][n][hidden]
    #pragma unroll
    for (int half = 0; half < 2; half++) {
        __syncthreads();
        #pragma unroll
        for (int i = 0; i < 4; i++) {
            float2 pa = f32x2_unpack(acc2[i][half * 2 + 0]);
            float2 pb = f32x2_unpack(acc2[i][half * 2 + 1]);
            sm.tb[ty * 4 + i][tx * 4 + 0] = pa.x;
            sm.tb[ty * 4 + i][tx * 4 + 1] = pa.y;
            sm.tb[ty * 4 + i][tx * 4 + 2] = pb.x;
            sm.tb[ty * 4 + i][tx * 4 + 3] = pb.y;
        }
        __syncthreads();
        int n_local = t >> 2, dseg = (t & 3) * 16;
        alignas(16) __half hs[16];
        #pragma unroll
        for (int dd = 0; dd < 16; dd++)
            hs[dd] = __float2half_rn(sm.tb[dseg + dd][n_local]);
        long base = ((long)b * HW + n0 + half * 64 + n_local) * HIDDEN + hh * DIMH + dseg;
        *(uint4*)(ot + base)     = *(uint4*)&hs[0];
        *(uint4*)(ot + base + 8) = *(uint4*)&hs[8];
    }
}

// ================= launch =================
extern "C" void kernel_launch(void* const* d_in, const int* in_sizes, int n_in,
                              void* d_out, int out_size)
{
    const float* x     = (const float*)d_in[0];   // (16,512,64,64)
    const float* w_qkv = (const float*)d_in[1];   // (1536,512)
    const float* w_out = (const float*)d_in[2];   // (512,512)
    const float* b_out = (const float*)d_in[3];   // (512,)
    float* y = (float*)d_out;

    float *qkv, *part, *ctx;
    float2* stats;
    __half *xt, *ot, *wq, *wo;
    cudaGetSymbolAddress((void**)&qkv,   g_qkv);
    cudaGetSymbolAddress((void**)&part,  g_ctx_part);
    cudaGetSymbolAddress((void**)&ctx,   g_ctx);
    cudaGetSymbolAddress((void**)&stats, g_stats);
    cudaGetSymbolAddress((void**)&xt,    g_xt);
    cudaGetSymbolAddress((void**)&ot,    g_ot);
    cudaGetSymbolAddress((void**)&wq,    g_wq);
    cudaGetSymbolAddress((void**)&wo,    g_wo);

    cudaFuncSetAttribute(gemm_fp16_kernel,
                         cudaFuncAttributeMaxDynamicSharedMemorySize, GEMM_SMEM);

    // 0. weight + input conversions
    conv_half_kernel<<<(OQKV * CDIM + 255) / 256, 256>>>(w_qkv, wq, OQKV * CDIM);
    conv_half_kernel<<<(HIDDEN * HIDDEN + 255) / 256, 256>>>(w_out, wo, HIDDEN * HIDDEN);
    trans_half_kernel<<<dim3(HW / 32, CDIM / 32, BATCH), 256>>>(x, xt, CDIM, HW);

    // 1. qkv = w_qkv @ x   (single-pass fp16 HMMA)
    gemm_fp16_kernel<<<dim3(HW / 128, OQKV / 128, BATCH), 128, GEMM_SMEM>>>(
        wq, xt, qkv, nullptr,
        OQKV, HW, CDIM, (long)HW * CDIM, (long)OQKV * HW);

    // 2. softmax row stats
    rowstat_kernel<<<8192, 256>>>(qkv, stats);
    // 3. context = softmax(k) @ v^T (f32x2 core)
    ctx_kernel<<<dim3(SPLIT, 128), 256>>>(qkv, stats, part);
    ctx_reduce_kernel<<<2048, 256>>>(part, stats, ctx);
    // 4. out = ctx^T @ q (f32x2 core), fused transposed fp16 epilogue
    attnout_kernel<<<dim3(32, 128), 256>>>(ctx, qkv, ot);

    // 5. y = w_out @ out + b_out   (single-pass fp16 HMMA)
    gemm_fp16_kernel<<<dim3(HW / 128, HIDDEN / 128, BATCH), 128, GEMM_SMEM>>>(
        wo, ot, y, b_out,
        HIDDEN, HW, HIDDEN, (long)HW * HIDDEN, (long)HIDDEN * HW);
}

// round 11
// speedup vs baseline: 3.5743x; 1.1120x over previous
#include <cuda_runtime.h>
#include <cuda_fp16.h>
#include <cstdint>

#define HEADS  8
#define DIMH   64
#define BATCH  16
#define CDIM   512
#define HW     4096
#define HIDDEN 512
#define OQKV   1536
#define SPLIT  8

// ---------------- scratch (no allocations allowed) ----------------
__device__ float  g_k[(size_t)BATCH * HIDDEN * HW];           // 134 MB (f32 k)
__device__ __half g_q16[(size_t)BATCH * HIDDEN * HW];         // 67 MB
__device__ __half g_v16[(size_t)BATCH * HIDDEN * HW];         // 67 MB
__device__ __half g_qt[(size_t)BATCH * HW * HIDDEN];          // 67 MB (q^T, GEMM2 B)
__device__ float  g_ctx_part[(size_t)SPLIT * BATCH * HEADS * DIMH * DIMH];
__device__ float  g_ctx[(size_t)BATCH * HEADS * DIMH * DIMH];
__device__ float2 g_stats[(size_t)BATCH * HIDDEN];
__device__ __half g_mcat[(size_t)BATCH * HIDDEN * HIDDEN];    // 8 MB
__device__ __half g_xt[(size_t)BATCH * HW * CDIM];            // 67 MB
__device__ __half g_wq[(size_t)OQKV * CDIM];

// ================= PTX helpers =================
__device__ __forceinline__ uint32_t smem_u32(const void* p) {
    uint32_t a;
    asm("{ .reg .u64 t; cvta.to.shared.u64 t, %1; cvt.u32.u64 %0, t; }"
        : "=r"(a) : "l"(p));
    return a;
}
__device__ __forceinline__ void cp_async16(uint32_t dst, const void* src) {
    asm volatile("cp.async.cg.shared.global [%0], [%1], 16;"
                 :: "r"(dst), "l"(src));
}
#define CP_COMMIT() asm volatile("cp.async.commit_group;")
#define CP_WAIT(n)  asm volatile("cp.async.wait_group %0;" :: "n"(n))

__device__ __forceinline__ void ldmx4(uint32_t* r, uint32_t addr) {
    asm volatile("ldmatrix.sync.aligned.m8n8.x4.shared.b16 {%0,%1,%2,%3}, [%4];"
                 : "=r"(r[0]), "=r"(r[1]), "=r"(r[2]), "=r"(r[3]) : "r"(addr));
}
__device__ __forceinline__ void mma16816(float* d, const uint32_t* a,
                                         uint32_t b0, uint32_t b1) {
    asm volatile(
        "mma.sync.aligned.m16n8k16.row.col.f32.f16.f16.f32 "
        "{%0,%1,%2,%3}, {%4,%5,%6,%7}, {%8,%9}, {%0,%1,%2,%3};"
        : "+f"(d[0]), "+f"(d[1]), "+f"(d[2]), "+f"(d[3])
        : "r"(a[0]), "r"(a[1]), "r"(a[2]), "r"(a[3]), "r"(b0), "r"(b1));
}

// packed f32x2
__device__ __forceinline__ unsigned long long f32x2_dup(float a) {
    unsigned long long r;
    asm("mov.b64 %0, {%1, %1};" : "=l"(r) : "f"(a));
    return r;
}
__device__ __forceinline__ unsigned long long f32x2_fma(unsigned long long a,
                                                        unsigned long long b,
                                                        unsigned long long c) {
    unsigned long long d;
    asm("fma.rn.f32x2 %0, %1, %2, %3;" : "=l"(d) : "l"(a), "l"(b), "l"(c));
    return d;
}
__device__ __forceinline__ float2 f32x2_unpack(unsigned long long v) {
    float2 f;
    asm("mov.b64 {%0, %1}, %2;" : "=f"(f.x), "=f"(f.y) : "l"(v));
    return f;
}

// ================= GEMM common config =================
#define ROWB 80
#define HALF_TILE (128 * ROWB)           // 10240 per 128x32 fp16 tile
#define NSTAGE 4
#define GEMM_SMEM (NSTAGE * 2 * HALF_TILE)   // 81920

// ======== GEMM1: qkv = wq @ xt^T, split outputs (q fp16, k f32, v fp16) ====
__global__ __launch_bounds__(128, 2) void gemm1_kernel(
    const __half* __restrict__ Ah, const __half* __restrict__ Bh_,
    __half* __restrict__ qo, float* __restrict__ ko, __half* __restrict__ vo)
{
    constexpr int STAGE_BYTES = 2 * HALF_TILE;
    constexpr int K = CDIM, N = HW;
    extern __shared__ char smem[];
    const uint32_t sb = smem_u32(smem);

    const int t = threadIdx.x;
    const int lane = t & 31, wid = t >> 5;
    const int m_off = (wid & 1) * 64, n_off = (wid >> 1) * 64;
    const int m0 = blockIdx.y * 128, n0 = blockIdx.x * 128;
    const long z = blockIdx.z;
    const __half* Bh = Bh_ + z * (long)N * K;

    const int lrow0 = t >> 2, lch = t & 3;
    const uint32_t aBase = sb + (uint32_t)((m_off + (lane & 15)) * ROWB + (lane >> 4) * 16);
    const uint32_t bBase = sb + HALF_TILE +
        (uint32_t)((n_off + (lane & 7) + ((lane >> 4) << 3)) * ROWB + ((lane >> 3) & 1) * 16);

    float acc[4][8][4];
    #pragma unroll
    for (int i = 0; i < 4; i++)
        #pragma unroll
        for (int j = 0; j < 8; j++)
            #pragma unroll
            for (int r = 0; r < 4; r++) acc[i][j][r] = 0.f;

    const int nst = K / 32;

    auto load_stage = [&](int s) {
        const int k0 = s * 32;
        const uint32_t bufb = sb + (uint32_t)((s % NSTAGE) * STAGE_BYTES);
        #pragma unroll
        for (int p = 0; p < 4; p++) {
            int row = lrow0 + p * 32;
            cp_async16(bufb + (uint32_t)(row * ROWB + lch * 16),
                       Ah + (long)(m0 + row) * K + k0 + lch * 8);
            cp_async16(bufb + HALF_TILE + (uint32_t)(row * ROWB + lch * 16),
                       Bh + (long)(n0 + row) * K + k0 + lch * 8);
        }
        CP_COMMIT();
    };

    #pragma unroll
    for (int s = 0; s < NSTAGE - 1; s++) load_stage(s);

    for (int s = 0; s < nst; s++) {
        if (s + NSTAGE - 1 < nst) { load_stage(s + NSTAGE - 1); CP_WAIT(NSTAGE - 2); }
        else                      { CP_WAIT(0); }
        __syncthreads();

        const uint32_t bufo = (uint32_t)((s % NSTAGE) * STAGE_BYTES);
        #pragma unroll
        for (int ks = 0; ks < 2; ks++) {
            uint32_t bh[16];
            #pragma unroll
            for (int nj = 0; nj < 4; nj++)
                ldmx4(&bh[nj * 4], bBase + bufo + (uint32_t)(nj * 16 * ROWB + ks * 32));
            #pragma unroll
            for (int mi = 0; mi < 4; mi++) {
                uint32_t ah[4];
                ldmx4(ah, aBase + bufo + (uint32_t)(mi * 16 * ROWB + ks * 32));
                #pragma unroll
                for (int j = 0; j < 8; j++) {
                    int bi = (j >> 1) * 4 + (j & 1) * 2;
                    mma16816(acc[mi][j], ah, bh[bi], bh[bi + 1]);
                }
            }
        }
        __syncthreads();
    }

    // ---- split epilogue: seg 0 -> q fp16, 1 -> k f32, 2 -> v fp16 ----
    const int mrow = m0 + m_off + (lane >> 2);
    const int ncol = n0 + n_off + (lane & 3) * 2;
    #pragma unroll
    for (int mi = 0; mi < 4; mi++) {
        #pragma unroll
        for (int half = 0; half < 2; half++) {
            int r = mrow + mi * 16 + half * 8;
            int seg = r >> 9, lr = r & 511;
            long rowbase = ((long)z * HIDDEN + lr) * HW;
            #pragma unroll
            for (int j = 0; j < 8; j++) {
                int cc = ncol + j * 8;
                float a = acc[mi][j][half * 2 + 0];
                float b = acc[mi][j][half * 2 + 1];
                if (seg == 1) {
                    *(float2*)(ko + rowbase + cc) = make_float2(a, b);
                } else {
                    __half2 hv = __floats2half2_rn(a, b);
                    __half* p = (seg == 0 ? qo : vo) + rowbase + cc;
                    *(__half2*)p = hv;
                }
            }
        }
    }
}

// ======== GEMM2: y[z] = mcat[z] @ qt[z]^T + bias  (fp16 HMMA) ========
__global__ __launch_bounds__(128, 2) void gemm2_kernel(
    const __half* __restrict__ A_, const __half* __restrict__ B_,
    float* __restrict__ C, const float* __restrict__ bias)
{
    constexpr int STAGE_BYTES = 2 * HALF_TILE;
    constexpr int K = HIDDEN, N = HW;
    extern __shared__ char smem[];
    const uint32_t sb = smem_u32(smem);

    const int t = threadIdx.x;
    const int lane = t & 31, wid = t >> 5;
    const int m_off = (wid & 1) * 64, n_off = (wid >> 1) * 64;
    const int m0 = blockIdx.y * 128, n0 = blockIdx.x * 128;
    const long z = blockIdx.z;
    const __half* Ah = A_ + z * (long)HIDDEN * HIDDEN;
    const __half* Bh = B_ + z * (long)N * K;

    const int lrow0 = t >> 2, lch = t & 3;
    const uint32_t aBase = sb + (uint32_t)((m_off + (lane & 15)) * ROWB + (lane >> 4) * 16);
    const uint32_t bBase = sb + HALF_TILE +
        (uint32_t)((n_off + (lane & 7) + ((lane >> 4) << 3)) * ROWB + ((lane >> 3) & 1) * 16);

    float acc[4][8][4];
    #pragma unroll
    for (int i = 0; i < 4; i++)
        #pragma unroll
        for (int j = 0; j < 8; j++)
            #pragma unroll
            for (int r = 0; r < 4; r++) acc[i][j][r] = 0.f;

    const int nst = K / 32;

    auto load_stage = [&](int s) {
        const int k0 = s * 32;
        const uint32_t bufb = sb + (uint32_t)((s % NSTAGE) * STAGE_BYTES);
        #pragma unroll
        for (int p = 0; p < 4; p++) {
            int row = lrow0 + p * 32;
            cp_async16(bufb + (uint32_t)(row * ROWB + lch * 16),
                       Ah + (long)(m0 + row) * K + k0 + lch * 8);
            cp_async16(bufb + HALF_TILE + (uint32_t)(row * ROWB + lch * 16),
                       Bh + (long)(n0 + row) * K + k0 + lch * 8);
        }
        CP_COMMIT();
    };

    #pragma unroll
    for (int s = 0; s < NSTAGE - 1; s++) load_stage(s);

    for (int s = 0; s < nst; s++) {
        if (s + NSTAGE - 1 < nst) { load_stage(s + NSTAGE - 1); CP_WAIT(NSTAGE - 2); }
        else                      { CP_WAIT(0); }
        __syncthreads();

        const uint32_t bufo = (uint32_t)((s % NSTAGE) * STAGE_BYTES);
        #pragma unroll
        for (int ks = 0; ks < 2; ks++) {
            uint32_t bh[16];
            #pragma unroll
            for (int nj = 0; nj < 4; nj++)
                ldmx4(&bh[nj * 4], bBase + bufo + (uint32_t)(nj * 16 * ROWB + ks * 32));
            #pragma unroll
            for (int mi = 0; mi < 4; mi++) {
                uint32_t ah[4];
                ldmx4(ah, aBase + bufo + (uint32_t)(mi * 16 * ROWB + ks * 32));
                #pragma unroll
                for (int j = 0; j < 8; j++) {
                    int bi = (j >> 1) * 4 + (j & 1) * 2;
                    mma16816(acc[mi][j], ah, bh[bi], bh[bi + 1]);
                }
            }
        }
        __syncthreads();
    }

    float* Cz = C + z * (long)HIDDEN * HW;
    const int mrow = m0 + m_off + (lane >> 2);
    const int ncol = n0 + n_off + (lane & 3) * 2;
    #pragma unroll
    for (int mi = 0; mi < 4; mi++) {
        int r0 = mrow + mi * 16;
        float bv0 = bias[r0];
        float bv1 = bias[r0 + 8];
        #pragma unroll
        for (int j = 0; j < 8; j++) {
            int cc = ncol + j * 8;
            *(float2*)(Cz + (long)r0 * N + cc) =
                make_float2(acc[mi][j][0] + bv0, acc[mi][j][1] + bv0);
            *(float2*)(Cz + (long)(r0 + 8) * N + cc) =
                make_float2(acc[mi][j][2] + bv1, acc[mi][j][3] + bv1);
        }
    }
}

// ================= conversion kernels =================
__global__ __launch_bounds__(256) void conv_half_kernel(
    const float* __restrict__ w, __half* __restrict__ hi, int n)
{
    int i = blockIdx.x * 256 + threadIdx.x;
    if (i < n) hi[i] = __float2half_rn(w[i]);
}

__global__ __launch_bounds__(256) void trans_half_kernel(
    const float* __restrict__ in, __half* __restrict__ oh, int R, int Cc)
{
    __shared__ float tile[32][33];
    const int z = blockIdx.z;
    const int c0 = blockIdx.x * 32, r0 = blockIdx.y * 32;
    const int tx = threadIdx.x & 31, ty = threadIdx.x >> 5;
    const float* ip = in + (long)z * R * Cc;
    #pragma unroll
    for (int i = 0; i < 4; i++)
        tile[ty + 8 * i][tx] = ip[(long)(r0 + ty + 8 * i) * Cc + c0 + tx];
    __syncthreads();
    #pragma unroll
    for (int i = 0; i < 4; i++) {
        long o = ((long)z * Cc + c0 + ty + 8 * i) * R + r0 + tx;
        oh[o] = __float2half_rn(tile[tx][ty + 8 * i]);
    }
}

// fp16 transpose: q16 [z][c][n] -> qt [z][n][c]
__global__ __launch_bounds__(256) void trans_q_kernel(
    const __half* __restrict__ q, __half* __restrict__ qt)
{
    __shared__ __half tile[64][65];
    const int z = blockIdx.z;
    const int n0 = blockIdx.x * 64, c0 = blockIdx.y * 64;
    const int t = threadIdx.x;
    const int row = t >> 2, seg = (t & 3) * 16;

    const __half* src = q + ((long)z * HIDDEN + c0 + row) * HW + n0 + seg;
    alignas(16) __half in[16];
    *(uint4*)&in[0] = *(const uint4*)src;
    *(uint4*)&in[8] = *(const uint4*)(src + 8);
    #pragma unroll
    for (int i = 0; i < 16; i++) tile[row][seg + i] = in[i];
    __syncthreads();
    alignas(16) __half outv[16];
    #pragma unroll
    for (int i = 0; i < 16; i++) outv[i] = tile[seg + i][row];
    __half* dst = qt + ((long)z * HW + n0 + row) * HIDDEN + c0 + seg;
    *(uint4*)dst = *(uint4*)&outv[0];
    *(uint4*)(dst + 8) = *(uint4*)&outv[8];
}

// ================= row stats for softmax(k) =================
__device__ __forceinline__ float warp_rmax(float v) {
    #pragma unroll
    for (int o = 16; o; o >>= 1) v = fmaxf(v, __shfl_xor_sync(0xffffffffu, v, o));
    return v;
}
__device__ __forceinline__ float warp_rsum(float v) {
    #pragma unroll
    for (int o = 16; o; o >>= 1) v += __shfl_xor_sync(0xffffffffu, v, o);
    return v;
}

__global__ __launch_bounds__(256) void rowstat_kernel(const float* __restrict__ kk,
                                                      float2* __restrict__ stats)
{
    int row = blockIdx.x;                 // b*512 + ch
    const float4* p = (const float4*)(kk + (long)row * HW);
    int t = threadIdx.x;

    float4 v[4];
    float m = -1e30f;
    #pragma unroll
    for (int i = 0; i < 4; i++) {
        v[i] = p[t + i * 256];
        m = fmaxf(m, fmaxf(fmaxf(v[i].x, v[i].y), fmaxf(v[i].z, v[i].w)));
    }
    __shared__ float red[8];
    m = warp_rmax(m);
    if ((t & 31) == 0) red[t >> 5] = m;
    __syncthreads();
    float bm = red[0];
    #pragma unroll
    for (int i = 1; i < 8; i++) bm = fmaxf(bm, red[i]);

    float s = 0.f;
    #pragma unroll
    for (int i = 0; i < 4; i++) {
        s += __expf(v[i].x - bm) + __expf(v[i].y - bm) +
             __expf(v[i].z - bm) + __expf(v[i].w - bm);
    }
    s = warp_rsum(s);
    __syncthreads();
    if ((t & 31) == 0) red[t >> 5] = s;
    __syncthreads();
    if (t == 0) {
        float bs = 0.f;
        #pragma unroll
        for (int i = 0; i < 8; i++) bs += red[i];
        stats[row] = make_float2(bm, 1.0f / bs);
    }
}

// ====== context = softmax(k) @ v^T (exp fused, split-K, f32x2 core) ======
__global__ __launch_bounds__(256) void ctx_kernel(const float* __restrict__ kk,
                                                  const __half* __restrict__ vv,
                                                  const float2* __restrict__ stats,
                                                  float* __restrict__ part)
{
    __shared__ float Ks[64][65];   // [d][n]
    __shared__ float Vs[64][66];   // [n][d]
    __shared__ float sm_m[64];
    int bh = blockIdx.y;
    int b = bh >> 3, hh = bh & 7;
    int split = blockIdx.x;
    const float* kb = kk + ((long)b * HIDDEN + hh * DIMH) * HW;
    const __half* vb = vv + ((long)b * HIDDEN + hh * DIMH) * HW;
    int t = threadIdx.x, tx = t & 15, ty = t >> 4;

    if (t < 64) sm_m[t] = stats[b * HIDDEN + hh * DIMH + t].x;
    __syncthreads();

    unsigned long long acc2[4][2];
    #pragma unroll
    for (int i = 0; i < 4; i++) { acc2[i][0] = 0ull; acc2[i][1] = 0ull; }

    for (int chunk = 0; chunk < 8; chunk++) {
        int n0 = split * 512 + chunk * 64;
        #pragma unroll
        for (int i = 0; i < 4; i++) {
            int idx = t + i * 256;
            int row = idx >> 4;            // d
            int col = (idx & 15) << 2;     // n
            float mrow = sm_m[row];
            float4 kv = *(const float4*)(kb + (long)row * HW + n0 + col);
            Ks[row][col] = __expf(kv.x - mrow); Ks[row][col + 1] = __expf(kv.y - mrow);
            Ks[row][col + 2] = __expf(kv.z - mrow); Ks[row][col + 3] = __expf(kv.w - mrow);
            uint2 raw = *(const uint2*)(vb + (long)row * HW + n0 + col);
            float2 f0 = __half22float2(*(__half2*)&raw.x);
            float2 f1 = __half22float2(*(__half2*)&raw.y);
            Vs[col + 0][row] = f0.x; Vs[col + 1][row] = f0.y;
            Vs[col + 2][row] = f1.x; Vs[col + 3][row] = f1.y;
        }
        __syncthreads();
        #pragma unroll 4
        for (int nn = 0; nn < 64; nn++) {
            const unsigned long long* bp =
                (const unsigned long long*)&Vs[nn][tx * 4];
            unsigned long long b0 = bp[0], b1 = bp[1];
            #pragma unroll
            for (int i = 0; i < 4; i++) {
                unsigned long long ap = f32x2_dup(Ks[ty * 4 + i][nn]);
                acc2[i][0] = f32x2_fma(ap, b0, acc2[i][0]);
                acc2[i][1] = f32x2_fma(ap, b1, acc2[i][1]);
            }
        }
        __syncthreads();
    }
    float* dst = part + ((long)split * 128 + bh) * 4096;
    #pragma unroll
    for (int i = 0; i < 4; i++) {
        float2 p0 = f32x2_unpack(acc2[i][0]);
        float2 p1 = f32x2_unpack(acc2[i][1]);
        float* r = dst + (ty * 4 + i) * 64 + tx * 4;
        r[0] = p0.x; r[1] = p0.y; r[2] = p1.x; r[3] = p1.y;
    }
}

__global__ __launch_bounds__(256) void ctx_reduce_kernel(const float* __restrict__ part,
                                                         const float2* __restrict__ stats,
                                                         float* __restrict__ ctx)
{
    long i = (long)blockIdx.x * 256 + threadIdx.x;
    float s = 0.f;
    #pragma unroll
    for (int sp = 0; sp < SPLIT; sp++) s += part[(long)sp * 524288 + i];
    int bh = (int)(i >> 12);
    int c  = (int)((i >> 6) & 63);
    float inv = stats[(bh >> 3) * HIDDEN + (bh & 7) * DIMH + c].y;
    ctx[i] = s * inv;
}

// ====== Mcat[b][o][h*64+c] = sum_d w_out[o][h*64+d] * ctx[b][h][c][d] ======
__global__ __launch_bounds__(256) void mcat_kernel(const float* __restrict__ wo,
                                                   const float* __restrict__ ctx,
                                                   __half* __restrict__ mcat)
{
    __shared__ float ctxs[64][66];   // [c][d], 8B-aligned rows
    __shared__ float wos[64][66];    // [o_local][d]
    int bh = blockIdx.x;
    int b = bh >> 3, h = bh & 7;
    const float* cb = ctx + (long)bh * 4096;
    int t = threadIdx.x;
    int og = (t >> 4) * 4, cg = (t & 15) * 4;

    for (int i = t; i < 4096; i += 256) ctxs[i >> 6][i & 63] = cb[i];

    for (int o0 = 0; o0 < HIDDEN; o0 += 64) {
        __syncthreads();
        for (int i = t; i < 4096; i += 256)
            wos[i >> 6][i & 63] = wo[(long)(o0 + (i >> 6)) * HIDDEN + h * 64 + (i & 63)];
        __syncthreads();

        unsigned long long acc2[4][4];
        #pragma unroll
        for (int i = 0; i < 4; i++)
            #pragma unroll
            for (int j = 0; j < 4; j++) acc2[i][j] = 0ull;

        #pragma unroll 8
        for (int d2 = 0; d2 < 64; d2 += 2) {
            unsigned long long av[4], bv[4];
            #pragma unroll
            for (int i = 0; i < 4; i++)
                av[i] = *(const unsigned long long*)&wos[og + i][d2];
            #pragma unroll
            for (int j = 0; j < 4; j++)
                bv[j] = *(const unsigned long long*)&ctxs[cg + j][d2];
            #pragma unroll
            for (int i = 0; i < 4; i++)
                #pragma unroll
                for (int j = 0; j < 4; j++)
                    acc2[i][j] = f32x2_fma(av[i], bv[j], acc2[i][j]);
        }
        // horizontal sum + fp16 store (c contiguous pairs)
        #pragma unroll
        for (int i = 0; i < 4; i++) {
            float r[4];
            #pragma unroll
            for (int j = 0; j < 4; j++) {
                float2 p = f32x2_unpack(acc2[i][j]);
                r[j] = p.x + p.y;
            }
            __half* dp = mcat + ((long)b * HIDDEN + o0 + og + i) * HIDDEN + h * 64 + cg;
            *(__half2*)(dp)     = __floats2half2_rn(r[0], r[1]);
            *(__half2*)(dp + 2) = __floats2half2_rn(r[2], r[3]);
        }
    }
}

// ================= launch =================
extern "C" void kernel_launch(void* const* d_in, const int* in_sizes, int n_in,
                              void* d_out, int out_size)
{
    const float* x     = (const float*)d_in[0];   // (16,512,64,64)
    const float* w_qkv = (const float*)d_in[1];   // (1536,512)
    const float* w_out = (const float*)d_in[2];   // (512,512)
    const float* b_out = (const float*)d_in[3];   // (512,)
    float* y = (float*)d_out;

    float *kk, *part, *ctx;
    float2* stats;
    __half *q16, *v16, *qt, *mcat, *xt, *wq;
    cudaGetSymbolAddress((void**)&kk,    g_k);
    cudaGetSymbolAddress((void**)&q16,   g_q16);
    cudaGetSymbolAddress((void**)&v16,   g_v16);
    cudaGetSymbolAddress((void**)&qt,    g_qt);
    cudaGetSymbolAddress((void**)&part,  g_ctx_part);
    cudaGetSymbolAddress((void**)&ctx,   g_ctx);
    cudaGetSymbolAddress((void**)&stats, g_stats);
    cudaGetSymbolAddress((void**)&mcat,  g_mcat);
    cudaGetSymbolAddress((void**)&xt,    g_xt);
    cudaGetSymbolAddress((void**)&wq,    g_wq);

    cudaFuncSetAttribute(gemm1_kernel,
                         cudaFuncAttributeMaxDynamicSharedMemorySize, GEMM_SMEM);
    cudaFuncSetAttribute(gemm2_kernel,
                         cudaFuncAttributeMaxDynamicSharedMemorySize, GEMM_SMEM);

    // 0. conversions
    conv_half_kernel<<<(OQKV * CDIM + 255) / 256, 256>>>(w_qkv, wq, OQKV * CDIM);
    trans_half_kernel<<<dim3(HW / 32, CDIM / 32, BATCH), 256>>>(x, xt, CDIM, HW);

    // 1. split qkv GEMM: q fp16, k f32, v fp16
    gemm1_kernel<<<dim3(HW / 128, OQKV / 128, BATCH), 128, GEMM_SMEM>>>(
        wq, xt, q16, kk, v16);

    // 2. q^T for GEMM2 B operand
    trans_q_kernel<<<dim3(HW / 64, HIDDEN / 64, BATCH), 256>>>(q16, qt);

    // 3. softmax row stats
    rowstat_kernel<<<8192, 256>>>(kk, stats);
    // 4. context = softmax(k) @ v^T
    ctx_kernel<<<dim3(SPLIT, 128), 256>>>(kk, v16, stats, part);
    ctx_reduce_kernel<<<2048, 256>>>(part, stats, ctx);
    // 5. Mcat = (W_out per-head) @ ctx^T   (tiny f32x2 GEMM)
    mcat_kernel<<<BATCH * HEADS, 256>>>(w_out, ctx, mcat);

    // 6. y = Mcat @ q + b_out
    gemm2_kernel<<<dim3(HW / 128, HIDDEN / 128, BATCH), 128, GEMM_SMEM>>>(
        mcat, qt, y, b_out);
}

// round 12
// speedup vs baseline: 4.2464x; 1.1880x over previous
#include <cuda_runtime.h>
#include <cuda_fp16.h>
#include <cstdint>

#define HEADS  8
#define DIMH   64
#define BATCH  16
#define CDIM   512
#define HW     4096
#define HIDDEN 512
#define SPLIT  8

// ---------------- scratch (no allocations allowed) ----------------
__device__ float  g_k[(size_t)BATCH * HIDDEN * HW];           // 134 MB (f32 k)
__device__ __half g_v16[(size_t)BATCH * HIDDEN * HW];         // 67 MB
__device__ float  g_ctx_part[(size_t)SPLIT * BATCH * HEADS * DIMH * DIMH];
__device__ float  g_ctx[(size_t)BATCH * HEADS * DIMH * DIMH];
__device__ float2 g_stats[(size_t)BATCH * HIDDEN];
__device__ __half g_mcat[(size_t)BATCH * HIDDEN * HIDDEN];    // 16 MB
__device__ __half g_mcomb[(size_t)BATCH * HIDDEN * CDIM];     // 16 MB
__device__ __half g_xt[(size_t)BATCH * HW * CDIM];            // 67 MB
__device__ __half g_wkv[(size_t)2 * HIDDEN * CDIM];           // k,v weight fp16
__device__ __half g_wqt[(size_t)CDIM * HIDDEN];               // q weight^T fp16

// ================= PTX helpers =================
__device__ __forceinline__ uint32_t smem_u32(const void* p) {
    uint32_t a;
    asm("{ .reg .u64 t; cvta.to.shared.u64 t, %1; cvt.u32.u64 %0, t; }"
        : "=r"(a) : "l"(p));
    return a;
}
__device__ __forceinline__ void cp_async16(uint32_t dst, const void* src) {
    asm volatile("cp.async.cg.shared.global [%0], [%1], 16;"
                 :: "r"(dst), "l"(src));
}
#define CP_COMMIT() asm volatile("cp.async.commit_group;")
#define CP_WAIT(n)  asm volatile("cp.async.wait_group %0;" :: "n"(n))

__device__ __forceinline__ void ldmx4(uint32_t* r, uint32_t addr) {
    asm volatile("ldmatrix.sync.aligned.m8n8.x4.shared.b16 {%0,%1,%2,%3}, [%4];"
                 : "=r"(r[0]), "=r"(r[1]), "=r"(r[2]), "=r"(r[3]) : "r"(addr));
}
__device__ __forceinline__ void mma16816(float* d, const uint32_t* a,
                                         uint32_t b0, uint32_t b1) {
    asm volatile(
        "mma.sync.aligned.m16n8k16.row.col.f32.f16.f16.f32 "
        "{%0,%1,%2,%3}, {%4,%5,%6,%7}, {%8,%9}, {%0,%1,%2,%3};"
        : "+f"(d[0]), "+f"(d[1]), "+f"(d[2]), "+f"(d[3])
        : "r"(a[0]), "r"(a[1]), "r"(a[2]), "r"(a[3]), "r"(b0), "r"(b1));
}

// packed f32x2
__device__ __forceinline__ unsigned long long f32x2_dup(float a) {
    unsigned long long r;
    asm("mov.b64 %0, {%1, %1};" : "=l"(r) : "f"(a));
    return r;
}
__device__ __forceinline__ unsigned long long f32x2_fma(unsigned long long a,
                                                        unsigned long long b,
                                                        unsigned long long c) {
    unsigned long long d;
    asm("fma.rn.f32x2 %0, %1, %2, %3;" : "=l"(d) : "l"(a), "l"(b), "l"(c));
    return d;
}
__device__ __forceinline__ float2 f32x2_unpack(unsigned long long v) {
    float2 f;
    asm("mov.b64 {%0, %1}, %2;" : "=f"(f.x), "=f"(f.y) : "l"(v));
    return f;
}

// ================= GEMM common config =================
#define ROWB 80
#define HALF_TILE (128 * ROWB)           // 10240 per 128x32 fp16 tile
#define NSTAGE 4
#define GEMM_SMEM (NSTAGE * 2 * HALF_TILE)   // 81920

// ======== GEMM1: [k;v] = wkv @ xt^T, split outputs (k f32, v fp16) ====
__global__ __launch_bounds__(128, 2) void gemm1_kernel(
    const __half* __restrict__ Ah, const __half* __restrict__ Bh_,
    float* __restrict__ ko, __half* __restrict__ vo)
{
    constexpr int STAGE_BYTES = 2 * HALF_TILE;
    constexpr int K = CDIM, N = HW;
    extern __shared__ char smem[];
    const uint32_t sb = smem_u32(smem);

    const int t = threadIdx.x;
    const int lane = t & 31, wid = t >> 5;
    const int m_off = (wid & 1) * 64, n_off = (wid >> 1) * 64;
    const int m0 = blockIdx.y * 128, n0 = blockIdx.x * 128;
    const long z = blockIdx.z;
    const __half* Bh = Bh_ + z * (long)N * K;

    const int lrow0 = t >> 2, lch = t & 3;
    const uint32_t aBase = sb + (uint32_t)((m_off + (lane & 15)) * ROWB + (lane >> 4) * 16);
    const uint32_t bBase = sb + HALF_TILE +
        (uint32_t)((n_off + (lane & 7) + ((lane >> 4) << 3)) * ROWB + ((lane >> 3) & 1) * 16);

    float acc[4][8][4];
    #pragma unroll
    for (int i = 0; i < 4; i++)
        #pragma unroll
        for (int j = 0; j < 8; j++)
            #pragma unroll
            for (int r = 0; r < 4; r++) acc[i][j][r] = 0.f;

    const int nst = K / 32;

    auto load_stage = [&](int s) {
        const int k0 = s * 32;
        const uint32_t bufb = sb + (uint32_t)((s % NSTAGE) * STAGE_BYTES);
        #pragma unroll
        for (int p = 0; p < 4; p++) {
            int row = lrow0 + p * 32;
            cp_async16(bufb + (uint32_t)(row * ROWB + lch * 16),
                       Ah + (long)(m0 + row) * K + k0 + lch * 8);
            cp_async16(bufb + HALF_TILE + (uint32_t)(row * ROWB + lch * 16),
                       Bh + (long)(n0 + row) * K + k0 + lch * 8);
        }
        CP_COMMIT();
    };

    #pragma unroll
    for (int s = 0; s < NSTAGE - 1; s++) load_stage(s);

    for (int s = 0; s < nst; s++) {
        if (s + NSTAGE - 1 < nst) { load_stage(s + NSTAGE - 1); CP_WAIT(NSTAGE - 2); }
        else                      { CP_WAIT(0); }
        __syncthreads();

        const uint32_t bufo = (uint32_t)((s % NSTAGE) * STAGE_BYTES);
        #pragma unroll
        for (int ks = 0; ks < 2; ks++) {
            uint32_t bh[16];
            #pragma unroll
            for (int nj = 0; nj < 4; nj++)
                ldmx4(&bh[nj * 4], bBase + bufo + (uint32_t)(nj * 16 * ROWB + ks * 32));
            #pragma unroll
            for (int mi = 0; mi < 4; mi++) {
                uint32_t ah[4];
                ldmx4(ah, aBase + bufo + (uint32_t)(mi * 16 * ROWB + ks * 32));
                #pragma unroll
                for (int j = 0; j < 8; j++) {
                    int bi = (j >> 1) * 4 + (j & 1) * 2;
                    mma16816(acc[mi][j], ah, bh[bi], bh[bi + 1]);
                }
            }
        }
        __syncthreads();
    }

    // ---- split epilogue: rows 0..511 -> k (f32), 512..1023 -> v (fp16) ----
    const int mrow = m0 + m_off + (lane >> 2);
    const int ncol = n0 + n_off + (lane & 3) * 2;
    #pragma unroll
    for (int mi = 0; mi < 4; mi++) {
        #pragma unroll
        for (int half = 0; half < 2; half++) {
            int r = mrow + mi * 16 + half * 8;
            int seg = r >> 9, lr = r & 511;
            long rowbase = ((long)z * HIDDEN + lr) * HW;
            #pragma unroll
            for (int j = 0; j < 8; j++) {
                int cc = ncol + j * 8;
                float a = acc[mi][j][half * 2 + 0];
                float b = acc[mi][j][half * 2 + 1];
                if (seg == 0) {
                    *(float2*)(ko + rowbase + cc) = make_float2(a, b);
                } else {
                    *(__half2*)(vo + rowbase + cc) = __floats2half2_rn(a, b);
                }
            }
        }
    }
}

// ======== generic fp16 HMMA GEMM: C[z] = A[z] @ B[z]^T (+bias) ========
template<typename OutT>
__global__ __launch_bounds__(128, 2) void gemm_g_kernel(
    const __half* __restrict__ A_, const __half* __restrict__ B_,
    OutT* __restrict__ C, const float* __restrict__ bias,
    int M, int N, int K, long sA, long sB, long sC)
{
    constexpr int STAGE_BYTES = 2 * HALF_TILE;
    extern __shared__ char smem[];
    const uint32_t sb = smem_u32(smem);

    const int t = threadIdx.x;
    const int lane = t & 31, wid = t >> 5;
    const int m_off = (wid & 1) * 64, n_off = (wid >> 1) * 64;
    const int m0 = blockIdx.y * 128, n0 = blockIdx.x * 128;
    const long z = blockIdx.z;
    const __half* Ah = A_ + z * sA;
    const __half* Bh = B_ + z * sB;

    const int lrow0 = t >> 2, lch = t & 3;
    const uint32_t aBase = sb + (uint32_t)((m_off + (lane & 15)) * ROWB + (lane >> 4) * 16);
    const uint32_t bBase = sb + HALF_TILE +
        (uint32_t)((n_off + (lane & 7) + ((lane >> 4) << 3)) * ROWB + ((lane >> 3) & 1) * 16);

    float acc[4][8][4];
    #pragma unroll
    for (int i = 0; i < 4; i++)
        #pragma unroll
        for (int j = 0; j < 8; j++)
            #pragma unroll
            for (int r = 0; r < 4; r++) acc[i][j][r] = 0.f;

    const int nst = K / 32;

    auto load_stage = [&](int s) {
        const int k0 = s * 32;
        const uint32_t bufb = sb + (uint32_t)((s % NSTAGE) * STAGE_BYTES);
        #pragma unroll
        for (int p = 0; p < 4; p++) {
            int row = lrow0 + p * 32;
            cp_async16(bufb + (uint32_t)(row * ROWB + lch * 16),
                       Ah + (long)(m0 + row) * K + k0 + lch * 8);
            cp_async16(bufb + HALF_TILE + (uint32_t)(row * ROWB + lch * 16),
                       Bh + (long)(n0 + row) * K + k0 + lch * 8);
        }
        CP_COMMIT();
    };

    #pragma unroll
    for (int s = 0; s < NSTAGE - 1; s++) load_stage(s);

    for (int s = 0; s < nst; s++) {
        if (s + NSTAGE - 1 < nst) { load_stage(s + NSTAGE - 1); CP_WAIT(NSTAGE - 2); }
        else                      { CP_WAIT(0); }
        __syncthreads();

        const uint32_t bufo = (uint32_t)((s % NSTAGE) * STAGE_BYTES);
        #pragma unroll
        for (int ks = 0; ks < 2; ks++) {
            uint32_t bh[16];
            #pragma unroll
            for (int nj = 0; nj < 4; nj++)
                ldmx4(&bh[nj * 4], bBase + bufo + (uint32_t)(nj * 16 * ROWB + ks * 32));
            #pragma unroll
            for (int mi = 0; mi < 4; mi++) {
                uint32_t ah[4];
                ldmx4(ah, aBase + bufo + (uint32_t)(mi * 16 * ROWB + ks * 32));
                #pragma unroll
                for (int j = 0; j < 8; j++) {
                    int bi = (j >> 1) * 4 + (j & 1) * 2;
                    mma16816(acc[mi][j], ah, bh[bi], bh[bi + 1]);
                }
            }
        }
        __syncthreads();
    }

    OutT* Cz = C + z * sC;
    const int mrow = m0 + m_off + (lane >> 2);
    const int ncol = n0 + n_off + (lane & 3) * 2;
    #pragma unroll
    for (int mi = 0; mi < 4; mi++) {
        int r0 = mrow + mi * 16;
        float bv0 = bias ? bias[r0] : 0.f;
        float bv1 = bias ? bias[r0 + 8] : 0.f;
        #pragma unroll
        for (int j = 0; j < 8; j++) {
            int cc = ncol + j * 8;
            if constexpr (sizeof(OutT) == 4) {
                *(float2*)(Cz + (long)r0 * N + cc) =
                    make_float2(acc[mi][j][0] + bv0, acc[mi][j][1] + bv0);
                *(float2*)(Cz + (long)(r0 + 8) * N + cc) =
                    make_float2(acc[mi][j][2] + bv1, acc[mi][j][3] + bv1);
            } else {
                *(__half2*)(Cz + (long)r0 * N + cc) =
                    __floats2half2_rn(acc[mi][j][0] + bv0, acc[mi][j][1] + bv0);
                *(__half2*)(Cz + (long)(r0 + 8) * N + cc) =
                    __floats2half2_rn(acc[mi][j][2] + bv1, acc[mi][j][3] + bv1);
            }
        }
    }
}

// ================= conversion kernels =================
__global__ __launch_bounds__(256) void conv_half_kernel(
    const float* __restrict__ w, __half* __restrict__ hi, int n)
{
    int i = blockIdx.x * 256 + threadIdx.x;
    if (i < n) hi[i] = __float2half_rn(w[i]);
}

// in: [z][R][Cc] f32 -> out: [z][Cc][R] fp16 (transpose)
__global__ __launch_bounds__(256) void trans_half_kernel(
    const float* __restrict__ in, __half* __restrict__ oh, int R, int Cc)
{
    __shared__ float tile[32][33];
    const int z = blockIdx.z;
    const int c0 = blockIdx.x * 32, r0 = blockIdx.y * 32;
    const int tx = threadIdx.x & 31, ty = threadIdx.x >> 5;
    const float* ip = in + (long)z * R * Cc;
    #pragma unroll
    for (int i = 0; i < 4; i++)
        tile[ty + 8 * i][tx] = ip[(long)(r0 + ty + 8 * i) * Cc + c0 + tx];
    __syncthreads();
    #pragma unroll
    for (int i = 0; i < 4; i++) {
        long o = ((long)z * Cc + c0 + ty + 8 * i) * R + r0 + tx;
        oh[o] = __float2half_rn(tile[tx][ty + 8 * i]);
    }
}

// ================= row stats for softmax(k) =================
__device__ __forceinline__ float warp_rmax(float v) {
    #pragma unroll
    for (int o = 16; o; o >>= 1) v = fmaxf(v, __shfl_xor_sync(0xffffffffu, v, o));
    return v;
}
__device__ __forceinline__ float warp_rsum(float v) {
    #pragma unroll
    for (int o = 16; o; o >>= 1) v += __shfl_xor_sync(0xffffffffu, v, o);
    return v;
}

__global__ __launch_bounds__(256) void rowstat_kernel(const float* __restrict__ kk,
                                                      float2* __restrict__ stats)
{
    int row = blockIdx.x;
    const float4* p = (const float4*)(kk + (long)row * HW);
    int t = threadIdx.x;

    float4 v[4];
    float m = -1e30f;
    #pragma unroll
    for (int i = 0; i < 4; i++) {
        v[i] = p[t + i * 256];
        m = fmaxf(m, fmaxf(fmaxf(v[i].x, v[i].y), fmaxf(v[i].z, v[i].w)));
    }
    __shared__ float red[8];
    m = warp_rmax(m);
    if ((t & 31) == 0) red[t >> 5] = m;
    __syncthreads();
    float bm = red[0];
    #pragma unroll
    for (int i = 1; i < 8; i++) bm = fmaxf(bm, red[i]);

    float s = 0.f;
    #pragma unroll
    for (int i = 0; i < 4; i++) {
        s += __expf(v[i].x - bm) + __expf(v[i].y - bm) +
             __expf(v[i].z - bm) + __expf(v[i].w - bm);
    }
    s = warp_rsum(s);
    __syncthreads();
    if ((t & 31) == 0) red[t >> 5] = s;
    __syncthreads();
    if (t == 0) {
        float bs = 0.f;
        #pragma unroll
        for (int i = 0; i < 8; i++) bs += red[i];
        stats[row] = make_float2(bm, 1.0f / bs);
    }
}

// ====== context = softmax(k) @ v^T (exp fused, split-K, f32x2 core) ======
__global__ __launch_bounds__(256) void ctx_kernel(const float* __restrict__ kk,
                                                  const __half* __restrict__ vv,
                                                  const float2* __restrict__ stats,
                                                  float* __restrict__ part)
{
    __shared__ float Ks[64][65];
    __shared__ float Vs[64][66];
    __shared__ float sm_m[64];
    int bh = blockIdx.y;
    int b = bh >> 3, hh = bh & 7;
    int split = blockIdx.x;
    const float* kb = kk + ((long)b * HIDDEN + hh * DIMH) * HW;
    const __half* vb = vv + ((long)b * HIDDEN + hh * DIMH) * HW;
    int t = threadIdx.x, tx = t & 15, ty = t >> 4;

    if (t < 64) sm_m[t] = stats[b * HIDDEN + hh * DIMH + t].x;
    __syncthreads();

    unsigned long long acc2[4][2];
    #pragma unroll
    for (int i = 0; i < 4; i++) { acc2[i][0] = 0ull; acc2[i][1] = 0ull; }

    for (int chunk = 0; chunk < 8; chunk++) {
        int n0 = split * 512 + chunk * 64;
        #pragma unroll
        for (int i = 0; i < 4; i++) {
            int idx = t + i * 256;
            int row = idx >> 4;
            int col = (idx & 15) << 2;
            float mrow = sm_m[row];
            float4 kv = *(const float4*)(kb + (long)row * HW + n0 + col);
            Ks[row][col] = __expf(kv.x - mrow); Ks[row][col + 1] = __expf(kv.y - mrow);
            Ks[row][col + 2] = __expf(kv.z - mrow); Ks[row][col + 3] = __expf(kv.w - mrow);
            uint2 raw = *(const uint2*)(vb + (long)row * HW + n0 + col);
            float2 f0 = __half22float2(*(__half2*)&raw.x);
            float2 f1 = __half22float2(*(__half2*)&raw.y);
            Vs[col + 0][row] = f0.x; Vs[col + 1][row] = f0.y;
            Vs[col + 2][row] = f1.x; Vs[col + 3][row] = f1.y;
        }
        __syncthreads();
        #pragma unroll 4
        for (int nn = 0; nn < 64; nn++) {
            const unsigned long long* bp =
                (const unsigned long long*)&Vs[nn][tx * 4];
            unsigned long long b0 = bp[0], b1 = bp[1];
            #pragma unroll
            for (int i = 0; i < 4; i++) {
                unsigned long long ap = f32x2_dup(Ks[ty * 4 + i][nn]);
                acc2[i][0] = f32x2_fma(ap, b0, acc2[i][0]);
                acc2[i][1] = f32x2_fma(ap, b1, acc2[i][1]);
            }
        }
        __syncthreads();
    }
    float* dst = part + ((long)split * 128 + bh) * 4096;
    #pragma unroll
    for (int i = 0; i < 4; i++) {
        float2 p0 = f32x2_unpack(acc2[i][0]);
        float2 p1 = f32x2_unpack(acc2[i][1]);
        float* r = dst + (ty * 4 + i) * 64 + tx * 4;
        r[0] = p0.x; r[1] = p0.y; r[2] = p1.x; r[3] = p1.y;
    }
}

__global__ __launch_bounds__(256) void ctx_reduce_kernel(const float* __restrict__ part,
                                                         const float2* __restrict__ stats,
                                                         float* __restrict__ ctx)
{
    long i = (long)blockIdx.x * 256 + threadIdx.x;
    float s = 0.f;
    #pragma unroll
    for (int sp = 0; sp < SPLIT; sp++) s += part[(long)sp * 524288 + i];
    int bh = (int)(i >> 12);
    int c  = (int)((i >> 6) & 63);
    float inv = stats[(bh >> 3) * HIDDEN + (bh & 7) * DIMH + c].y;
    ctx[i] = s * inv;
}

// ====== Mcat[b][o][h*64+c] = sum_d w_out[o][h*64+d] * ctx[b][h][c][d] ======
__global__ __launch_bounds__(256) void mcat_kernel(const float* __restrict__ wo,
                                                   const float* __restrict__ ctx,
                                                   __half* __restrict__ mcat)
{
    __shared__ float ctxs[64][66];
    __shared__ float wos[64][66];
    int bh = blockIdx.x;
    int b = bh >> 3, h = bh & 7;
    const float* cb = ctx + (long)bh * 4096;
    int t = threadIdx.x;
    int og = (t >> 4) * 4, cg = (t & 15) * 4;

    for (int i = t; i < 4096; i += 256) ctxs[i >> 6][i & 63] = cb[i];

    for (int o0 = 0; o0 < HIDDEN; o0 += 64) {
        __syncthreads();
        for (int i = t; i < 4096; i += 256)
            wos[i >> 6][i & 63] = wo[(long)(o0 + (i >> 6)) * HIDDEN + h * 64 + (i & 63)];
        __syncthreads();

        unsigned long long acc2[4][4];
        #pragma unroll
        for (int i = 0; i < 4; i++)
            #pragma unroll
            for (int j = 0; j < 4; j++) acc2[i][j] = 0ull;

        #pragma unroll 8
        for (int d2 = 0; d2 < 64; d2 += 2) {
            unsigned long long av[4], bv[4];
            #pragma unroll
            for (int i = 0; i < 4; i++)
                av[i] = *(const unsigned long long*)&wos[og + i][d2];
            #pragma unroll
            for (int j = 0; j < 4; j++)
                bv[j] = *(const unsigned long long*)&ctxs[cg + j][d2];
            #pragma unroll
            for (int i = 0; i < 4; i++)
                #pragma unroll
                for (int j = 0; j < 4; j++)
                    acc2[i][j] = f32x2_fma(av[i], bv[j], acc2[i][j]);
        }
        #pragma unroll
        for (int i = 0; i < 4; i++) {
            float r[4];
            #pragma unroll
            for (int j = 0; j < 4; j++) {
                float2 p = f32x2_unpack(acc2[i][j]);
                r[j] = p.x + p.y;
            }
            __half* dp = mcat + ((long)b * HIDDEN + o0 + og + i) * HIDDEN + h * 64 + cg;
            *(__half2*)(dp)     = __floats2half2_rn(r[0], r[1]);
            *(__half2*)(dp + 2) = __floats2half2_rn(r[2], r[3]);
        }
    }
}

// ================= launch =================
extern "C" void kernel_launch(void* const* d_in, const int* in_sizes, int n_in,
                              void* d_out, int out_size)
{
    const float* x     = (const float*)d_in[0];   // (16,512,64,64)
    const float* w_qkv = (const float*)d_in[1];   // (1536,512): [q;k;v]
    const float* w_out = (const float*)d_in[2];   // (512,512)
    const float* b_out = (const float*)d_in[3];   // (512,)
    float* y = (float*)d_out;

    float *kk, *part, *ctx;
    float2* stats;
    __half *v16, *mcat, *mcomb, *xt, *wkv, *wqt;
    cudaGetSymbolAddress((void**)&kk,    g_k);
    cudaGetSymbolAddress((void**)&v16,   g_v16);
    cudaGetSymbolAddress((void**)&part,  g_ctx_part);
    cudaGetSymbolAddress((void**)&ctx,   g_ctx);
    cudaGetSymbolAddress((void**)&stats, g_stats);
    cudaGetSymbolAddress((void**)&mcat,  g_mcat);
    cudaGetSymbolAddress((void**)&mcomb, g_mcomb);
    cudaGetSymbolAddress((void**)&xt,    g_xt);
    cudaGetSymbolAddress((void**)&wkv,   g_wkv);
    cudaGetSymbolAddress((void**)&wqt,   g_wqt);

    cudaFuncSetAttribute(gemm1_kernel,
                         cudaFuncAttributeMaxDynamicSharedMemorySize, GEMM_SMEM);
    cudaFuncSetAttribute(gemm_g_kernel<__half>,
                         cudaFuncAttributeMaxDynamicSharedMemorySize, GEMM_SMEM);
    cudaFuncSetAttribute(gemm_g_kernel<float>,
                         cudaFuncAttributeMaxDynamicSharedMemorySize, GEMM_SMEM);

    // 0. conversions: k,v weights fp16; q weight transposed fp16; x transposed fp16
    conv_half_kernel<<<(2 * HIDDEN * CDIM + 255) / 256, 256>>>(
        w_qkv + (size_t)HIDDEN * CDIM, wkv, 2 * HIDDEN * CDIM);
    trans_half_kernel<<<dim3(CDIM / 32, HIDDEN / 32, 1), 256>>>(w_qkv, wqt, HIDDEN, CDIM);
    trans_half_kernel<<<dim3(HW / 32, CDIM / 32, BATCH), 256>>>(x, xt, CDIM, HW);

    // 1. [k;v] GEMM (M=1024): k f32, v fp16
    gemm1_kernel<<<dim3(HW / 128, 8, BATCH), 128, GEMM_SMEM>>>(wkv, xt, kk, v16);

    // 2. softmax row stats
    rowstat_kernel<<<8192, 256>>>(kk, stats);
    // 3. context = softmax(k) @ v^T
    ctx_kernel<<<dim3(SPLIT, 128), 256>>>(kk, v16, stats, part);
    ctx_reduce_kernel<<<2048, 256>>>(part, stats, ctx);
    // 4. Mcat = (W_out per-head) @ ctx^T
    mcat_kernel<<<BATCH * HEADS, 256>>>(w_out, ctx, mcat);

    // 5. Mcomb[b] = Mcat[b] @ Wq^T   (batched 512x512x512 fp16 HMMA)
    gemm_g_kernel<__half><<<dim3(CDIM / 128, HIDDEN / 128, BATCH), 128, GEMM_SMEM>>>(
        mcat, wqt, mcomb, nullptr,
        HIDDEN, CDIM, HIDDEN,
        (long)HIDDEN * HIDDEN, 0L, (long)HIDDEN * CDIM);

    // 6. y = Mcomb @ x + b_out
    gemm_g_kernel<float><<<dim3(HW / 128, HIDDEN / 128, BATCH), 128, GEMM_SMEM>>>(
        mcomb, xt, y, b_out,
        HIDDEN, HW, CDIM,
        (long)HIDDEN * CDIM, (long)HW * CDIM, (long)HIDDEN * HW);
}

// round 13
// speedup vs baseline: 4.3940x; 1.0347x over previous
#include <cuda_runtime.h>
#include <cuda_fp16.h>
#include <cstdint>

#define HEADS  8
#define DIMH   64
#define BATCH  16
#define CDIM   512
#define HW     4096
#define HIDDEN 512
#define SPLIT  8

// ---------------- scratch (no allocations allowed) ----------------
__device__ __half g_expk[(size_t)BATCH * HIDDEN * HW];        // 67 MB  exp(k) fp16
__device__ __half g_v16[(size_t)BATCH * HIDDEN * HW];         // 67 MB
__device__ float  g_ctx_part[(size_t)SPLIT * BATCH * HEADS * DIMH * DIMH];
__device__ float  g_sums[(size_t)SPLIT * BATCH * HEADS * DIMH]; // split-partial row sums
__device__ __half g_mcat[(size_t)BATCH * HIDDEN * HIDDEN];    // 16 MB
__device__ __half g_mcomb[(size_t)BATCH * HIDDEN * CDIM];     // 16 MB
__device__ __half g_xt[(size_t)BATCH * HW * CDIM];            // 67 MB
__device__ __half g_wkv[(size_t)2 * HIDDEN * CDIM];           // k,v weight fp16
__device__ __half g_wqt[(size_t)CDIM * HIDDEN];               // q weight^T fp16

// ================= PTX helpers =================
__device__ __forceinline__ uint32_t smem_u32(const void* p) {
    uint32_t a;
    asm("{ .reg .u64 t; cvta.to.shared.u64 t, %1; cvt.u32.u64 %0, t; }"
        : "=r"(a) : "l"(p));
    return a;
}
__device__ __forceinline__ void cp_async16(uint32_t dst, const void* src) {
    asm volatile("cp.async.cg.shared.global [%0], [%1], 16;"
                 :: "r"(dst), "l"(src));
}
#define CP_COMMIT() asm volatile("cp.async.commit_group;")
#define CP_WAIT(n)  asm volatile("cp.async.wait_group %0;" :: "n"(n))

__device__ __forceinline__ void ldmx4(uint32_t* r, uint32_t addr) {
    asm volatile("ldmatrix.sync.aligned.m8n8.x4.shared.b16 {%0,%1,%2,%3}, [%4];"
                 : "=r"(r[0]), "=r"(r[1]), "=r"(r[2]), "=r"(r[3]) : "r"(addr));
}
__device__ __forceinline__ void mma16816(float* d, const uint32_t* a,
                                         uint32_t b0, uint32_t b1) {
    asm volatile(
        "mma.sync.aligned.m16n8k16.row.col.f32.f16.f16.f32 "
        "{%0,%1,%2,%3}, {%4,%5,%6,%7}, {%8,%9}, {%0,%1,%2,%3};"
        : "+f"(d[0]), "+f"(d[1]), "+f"(d[2]), "+f"(d[3])
        : "r"(a[0]), "r"(a[1]), "r"(a[2]), "r"(a[3]), "r"(b0), "r"(b1));
}

// packed f32x2
__device__ __forceinline__ unsigned long long f32x2_dup(float a) {
    unsigned long long r;
    asm("mov.b64 %0, {%1, %1};" : "=l"(r) : "f"(a));
    return r;
}
__device__ __forceinline__ unsigned long long f32x2_fma(unsigned long long a,
                                                        unsigned long long b,
                                                        unsigned long long c) {
    unsigned long long d;
    asm("fma.rn.f32x2 %0, %1, %2, %3;" : "=l"(d) : "l"(a), "l"(b), "l"(c));
    return d;
}
__device__ __forceinline__ float2 f32x2_unpack(unsigned long long v) {
    float2 f;
    asm("mov.b64 {%0, %1}, %2;" : "=f"(f.x), "=f"(f.y) : "l"(v));
    return f;
}

// ================= GEMM common config =================
#define ROWB 80
#define HALF_TILE (128 * ROWB)           // 10240 per 128x32 fp16 tile
#define NSTAGE 4
#define GEMM_SMEM (NSTAGE * 2 * HALF_TILE)   // 81920

// ======== GEMM1: [k;v] = wkv @ xt^T; epilogue: exp(k)->fp16, v->fp16 ====
__global__ __launch_bounds__(128, 2) void gemm1_kernel(
    const __half* __restrict__ Ah, const __half* __restrict__ Bh_,
    __half* __restrict__ eko, __half* __restrict__ vo)
{
    constexpr int STAGE_BYTES = 2 * HALF_TILE;
    constexpr int K = CDIM, N = HW;
    extern __shared__ char smem[];
    const uint32_t sb = smem_u32(smem);

    const int t = threadIdx.x;
    const int lane = t & 31, wid = t >> 5;
    const int m_off = (wid & 1) * 64, n_off = (wid >> 1) * 64;
    const int m0 = blockIdx.y * 128, n0 = blockIdx.x * 128;
    const long z = blockIdx.z;
    const __half* Bh = Bh_ + z * (long)N * K;

    const int lrow0 = t >> 2, lch = t & 3;
    const uint32_t aBase = sb + (uint32_t)((m_off + (lane & 15)) * ROWB + (lane >> 4) * 16);
    const uint32_t bBase = sb + HALF_TILE +
        (uint32_t)((n_off + (lane & 7) + ((lane >> 4) << 3)) * ROWB + ((lane >> 3) & 1) * 16);

    float acc[4][8][4];
    #pragma unroll
    for (int i = 0; i < 4; i++)
        #pragma unroll
        for (int j = 0; j < 8; j++)
            #pragma unroll
            for (int r = 0; r < 4; r++) acc[i][j][r] = 0.f;

    const int nst = K / 32;

    auto load_stage = [&](int s) {
        const int k0 = s * 32;
        const uint32_t bufb = sb + (uint32_t)((s % NSTAGE) * STAGE_BYTES);
        #pragma unroll
        for (int p = 0; p < 4; p++) {
            int row = lrow0 + p * 32;
            cp_async16(bufb + (uint32_t)(row * ROWB + lch * 16),
                       Ah + (long)(m0 + row) * K + k0 + lch * 8);
            cp_async16(bufb + HALF_TILE + (uint32_t)(row * ROWB + lch * 16),
                       Bh + (long)(n0 + row) * K + k0 + lch * 8);
        }
        CP_COMMIT();
    };

    #pragma unroll
    for (int s = 0; s < NSTAGE - 1; s++) load_stage(s);

    for (int s = 0; s < nst; s++) {
        if (s + NSTAGE - 1 < nst) { load_stage(s + NSTAGE - 1); CP_WAIT(NSTAGE - 2); }
        else                      { CP_WAIT(0); }
        __syncthreads();

        const uint32_t bufo = (uint32_t)((s % NSTAGE) * STAGE_BYTES);
        #pragma unroll
        for (int ks = 0; ks < 2; ks++) {
            uint32_t bh[16];
            #pragma unroll
            for (int nj = 0; nj < 4; nj++)
                ldmx4(&bh[nj * 4], bBase + bufo + (uint32_t)(nj * 16 * ROWB + ks * 32));
            #pragma unroll
            for (int mi = 0; mi < 4; mi++) {
                uint32_t ah[4];
                ldmx4(ah, aBase + bufo + (uint32_t)(mi * 16 * ROWB + ks * 32));
                #pragma unroll
                for (int j = 0; j < 8; j++) {
                    int bi = (j >> 1) * 4 + (j & 1) * 2;
                    mma16816(acc[mi][j], ah, bh[bi], bh[bi + 1]);
                }
            }
        }
        __syncthreads();
    }

    // ---- epilogue: rows 0..511 -> exp(k) fp16, 512..1023 -> v fp16 ----
    const int mrow = m0 + m_off + (lane >> 2);
    const int ncol = n0 + n_off + (lane & 3) * 2;
    #pragma unroll
    for (int mi = 0; mi < 4; mi++) {
        #pragma unroll
        for (int half = 0; half < 2; half++) {
            int r = mrow + mi * 16 + half * 8;
            int seg = r >> 9, lr = r & 511;
            long rowbase = ((long)z * HIDDEN + lr) * HW;
            #pragma unroll
            for (int j = 0; j < 8; j++) {
                int cc = ncol + j * 8;
                float a = acc[mi][j][half * 2 + 0];
                float b = acc[mi][j][half * 2 + 1];
                if (seg == 0) {
                    *(__half2*)(eko + rowbase + cc) =
                        __floats2half2_rn(__expf(a), __expf(b));
                } else {
                    *(__half2*)(vo + rowbase + cc) = __floats2half2_rn(a, b);
                }
            }
        }
    }
}

// ======== generic fp16 HMMA GEMM: C[z] = A[z] @ B[z]^T (+bias) ========
template<typename OutT>
__global__ __launch_bounds__(128, 2) void gemm_g_kernel(
    const __half* __restrict__ A_, const __half* __restrict__ B_,
    OutT* __restrict__ C, const float* __restrict__ bias,
    int M, int N, int K, long sA, long sB, long sC)
{
    constexpr int STAGE_BYTES = 2 * HALF_TILE;
    extern __shared__ char smem[];
    const uint32_t sb = smem_u32(smem);

    const int t = threadIdx.x;
    const int lane = t & 31, wid = t >> 5;
    const int m_off = (wid & 1) * 64, n_off = (wid >> 1) * 64;
    const int m0 = blockIdx.y * 128, n0 = blockIdx.x * 128;
    const long z = blockIdx.z;
    const __half* Ah = A_ + z * sA;
    const __half* Bh = B_ + z * sB;

    const int lrow0 = t >> 2, lch = t & 3;
    const uint32_t aBase = sb + (uint32_t)((m_off + (lane & 15)) * ROWB + (lane >> 4) * 16);
    const uint32_t bBase = sb + HALF_TILE +
        (uint32_t)((n_off + (lane & 7) + ((lane >> 4) << 3)) * ROWB + ((lane >> 3) & 1) * 16);

    float acc[4][8][4];
    #pragma unroll
    for (int i = 0; i < 4; i++)
        #pragma unroll
        for (int j = 0; j < 8; j++)
            #pragma unroll
            for (int r = 0; r < 4; r++) acc[i][j][r] = 0.f;

    const int nst = K / 32;

    auto load_stage = [&](int s) {
        const int k0 = s * 32;
        const uint32_t bufb = sb + (uint32_t)((s % NSTAGE) * STAGE_BYTES);
        #pragma unroll
        for (int p = 0; p < 4; p++) {
            int row = lrow0 + p * 32;
            cp_async16(bufb + (uint32_t)(row * ROWB + lch * 16),
                       Ah + (long)(m0 + row) * K + k0 + lch * 8);
            cp_async16(bufb + HALF_TILE + (uint32_t)(row * ROWB + lch * 16),
                       Bh + (long)(n0 + row) * K + k0 + lch * 8);
        }
        CP_COMMIT();
    };

    #pragma unroll
    for (int s = 0; s < NSTAGE - 1; s++) load_stage(s);

    for (int s = 0; s < nst; s++) {
        if (s + NSTAGE - 1 < nst) { load_stage(s + NSTAGE - 1); CP_WAIT(NSTAGE - 2); }
        else                      { CP_WAIT(0); }
        __syncthreads();

        const uint32_t bufo = (uint32_t)((s % NSTAGE) * STAGE_BYTES);
        #pragma unroll
        for (int ks = 0; ks < 2; ks++) {
            uint32_t bh[16];
            #pragma unroll
            for (int nj = 0; nj < 4; nj++)
                ldmx4(&bh[nj * 4], bBase + bufo + (uint32_t)(nj * 16 * ROWB + ks * 32));
            #pragma unroll
            for (int mi = 0; mi < 4; mi++) {
                uint32_t ah[4];
                ldmx4(ah, aBase + bufo + (uint32_t)(mi * 16 * ROWB + ks * 32));
                #pragma unroll
                for (int j = 0; j < 8; j++) {
                    int bi = (j >> 1) * 4 + (j & 1) * 2;
                    mma16816(acc[mi][j], ah, bh[bi], bh[bi + 1]);
                }
            }
        }
        __syncthreads();
    }

    OutT* Cz = C + z * sC;
    const int mrow = m0 + m_off + (lane >> 2);
    const int ncol = n0 + n_off + (lane & 3) * 2;
    #pragma unroll
    for (int mi = 0; mi < 4; mi++) {
        int r0 = mrow + mi * 16;
        float bv0 = bias ? bias[r0] : 0.f;
        float bv1 = bias ? bias[r0 + 8] : 0.f;
        #pragma unroll
        for (int j = 0; j < 8; j++) {
            int cc = ncol + j * 8;
            if constexpr (sizeof(OutT) == 4) {
                *(float2*)(Cz + (long)r0 * N + cc) =
                    make_float2(acc[mi][j][0] + bv0, acc[mi][j][1] + bv0);
                *(float2*)(Cz + (long)(r0 + 8) * N + cc) =
                    make_float2(acc[mi][j][2] + bv1, acc[mi][j][3] + bv1);
            } else {
                *(__half2*)(Cz + (long)r0 * N + cc) =
                    __floats2half2_rn(acc[mi][j][0] + bv0, acc[mi][j][1] + bv0);
                *(__half2*)(Cz + (long)(r0 + 8) * N + cc) =
                    __floats2half2_rn(acc[mi][j][2] + bv1, acc[mi][j][3] + bv1);
            }
        }
    }
}

// ================= conversion kernels =================
__global__ __launch_bounds__(256) void conv_half_kernel(
    const float* __restrict__ w, __half* __restrict__ hi, int n)
{
    int i = blockIdx.x * 256 + threadIdx.x;
    if (i < n) hi[i] = __float2half_rn(w[i]);
}

// in: [z][R][Cc] f32 -> out: [z][Cc][R] fp16 (transpose)
__global__ __launch_bounds__(256) void trans_half_kernel(
    const float* __restrict__ in, __half* __restrict__ oh, int R, int Cc)
{
    __shared__ float tile[32][33];
    const int z = blockIdx.z;
    const int c0 = blockIdx.x * 32, r0 = blockIdx.y * 32;
    const int tx = threadIdx.x & 31, ty = threadIdx.x >> 5;
    const float* ip = in + (long)z * R * Cc;
    #pragma unroll
    for (int i = 0; i < 4; i++)
        tile[ty + 8 * i][tx] = ip[(long)(r0 + ty + 8 * i) * Cc + c0 + tx];
    __syncthreads();
    #pragma unroll
    for (int i = 0; i < 4; i++) {
        long o = ((long)z * Cc + c0 + ty + 8 * i) * R + r0 + tx;
        oh[o] = __float2half_rn(tile[tx][ty + 8 * i]);
    }
}

// ====== context partials: part = expk @ v^T per split; also row sums ======
__global__ __launch_bounds__(256) void ctx_kernel(const __half* __restrict__ ek,
                                                  const __half* __restrict__ vv,
                                                  float* __restrict__ part,
                                                  float* __restrict__ sums)
{
    __shared__ float Ks[64][65];   // [c][n]
    __shared__ float Vs[64][66];   // [n][d]
    int bh = blockIdx.y;
    int b = bh >> 3, hh = bh & 7;
    int split = blockIdx.x;
    const __half* kb = ek + ((long)b * HIDDEN + hh * DIMH) * HW;
    const __half* vb = vv + ((long)b * HIDDEN + hh * DIMH) * HW;
    int t = threadIdx.x, tx = t & 15, ty = t >> 4;

    unsigned long long acc2[4][2];
    #pragma unroll
    for (int i = 0; i < 4; i++) { acc2[i][0] = 0ull; acc2[i][1] = 0ull; }
    float psum[4] = {0.f, 0.f, 0.f, 0.f};

    for (int chunk = 0; chunk < 8; chunk++) {
        int n0 = split * 512 + chunk * 64;
        #pragma unroll
        for (int i = 0; i < 4; i++) {
            int row = 16 * i + ty;         // c (for K) / source row (for V)
            int col = tx << 2;             // n within tile
            uint2 kraw = *(const uint2*)(kb + (long)row * HW + n0 + col);
            float2 k0 = __half22float2(*(__half2*)&kraw.x);
            float2 k1 = __half22float2(*(__half2*)&kraw.y);
            Ks[row][col] = k0.x; Ks[row][col + 1] = k0.y;
            Ks[row][col + 2] = k1.x; Ks[row][col + 3] = k1.y;
            psum[i] += (k0.x + k0.y) + (k1.x + k1.y);
            uint2 raw = *(const uint2*)(vb + (long)row * HW + n0 + col);
            float2 f0 = __half22float2(*(__half2*)&raw.x);
            float2 f1 = __half22float2(*(__half2*)&raw.y);
            Vs[col + 0][row] = f0.x; Vs[col + 1][row] = f0.y;
            Vs[col + 2][row] = f1.x; Vs[col + 3][row] = f1.y;
        }
        __syncthreads();
        #pragma unroll 4
        for (int nn = 0; nn < 64; nn++) {
            const unsigned long long* bp =
                (const unsigned long long*)&Vs[nn][tx * 4];
            unsigned long long b0 = bp[0], b1 = bp[1];
            #pragma unroll
            for (int i = 0; i < 4; i++) {
                unsigned long long ap = f32x2_dup(Ks[ty * 4 + i][nn]);
                acc2[i][0] = f32x2_fma(ap, b0, acc2[i][0]);
                acc2[i][1] = f32x2_fma(ap, b1, acc2[i][1]);
            }
        }
        __syncthreads();
    }
    // reduce psum across the 16 lanes sharing each row (tx bits within warp)
    #pragma unroll
    for (int i = 0; i < 4; i++) {
        #pragma unroll
        for (int o = 8; o; o >>= 1)
            psum[i] += __shfl_xor_sync(0xffffffffu, psum[i], o);
    }
    if (tx == 0) {
        #pragma unroll
        for (int i = 0; i < 4; i++)
            sums[((long)split * 128 + bh) * 64 + 16 * i + ty] = psum[i];
    }
    float* dst = part + ((long)split * 128 + bh) * 4096;
    #pragma unroll
    for (int i = 0; i < 4; i++) {
        float2 p0 = f32x2_unpack(acc2[i][0]);
        float2 p1 = f32x2_unpack(acc2[i][1]);
        float* r = dst + (ty * 4 + i) * 64 + tx * 4;
        r[0] = p0.x; r[1] = p0.y; r[2] = p1.x; r[3] = p1.y;
    }
}

// == Mcat[b][o][h*64+c] = sum_d w_out[o][h*64+d] * ctx_norm[b][h][c][d] ==
// (split reduction + 1/S_c normalization fused into the ctx load)
__global__ __launch_bounds__(256) void mcat_kernel(const float* __restrict__ wo,
                                                   const float* __restrict__ part,
                                                   const float* __restrict__ sums,
                                                   __half* __restrict__ mcat)
{
    __shared__ float ctxs[64][66];
    __shared__ float wos[64][66];
    __shared__ float invs[64];
    int bh = blockIdx.x;
    int b = bh >> 3, h = bh & 7;
    int t = threadIdx.x;
    int og = (t >> 4) * 4, cg = (t & 15) * 4;

    if (t < 64) {
        float s = 0.f;
        #pragma unroll
        for (int sp = 0; sp < SPLIT; sp++)
            s += sums[((long)sp * 128 + bh) * 64 + t];
        invs[t] = 1.0f / s;
    }
    __syncthreads();
    for (int i = t; i < 4096; i += 256) {
        float s = 0.f;
        #pragma unroll
        for (int sp = 0; sp < SPLIT; sp++)
            s += part[((long)sp * 128 + bh) * 4096 + i];
        ctxs[i >> 6][i & 63] = s * invs[i >> 6];
    }

    for (int o0 = 0; o0 < HIDDEN; o0 += 64) {
        __syncthreads();
        for (int i = t; i < 4096; i += 256)
            wos[i >> 6][i & 63] = wo[(long)(o0 + (i >> 6)) * HIDDEN + h * 64 + (i & 63)];
        __syncthreads();

        unsigned long long acc2[4][4];
        #pragma unroll
        for (int i = 0; i < 4; i++)
            #pragma unroll
            for (int j = 0; j < 4; j++) acc2[i][j] = 0ull;

        #pragma unroll 8
        for (int d2 = 0; d2 < 64; d2 += 2) {
            unsigned long long av[4], bv[4];
            #pragma unroll
            for (int i = 0; i < 4; i++)
                av[i] = *(const unsigned long long*)&wos[og + i][d2];
            #pragma unroll
            for (int j = 0; j < 4; j++)
                bv[j] = *(const unsigned long long*)&ctxs[cg + j][d2];
            #pragma unroll
            for (int i = 0; i < 4; i++)
                #pragma unroll
                for (int j = 0; j < 4; j++)
                    acc2[i][j] = f32x2_fma(av[i], bv[j], acc2[i][j]);
        }
        #pragma unroll
        for (int i = 0; i < 4; i++) {
            float r[4];
            #pragma unroll
            for (int j = 0; j < 4; j++) {
                float2 p = f32x2_unpack(acc2[i][j]);
                r[j] = p.x + p.y;
            }
            __half* dp = mcat + ((long)b * HIDDEN + o0 + og + i) * HIDDEN + h * 64 + cg;
            *(__half2*)(dp)     = __floats2half2_rn(r[0], r[1]);
            *(__half2*)(dp + 2) = __floats2half2_rn(r[2], r[3]);
        }
    }
}

// ================= launch =================
extern "C" void kernel_launch(void* const* d_in, const int* in_sizes, int n_in,
                              void* d_out, int out_size)
{
    const float* x     = (const float*)d_in[0];   // (16,512,64,64)
    const float* w_qkv = (const float*)d_in[1];   // (1536,512): [q;k;v]
    const float* w_out = (const float*)d_in[2];   // (512,512)
    const float* b_out = (const float*)d_in[3];   // (512,)
    float* y = (float*)d_out;

    float *part, *sums;
    __half *expk, *v16, *mcat, *mcomb, *xt, *wkv, *wqt;
    cudaGetSymbolAddress((void**)&expk,  g_expk);
    cudaGetSymbolAddress((void**)&v16,   g_v16);
    cudaGetSymbolAddress((void**)&part,  g_ctx_part);
    cudaGetSymbolAddress((void**)&sums,  g_sums);
    cudaGetSymbolAddress((void**)&mcat,  g_mcat);
    cudaGetSymbolAddress((void**)&mcomb, g_mcomb);
    cudaGetSymbolAddress((void**)&xt,    g_xt);
    cudaGetSymbolAddress((void**)&wkv,   g_wkv);
    cudaGetSymbolAddress((void**)&wqt,   g_wqt);

    cudaFuncSetAttribute(gemm1_kernel,
                         cudaFuncAttributeMaxDynamicSharedMemorySize, GEMM_SMEM);
    cudaFuncSetAttribute(gemm_g_kernel<__half>,
                         cudaFuncAttributeMaxDynamicSharedMemorySize, GEMM_SMEM);
    cudaFuncSetAttribute(gemm_g_kernel<float>,
                         cudaFuncAttributeMaxDynamicSharedMemorySize, GEMM_SMEM);

    // 0. conversions
    conv_half_kernel<<<(2 * HIDDEN * CDIM + 255) / 256, 256>>>(
        w_qkv + (size_t)HIDDEN * CDIM, wkv, 2 * HIDDEN * CDIM);
    trans_half_kernel<<<dim3(CDIM / 32, HIDDEN / 32, 1), 256>>>(w_qkv, wqt, HIDDEN, CDIM);
    trans_half_kernel<<<dim3(HW / 32, CDIM / 32, BATCH), 256>>>(x, xt, CDIM, HW);

    // 1. [k;v] GEMM: expk fp16 (no-max softmax numerator), v fp16
    gemm1_kernel<<<dim3(HW / 128, 8, BATCH), 128, GEMM_SMEM>>>(wkv, xt, expk, v16);

    // 2. context split-partials + row sums
    ctx_kernel<<<dim3(SPLIT, 128), 256>>>(expk, v16, part, sums);

    // 3. Mcat = (W_out per-head) @ normalize(ctx)^T  (split-reduce fused)
    mcat_kernel<<<BATCH * HEADS, 256>>>(w_out, part, sums, mcat);

    // 4. Mcomb[b] = Mcat[b] @ Wq^T
    gemm_g_kernel<__half><<<dim3(CDIM / 128, HIDDEN / 128, BATCH), 128, GEMM_SMEM>>>(
        mcat, wqt, mcomb, nullptr,
        HIDDEN, CDIM, HIDDEN,
        (long)HIDDEN * HIDDEN, 0L, (long)HIDDEN * CDIM);

    // 5. y = Mcomb @ x + b_out
    gemm_g_kernel<float><<<dim3(HW / 128, HIDDEN / 128, BATCH), 128, GEMM_SMEM>>>(
        mcomb, xt, y, b_out,
        HIDDEN, HW, CDIM,
        (long)HIDDEN * CDIM, (long)HW * CDIM, (long)HIDDEN * HW);
}

// round 14
// speedup vs baseline: 5.2291x; 1.1901x over previous
#include <cuda_runtime.h>
#include <cuda_fp16.h>
#include <cstdint>

#define HEADS  8
#define DIMH   64
#define BATCH  16
#define CDIM   512
#define HW     4096
#define HIDDEN 512
#define NSPLIT 32
#define BH_TOT (BATCH * HEADS)

// ---------------- scratch (no allocations allowed) ----------------
__device__ __half g_x16[(size_t)BATCH * CDIM * HW];           // 67 MB, x fp16 natural [b][c][n]
__device__ __half g_part[(size_t)NSPLIT * BH_TOT * DIMH * DIMH]; // 33.5 MB fp16 ctx partials
__device__ float  g_sums[(size_t)NSPLIT * BH_TOT * DIMH];     // 1 MB
__device__ __half g_mcat[(size_t)BATCH * HIDDEN * HIDDEN];
__device__ __half g_mcomb[(size_t)BATCH * HIDDEN * CDIM];
__device__ __half g_wkv[(size_t)2 * HIDDEN * CDIM];           // head-blocked [h][k64;v64][512]
__device__ __half g_wq16[(size_t)HIDDEN * CDIM];              // Wq natural fp16

// ================= PTX helpers =================
__device__ __forceinline__ uint32_t smem_u32(const void* p) {
    uint32_t a;
    asm("{ .reg .u64 t; cvta.to.shared.u64 t, %1; cvt.u32.u64 %0, t; }"
        : "=r"(a) : "l"(p));
    return a;
}
__device__ __forceinline__ void cp_async16(uint32_t dst, const void* src) {
    asm volatile("cp.async.cg.shared.global [%0], [%1], 16;"
                 :: "r"(dst), "l"(src));
}
#define CP_COMMIT() asm volatile("cp.async.commit_group;")
#define CP_WAIT(n)  asm volatile("cp.async.wait_group %0;" :: "n"(n))

__device__ __forceinline__ void ldmx4(uint32_t* r, uint32_t addr) {
    asm volatile("ldmatrix.sync.aligned.m8n8.x4.shared.b16 {%0,%1,%2,%3}, [%4];"
                 : "=r"(r[0]), "=r"(r[1]), "=r"(r[2]), "=r"(r[3]) : "r"(addr));
}
__device__ __forceinline__ void ldmx4t(uint32_t* r, uint32_t addr) {
    asm volatile("ldmatrix.sync.aligned.m8n8.x4.trans.shared.b16 {%0,%1,%2,%3}, [%4];"
                 : "=r"(r[0]), "=r"(r[1]), "=r"(r[2]), "=r"(r[3]) : "r"(addr));
}
__device__ __forceinline__ void mma16816(float* d, const uint32_t* a,
                                         uint32_t b0, uint32_t b1) {
    asm volatile(
        "mma.sync.aligned.m16n8k16.row.col.f32.f16.f16.f32 "
        "{%0,%1,%2,%3}, {%4,%5,%6,%7}, {%8,%9}, {%0,%1,%2,%3};"
        : "+f"(d[0]), "+f"(d[1]), "+f"(d[2]), "+f"(d[3])
        : "r"(a[0]), "r"(a[1]), "r"(a[2]), "r"(a[3]), "r"(b0), "r"(b1));
}

// packed f32x2
__device__ __forceinline__ unsigned long long f32x2_dup(float a) {
    unsigned long long r;
    asm("mov.b64 %0, {%1, %1};" : "=l"(r) : "f"(a));
    return r;
}
__device__ __forceinline__ unsigned long long f32x2_fma(unsigned long long a,
                                                        unsigned long long b,
                                                        unsigned long long c) {
    unsigned long long d;
    asm("fma.rn.f32x2 %0, %1, %2, %3;" : "=l"(d) : "l"(a), "l"(b), "l"(c));
    return d;
}
__device__ __forceinline__ float2 f32x2_unpack(unsigned long long v) {
    float2 f;
    asm("mov.b64 {%0, %1}, %2;" : "=f"(f.x), "=f"(f.y) : "l"(v));
    return f;
}

// ================= GEMM config =================
// A: [m][k] rows, 128x32 fp16 (64B) padded to 80B. Non-trans ldmatrix.
// B: [k][n] rows, 32x128 fp16 (256B) padded to 272B. TRANS ldmatrix (17 16B-segs/row).
#define AROWB 80
#define BROWB 272
#define A_TILE (128 * AROWB)                 // 10240
#define B_TILE (32 * BROWB)                  // 8704
#define STAGE_BYTES (A_TILE + B_TILE)        // 18944
#define NSTAGE 4
#define GEMM_SMEM (NSTAGE * STAGE_BYTES)     // 75776
#define VTOFF 8320                           // float index of V tile in epilogue (after 64x130 K)

// ====== GEMM1 + fused ctx: per-CTA tile = one head's [k64;v64] x n128 ======
__global__ __launch_bounds__(128, 2) void gemm1ctx_kernel(
    const __half* __restrict__ Ah, const __half* __restrict__ B_,
    __half* __restrict__ part, float* __restrict__ sums)
{
    constexpr int K = CDIM, N = HW;
    extern __shared__ char smem[];
    const uint32_t sb = smem_u32(smem);

    const int t = threadIdx.x;
    const int lane = t & 31, wid = t >> 5;
    const int m_off = (wid & 1) * 64, n_off = (wid >> 1) * 64;
    const int m0 = blockIdx.y * 128;          // head block
    const int n0 = blockIdx.x * 128;          // split window
    const long z = blockIdx.z;
    const __half* Bh = B_ + z * (long)CDIM * HW;

    const uint32_t aBase = sb + (uint32_t)((m_off + (lane & 15)) * AROWB + (lane >> 4) * 16);
    const uint32_t bBase = sb + A_TILE +
        (uint32_t)(((lane & 7) + ((lane >> 3) & 1) * 8) * BROWB +
                   ((lane >> 4) & 1) * 16 + n_off * 2);

    float acc[4][8][4];
    #pragma unroll
    for (int i = 0; i < 4; i++)
        #pragma unroll
        for (int j = 0; j < 8; j++)
            #pragma unroll
            for (int r = 0; r < 4; r++) acc[i][j][r] = 0.f;

    const int nst = K / 32;

    auto load_stage = [&](int s) {
        const int k0 = s * 32;
        const uint32_t bufb = sb + (uint32_t)((s % NSTAGE) * STAGE_BYTES);
        #pragma unroll
        for (int p = 0; p < 4; p++) {                  // A: 128 rows x 64B
            int row = (t >> 2) + p * 32;
            cp_async16(bufb + (uint32_t)(row * AROWB + (t & 3) * 16),
                       Ah + (long)(m0 + row) * K + k0 + (t & 3) * 8);
        }
        #pragma unroll
        for (int p = 0; p < 4; p++) {                  // B: 32 rows x 256B
            int idx = t + p * 128;
            int krow = idx >> 4, nch = idx & 15;
            cp_async16(bufb + A_TILE + (uint32_t)(krow * BROWB + nch * 16),
                       Bh + (long)(k0 + krow) * N + n0 + nch * 8);
        }
        CP_COMMIT();
    };

    #pragma unroll
    for (int s = 0; s < NSTAGE - 1; s++) load_stage(s);

    for (int s = 0; s < nst; s++) {
        if (s + NSTAGE - 1 < nst) { load_stage(s + NSTAGE - 1); CP_WAIT(NSTAGE - 2); }
        else                      { CP_WAIT(0); }
        __syncthreads();

        const uint32_t bufo = (uint32_t)((s % NSTAGE) * STAGE_BYTES);
        #pragma unroll
        for (int ks = 0; ks < 2; ks++) {
            uint32_t bh[16];
            #pragma unroll
            for (int nj = 0; nj < 4; nj++)
                ldmx4t(&bh[nj * 4], bBase + bufo + (uint32_t)(ks * 16 * BROWB + nj * 32));
            #pragma unroll
            for (int mi = 0; mi < 4; mi++) {
                uint32_t ah[4];
                ldmx4(ah, aBase + bufo + (uint32_t)(mi * 16 * AROWB + ks * 32));
                #pragma unroll
                for (int j = 0; j < 8; j++) {
                    int bi = (j >> 1) * 4 + (j & 1) * 2;
                    mma16816(acc[mi][j], ah, bh[bi], bh[bi + 1]);
                }
            }
        }
        __syncthreads();
    }

    // ---- fused ctx epilogue (pipeline SMEM is dead; reuse) ----
    float* smf = (float*)smem;
    const int lr = lane >> 2;
    const int lc = (lane & 3) * 2;
    if ((wid & 1) == 0) {                         // k half -> KT[c][n] (exp)
        #pragma unroll
        for (int mi = 0; mi < 4; mi++)
            #pragma unroll
            for (int hf = 0; hf < 2; hf++) {
                int c = mi * 16 + hf * 8 + lr;
                #pragma unroll
                for (int j = 0; j < 8; j++) {
                    int n = n_off + j * 8 + lc;
                    smf[c * 130 + n]     = __expf(acc[mi][j][hf * 2 + 0]);
                    smf[c * 130 + n + 1] = __expf(acc[mi][j][hf * 2 + 1]);
                }
            }
    } else {                                      // v half -> VT[n][d]
        #pragma unroll
        for (int mi = 0; mi < 4; mi++)
            #pragma unroll
            for (int hf = 0; hf < 2; hf++) {
                int d = mi * 16 + hf * 8 + lr;
                #pragma unroll
                for (int j = 0; j < 8; j++) {
                    int n = n_off + j * 8 + lc;
                    smf[VTOFF + n * 66 + d]       = acc[mi][j][hf * 2 + 0];
                    smf[VTOFF + (n + 1) * 66 + d] = acc[mi][j][hf * 2 + 1];
                }
            }
    }
    __syncthreads();

    // ctx[c][d] = sum_n KT[c][n] * VT[n][d];  c0: 4 rows, d: 4 pairs strided 16
    const int c0 = (t >> 3) * 4;
    const int dg = t & 7;
    unsigned long long a2[4][4];
    #pragma unroll
    for (int i = 0; i < 4; i++)
        #pragma unroll
        for (int jj = 0; jj < 4; jj++) a2[i][jj] = 0ull;
    float ksum[4] = {0.f, 0.f, 0.f, 0.f};

    for (int nn = 0; nn < 128; nn++) {
        unsigned long long ap[4];
        #pragma unroll
        for (int i = 0; i < 4; i++) {
            float kv = smf[(c0 + i) * 130 + nn];
            ksum[i] += kv;
            ap[i] = f32x2_dup(kv);
        }
        #pragma unroll
        for (int jj = 0; jj < 4; jj++) {
            unsigned long long vv = *(const unsigned long long*)
                &smf[VTOFF + nn * 66 + dg * 2 + jj * 16];
            #pragma unroll
            for (int i = 0; i < 4; i++)
                a2[i][jj] = f32x2_fma(ap[i], vv, a2[i][jj]);
        }
    }

    const int bh = (int)z * HEADS + blockIdx.y;
    const int split = blockIdx.x;
    __half* dst = part + ((long)split * BH_TOT + bh) * 4096;
    #pragma unroll
    for (int i = 0; i < 4; i++) {
        #pragma unroll
        for (int jj = 0; jj < 4; jj++) {
            float2 p = f32x2_unpack(a2[i][jj]);
            *(__half2*)&dst[(c0 + i) * 64 + dg * 2 + jj * 16] =
                __floats2half2_rn(p.x, p.y);
        }
        if (dg == 0)
            sums[((long)split * BH_TOT + bh) * 64 + c0 + i] = ksum[i];
    }
}

// ======== generic fp16 HMMA GEMM: C[z] = A[z] @ B[z] (+bias), B is [k][n] ====
template<typename OutT>
__global__ __launch_bounds__(128, 2) void gemm_g_kernel(
    const __half* __restrict__ A_, const __half* __restrict__ B_,
    OutT* __restrict__ C, const float* __restrict__ bias,
    int M, int N, int K, long sA, long sB, long sC)
{
    extern __shared__ char smem[];
    const uint32_t sb = smem_u32(smem);

    const int t = threadIdx.x;
    const int lane = t & 31, wid = t >> 5;
    const int m_off = (wid & 1) * 64, n_off = (wid >> 1) * 64;
    const int m0 = blockIdx.y * 128, n0 = blockIdx.x * 128;
    const long z = blockIdx.z;
    const __half* Ah = A_ + z * sA;
    const __half* Bh = B_ + z * sB;

    const uint32_t aBase = sb + (uint32_t)((m_off + (lane & 15)) * AROWB + (lane >> 4) * 16);
    const uint32_t bBase = sb + A_TILE +
        (uint32_t)(((lane & 7) + ((lane >> 3) & 1) * 8) * BROWB +
                   ((lane >> 4) & 1) * 16 + n_off * 2);

    float acc[4][8][4];
    #pragma unroll
    for (int i = 0; i < 4; i++)
        #pragma unroll
        for (int j = 0; j < 8; j++)
            #pragma unroll
            for (int r = 0; r < 4; r++) acc[i][j][r] = 0.f;

    const int nst = K / 32;

    auto load_stage = [&](int s) {
        const int k0 = s * 32;
        const uint32_t bufb = sb + (uint32_t)((s % NSTAGE) * STAGE_BYTES);
        #pragma unroll
        for (int p = 0; p < 4; p++) {
            int row = (t >> 2) + p * 32;
            cp_async16(bufb + (uint32_t)(row * AROWB + (t & 3) * 16),
                       Ah + (long)(m0 + row) * K + k0 + (t & 3) * 8);
        }
        #pragma unroll
        for (int p = 0; p < 4; p++) {
            int idx = t + p * 128;
            int krow = idx >> 4, nch = idx & 15;
            cp_async16(bufb + A_TILE + (uint32_t)(krow * BROWB + nch * 16),
                       Bh + (long)(k0 + krow) * N + n0 + nch * 8);
        }
        CP_COMMIT();
    };

    #pragma unroll
    for (int s = 0; s < NSTAGE - 1; s++) load_stage(s);

    for (int s = 0; s < nst; s++) {
        if (s + NSTAGE - 1 < nst) { load_stage(s + NSTAGE - 1); CP_WAIT(NSTAGE - 2); }
        else                      { CP_WAIT(0); }
        __syncthreads();

        const uint32_t bufo = (uint32_t)((s % NSTAGE) * STAGE_BYTES);
        #pragma unroll
        for (int ks = 0; ks < 2; ks++) {
            uint32_t bh[16];
            #pragma unroll
            for (int nj = 0; nj < 4; nj++)
                ldmx4t(&bh[nj * 4], bBase + bufo + (uint32_t)(ks * 16 * BROWB + nj * 32));
            #pragma unroll
            for (int mi = 0; mi < 4; mi++) {
                uint32_t ah[4];
                ldmx4(ah, aBase + bufo + (uint32_t)(mi * 16 * AROWB + ks * 32));
                #pragma unroll
                for (int j = 0; j < 8; j++) {
                    int bi = (j >> 1) * 4 + (j & 1) * 2;
                    mma16816(acc[mi][j], ah, bh[bi], bh[bi + 1]);
                }
            }
        }
        __syncthreads();
    }

    OutT* Cz = C + z * sC;
    const int mrow = m0 + m_off + (lane >> 2);
    const int ncol = n0 + n_off + (lane & 3) * 2;
    #pragma unroll
    for (int mi = 0; mi < 4; mi++) {
        int r0 = mrow + mi * 16;
        float bv0 = bias ? bias[r0] : 0.f;
        float bv1 = bias ? bias[r0 + 8] : 0.f;
        #pragma unroll
        for (int j = 0; j < 8; j++) {
            int cc = ncol + j * 8;
            if constexpr (sizeof(OutT) == 4) {
                *(float2*)(Cz + (long)r0 * N + cc) =
                    make_float2(acc[mi][j][0] + bv0, acc[mi][j][1] + bv0);
                *(float2*)(Cz + (long)(r0 + 8) * N + cc) =
                    make_float2(acc[mi][j][2] + bv1, acc[mi][j][3] + bv1);
            } else {
                *(__half2*)(Cz + (long)r0 * N + cc) =
                    __floats2half2_rn(acc[mi][j][0] + bv0, acc[mi][j][1] + bv0);
                *(__half2*)(Cz + (long)(r0 + 8) * N + cc) =
                    __floats2half2_rn(acc[mi][j][2] + bv1, acc[mi][j][3] + bv1);
            }
        }
    }
}

// ================= conversion kernels =================
// vectorized f32 -> fp16, same layout (n must be multiple of 2048)
__global__ __launch_bounds__(256) void convx_kernel(
    const float* __restrict__ in, __half* __restrict__ out)
{
    long i = ((long)blockIdx.x * 256 + threadIdx.x) * 8;
    float4 a = *(const float4*)(in + i);
    float4 b = *(const float4*)(in + i + 4);
    __half2 h0 = __floats2half2_rn(a.x, a.y), h1 = __floats2half2_rn(a.z, a.w);
    __half2 h2 = __floats2half2_rn(b.x, b.y), h3 = __floats2half2_rn(b.z, b.w);
    uint4 o;
    o.x = *(uint32_t*)&h0; o.y = *(uint32_t*)&h1;
    o.z = *(uint32_t*)&h2; o.w = *(uint32_t*)&h3;
    *(uint4*)(out + i) = o;
}

// w_qkv k/v rows -> head-blocked fp16: row h*128 + {0..63: k_h, 64..127: v_h}
__global__ __launch_bounds__(256) void conv_wkv_kernel(
    const float* __restrict__ w, __half* __restrict__ wkv)
{
    int i = blockIdx.x * 256 + threadIdx.x;   // over 1024 * 128 float4 groups
    int r_new = i >> 7;
    int colg = i & 127;
    int h = r_new >> 7, wr = r_new & 127;
    int src_row = (wr < 64) ? (HIDDEN + h * 64 + wr)
                            : (2 * HIDDEN + h * 64 + (wr - 64));
    float4 a = *(const float4*)(w + (long)src_row * CDIM + colg * 4);
    __half2 h0 = __floats2half2_rn(a.x, a.y), h1 = __floats2half2_rn(a.z, a.w);
    *(__half2*)(wkv + (long)r_new * CDIM + colg * 4)     = h0;
    *(__half2*)(wkv + (long)r_new * CDIM + colg * 4 + 2) = h1;
}

// == Mcat[b][o][h*64+c] = sum_d w_out[o][h*64+d] * ctx_norm[b][h][c][d] ==
__global__ __launch_bounds__(256) void mcat_kernel(const float* __restrict__ wo,
                                                   const __half* __restrict__ part,
                                                   const float* __restrict__ sums,
                                                   __half* __restrict__ mcat)
{
    __shared__ float ctxs[64][66];
    __shared__ float wos[64][66];
    __shared__ float invs[64];
    int bh = blockIdx.x;
    int b = bh >> 3, h = bh & 7;
    int t = threadIdx.x;
    int og = (t >> 4) * 4, cg = (t & 15) * 4;

    if (t < 64) {
        float s = 0.f;
        #pragma unroll 8
        for (int sp = 0; sp < NSPLIT; sp++)
            s += sums[((long)sp * BH_TOT + bh) * 64 + t];
        invs[t] = 1.0f / s;
    }
    __syncthreads();
    for (int i0 = t * 2; i0 < 4096; i0 += 512) {
        float sx = 0.f, sy = 0.f;
        #pragma unroll 8
        for (int sp = 0; sp < NSPLIT; sp++) {
            __half2 hp = *(const __half2*)&part[((long)sp * BH_TOT + bh) * 4096 + i0];
            float2 f = __half22float2(hp);
            sx += f.x; sy += f.y;
        }
        int c = i0 >> 6, d = i0 & 63;
        ctxs[c][d]     = sx * invs[c];
        ctxs[c][d + 1] = sy * invs[c];
    }

    for (int o0 = 0; o0 < HIDDEN; o0 += 64) {
        __syncthreads();
        for (int i = t; i < 4096; i += 256)
            wos[i >> 6][i & 63] = wo[(long)(o0 + (i >> 6)) * HIDDEN + h * 64 + (i & 63)];
        __syncthreads();

        unsigned long long acc2[4][4];
        #pragma unroll
        for (int i = 0; i < 4; i++)
            #pragma unroll
            for (int j = 0; j < 4; j++) acc2[i][j] = 0ull;

        #pragma unroll 8
        for (int d2 = 0; d2 < 64; d2 += 2) {
            unsigned long long av[4], bv[4];
            #pragma unroll
            for (int i = 0; i < 4; i++)
                av[i] = *(const unsigned long long*)&wos[og + i][d2];
            #pragma unroll
            for (int j = 0; j < 4; j++)
                bv[j] = *(const unsigned long long*)&ctxs[cg + j][d2];
            #pragma unroll
            for (int i = 0; i < 4; i++)
                #pragma unroll
                for (int j = 0; j < 4; j++)
                    acc2[i][j] = f32x2_fma(av[i], bv[j], acc2[i][j]);
        }
        #pragma unroll
        for (int i = 0; i < 4; i++) {
            float r[4];
            #pragma unroll
            for (int j = 0; j < 4; j++) {
                float2 p = f32x2_unpack(acc2[i][j]);
                r[j] = p.x + p.y;
            }
            __half* dp = mcat + ((long)b * HIDDEN + o0 + og + i) * HIDDEN + h * 64 + cg;
            *(__half2*)(dp)     = __floats2half2_rn(r[0], r[1]);
            *(__half2*)(dp + 2) = __floats2half2_rn(r[2], r[3]);
        }
    }
}

// ================= launch =================
extern "C" void kernel_launch(void* const* d_in, const int* in_sizes, int n_in,
                              void* d_out, int out_size)
{
    const float* x     = (const float*)d_in[0];   // (16,512,64,64)
    const float* w_qkv = (const float*)d_in[1];   // (1536,512): [q;k;v]
    const float* w_out = (const float*)d_in[2];   // (512,512)
    const float* b_out = (const float*)d_in[3];   // (512,)
    float* y = (float*)d_out;

    float* sums;
    __half *x16, *part, *mcat, *mcomb, *wkv, *wq16;
    cudaGetSymbolAddress((void**)&x16,   g_x16);
    cudaGetSymbolAddress((void**)&part,  g_part);
    cudaGetSymbolAddress((void**)&sums,  g_sums);
    cudaGetSymbolAddress((void**)&mcat,  g_mcat);
    cudaGetSymbolAddress((void**)&mcomb, g_mcomb);
    cudaGetSymbolAddress((void**)&wkv,   g_wkv);
    cudaGetSymbolAddress((void**)&wq16,  g_wq16);

    cudaFuncSetAttribute(gemm1ctx_kernel,
                         cudaFuncAttributeMaxDynamicSharedMemorySize, GEMM_SMEM);
    cudaFuncSetAttribute(gemm_g_kernel<__half>,
                         cudaFuncAttributeMaxDynamicSharedMemorySize, GEMM_SMEM);
    cudaFuncSetAttribute(gemm_g_kernel<float>,
                         cudaFuncAttributeMaxDynamicSharedMemorySize, GEMM_SMEM);

    // 0. conversions (all layout-preserving except head-block permute of wkv)
    convx_kernel<<<(int)(((long)BATCH * CDIM * HW) / 2048), 256>>>(x, x16);
    convx_kernel<<<(HIDDEN * CDIM) / 2048, 256>>>(w_qkv, wq16);     // Wq natural
    conv_wkv_kernel<<<(2 * HIDDEN * CDIM / 4) / 256, 256>>>(w_qkv, wkv);

    // 1. fused [k;v] GEMM + exp + ctx partials + row sums
    gemm1ctx_kernel<<<dim3(NSPLIT, HEADS, BATCH), 128, GEMM_SMEM>>>(
        wkv, x16, part, sums);

    // 2. Mcat = (W_out per-head) @ normalize(ctx)^T  (split-reduce fused)
    mcat_kernel<<<BH_TOT, 256>>>(w_out, part, sums, mcat);

    // 3. Mcomb[b] = Mcat[b] @ Wq   (B = Wq natural [k][n])
    gemm_g_kernel<__half><<<dim3(CDIM / 128, HIDDEN / 128, BATCH), 128, GEMM_SMEM>>>(
        mcat, wq16, mcomb, nullptr,
        HIDDEN, CDIM, HIDDEN,
        (long)HIDDEN * HIDDEN, 0L, (long)HIDDEN * CDIM);

    // 4. y = Mcomb @ x + b_out   (B = x16 natural [c][n])
    gemm_g_kernel<float><<<dim3(HW / 128, HIDDEN / 128, BATCH), 128, GEMM_SMEM>>>(
        mcomb, x16, y, b_out,
        HIDDEN, HW, CDIM,
        (long)HIDDEN * CDIM, (long)CDIM * HW, (long)HIDDEN * HW);
}

// round 15
// speedup vs baseline: 6.1423x; 1.1746x over previous
#include <cuda_runtime.h>
#include <cuda_fp16.h>
#include <cstdint>

#define HEADS  8
#define DIMH   64
#define BATCH  16
#define CDIM   512
#define HW     4096
#define HIDDEN 512
#define NSPLIT 32
#define BH_TOT (BATCH * HEADS)

// ---------------- scratch (no allocations allowed) ----------------
__device__ __half g_x16[(size_t)BATCH * CDIM * HW];           // 67 MB, x fp16 natural [b][c][n]
__device__ __half g_part[(size_t)NSPLIT * BH_TOT * DIMH * DIMH]; // 33.5 MB fp16 ctx partials
__device__ float  g_sums[(size_t)NSPLIT * BH_TOT * DIMH];     // 1 MB
__device__ __half g_mcat[(size_t)BATCH * HIDDEN * HIDDEN];
__device__ __half g_mcomb[(size_t)BATCH * HIDDEN * CDIM];
__device__ __half g_wkv[(size_t)2 * HIDDEN * CDIM];           // head-blocked [h][k64;v64][512]
__device__ __half g_wq16[(size_t)HIDDEN * CDIM];              // Wq natural fp16

// ================= PTX helpers =================
__device__ __forceinline__ uint32_t smem_u32(const void* p) {
    uint32_t a;
    asm("{ .reg .u64 t; cvta.to.shared.u64 t, %1; cvt.u32.u64 %0, t; }"
        : "=r"(a) : "l"(p));
    return a;
}
__device__ __forceinline__ void cp_async16(uint32_t dst, const void* src) {
    asm volatile("cp.async.cg.shared.global [%0], [%1], 16;"
                 :: "r"(dst), "l"(src));
}
#define CP_COMMIT() asm volatile("cp.async.commit_group;")
#define CP_WAIT(n)  asm volatile("cp.async.wait_group %0;" :: "n"(n))

__device__ __forceinline__ void ldmx4(uint32_t* r, uint32_t addr) {
    asm volatile("ldmatrix.sync.aligned.m8n8.x4.shared.b16 {%0,%1,%2,%3}, [%4];"
                 : "=r"(r[0]), "=r"(r[1]), "=r"(r[2]), "=r"(r[3]) : "r"(addr));
}
__device__ __forceinline__ void ldmx4t(uint32_t* r, uint32_t addr) {
    asm volatile("ldmatrix.sync.aligned.m8n8.x4.trans.shared.b16 {%0,%1,%2,%3}, [%4];"
                 : "=r"(r[0]), "=r"(r[1]), "=r"(r[2]), "=r"(r[3]) : "r"(addr));
}
__device__ __forceinline__ void mma16816(float* d, const uint32_t* a,
                                         uint32_t b0, uint32_t b1) {
    asm volatile(
        "mma.sync.aligned.m16n8k16.row.col.f32.f16.f16.f32 "
        "{%0,%1,%2,%3}, {%4,%5,%6,%7}, {%8,%9}, {%0,%1,%2,%3};"
        : "+f"(d[0]), "+f"(d[1]), "+f"(d[2]), "+f"(d[3])
        : "r"(a[0]), "r"(a[1]), "r"(a[2]), "r"(a[3]), "r"(b0), "r"(b1));
}

// packed f32x2
__device__ __forceinline__ unsigned long long f32x2_dup(float a) {
    unsigned long long r;
    asm("mov.b64 %0, {%1, %1};" : "=l"(r) : "f"(a));
    return r;
}
__device__ __forceinline__ unsigned long long f32x2_fma(unsigned long long a,
                                                        unsigned long long b,
                                                        unsigned long long c) {
    unsigned long long d;
    asm("fma.rn.f32x2 %0, %1, %2, %3;" : "=l"(d) : "l"(a), "l"(b), "l"(c));
    return d;
}
__device__ __forceinline__ float2 f32x2_unpack(unsigned long long v) {
    float2 f;
    asm("mov.b64 {%0, %1}, %2;" : "=f"(f.x), "=f"(f.y) : "l"(v));
    return f;
}

// ================= GEMM config =================
// A: [m][k] rows, 128x32 fp16 (64B) padded to 80B. Non-trans ldmatrix.
// B: [k][n] rows, 32x128 fp16 (256B) padded to 272B. TRANS ldmatrix.
#define AROWB 80
#define BROWB 272
#define A_TILE (128 * AROWB)                 // 10240
#define B_TILE (32 * BROWB)                  // 8704
#define STAGE_BYTES (A_TILE + B_TILE)        // 18944
#define NSTAGE 4
#define GEMM_SMEM (NSTAGE * STAGE_BYTES)     // 75776
// epilogue fp16 tiles: KT [64c][128n], VT [64d][128n], rows 272B
#define CROWB 272
#define KT_OFF 0
#define VT_OFF (64 * CROWB)                  // 17408 bytes

// ====== GEMM1 + fused ctx (HMMA epilogue) ======
__global__ __launch_bounds__(128, 2) void gemm1ctx_kernel(
    const __half* __restrict__ Ah, const __half* __restrict__ B_,
    __half* __restrict__ part, float* __restrict__ sums)
{
    constexpr int K = CDIM, N = HW;
    extern __shared__ char smem[];
    const uint32_t sb = smem_u32(smem);

    const int t = threadIdx.x;
    const int lane = t & 31, wid = t >> 5;
    const int m_off = (wid & 1) * 64, n_off = (wid >> 1) * 64;
    const int m0 = blockIdx.y * 128;          // head block
    const int n0 = blockIdx.x * 128;          // split window
    const long z = blockIdx.z;
    const __half* Bh = B_ + z * (long)CDIM * HW;

    const uint32_t aBase = sb + (uint32_t)((m_off + (lane & 15)) * AROWB + (lane >> 4) * 16);
    const uint32_t bBase = sb + A_TILE +
        (uint32_t)(((lane & 7) + ((lane >> 3) & 1) * 8) * BROWB +
                   ((lane >> 4) & 1) * 16 + n_off * 2);

    float acc[4][8][4];
    #pragma unroll
    for (int i = 0; i < 4; i++)
        #pragma unroll
        for (int j = 0; j < 8; j++)
            #pragma unroll
            for (int r = 0; r < 4; r++) acc[i][j][r] = 0.f;

    const int nst = K / 32;

    auto load_stage = [&](int s) {
        const int k0 = s * 32;
        const uint32_t bufb = sb + (uint32_t)((s % NSTAGE) * STAGE_BYTES);
        #pragma unroll
        for (int p = 0; p < 4; p++) {                  // A: 128 rows x 64B
            int row = (t >> 2) + p * 32;
            cp_async16(bufb + (uint32_t)(row * AROWB + (t & 3) * 16),
                       Ah + (long)(m0 + row) * K + k0 + (t & 3) * 8);
        }
        #pragma unroll
        for (int p = 0; p < 4; p++) {                  // B: 32 rows x 256B
            int idx = t + p * 128;
            int krow = idx >> 4, nch = idx & 15;
            cp_async16(bufb + A_TILE + (uint32_t)(krow * BROWB + nch * 16),
                       Bh + (long)(k0 + krow) * N + n0 + nch * 8);
        }
        CP_COMMIT();
    };

    #pragma unroll
    for (int s = 0; s < NSTAGE - 1; s++) load_stage(s);

    for (int s = 0; s < nst; s++) {
        if (s + NSTAGE - 1 < nst) { load_stage(s + NSTAGE - 1); CP_WAIT(NSTAGE - 2); }
        else                      { CP_WAIT(0); }
        __syncthreads();

        const uint32_t bufo = (uint32_t)((s % NSTAGE) * STAGE_BYTES);
        #pragma unroll
        for (int ks = 0; ks < 2; ks++) {
            uint32_t bh[16];
            #pragma unroll
            for (int nj = 0; nj < 4; nj++)
                ldmx4t(&bh[nj * 4], bBase + bufo + (uint32_t)(ks * 16 * BROWB + nj * 32));
            #pragma unroll
            for (int mi = 0; mi < 4; mi++) {
                uint32_t ah[4];
                ldmx4(ah, aBase + bufo + (uint32_t)(mi * 16 * AROWB + ks * 32));
                #pragma unroll
                for (int j = 0; j < 8; j++) {
                    int bi = (j >> 1) * 4 + (j & 1) * 2;
                    mma16816(acc[mi][j], ah, bh[bi], bh[bi + 1]);
                }
            }
        }
        __syncthreads();
    }

    // ---- fused ctx epilogue: fp16 tiles + HMMA ----
    const int lr = lane >> 2;
    const int lc = (lane & 3) * 2;
    const int isV = wid & 1;
    {
        char* base = smem + (isV ? VT_OFF : KT_OFF);
        #pragma unroll
        for (int mi = 0; mi < 4; mi++)
            #pragma unroll
            for (int hf = 0; hf < 2; hf++) {
                int r = mi * 16 + hf * 8 + lr;            // c (k half) or d (v half)
                #pragma unroll
                for (int j = 0; j < 8; j++) {
                    int n = n_off + j * 8 + lc;
                    float a = acc[mi][j][hf * 2 + 0];
                    float b = acc[mi][j][hf * 2 + 1];
                    __half2 hv = isV ? __floats2half2_rn(a, b)
                                     : __floats2half2_rn(__expf(a), __expf(b));
                    *(__half2*)(base + r * CROWB + n * 2) = hv;
                }
            }
    }
    __syncthreads();

    const int bh_idx = (int)z * HEADS + blockIdx.y;
    const int split = blockIdx.x;

    // row sums of exp(k): 64 threads, one KT row each
    if (t < 64) {
        const uint4* rp = (const uint4*)(smem + KT_OFF + t * CROWB);
        float s = 0.f;
        #pragma unroll
        for (int i = 0; i < 16; i++) {
            uint4 v = rp[i];
            float2 f;
            f = __half22float2(*(__half2*)&v.x); s += f.x + f.y;
            f = __half22float2(*(__half2*)&v.y); s += f.x + f.y;
            f = __half22float2(*(__half2*)&v.z); s += f.x + f.y;
            f = __half22float2(*(__half2*)&v.w); s += f.x + f.y;
        }
        sums[((long)split * BH_TOT + bh_idx) * 64 + t] = s;
    }

    // ctx[c][d] = KT @ VT^T : m=64(c), n=64(d), k=128(n). Warp w: c-slice 16.
    const int c_off = wid * 16;
    const uint32_t aB2 = sb + KT_OFF +
        (uint32_t)((c_off + (lane & 15)) * CROWB + (lane >> 4) * 16);
    const uint32_t bB2 = sb + VT_OFF +
        (uint32_t)(((lane & 7) + ((lane >> 4) << 3)) * CROWB + ((lane >> 3) & 1) * 16);

    float accc[8][4];
    #pragma unroll
    for (int j = 0; j < 8; j++)
        #pragma unroll
        for (int r = 0; r < 4; r++) accc[j][r] = 0.f;

    #pragma unroll
    for (int ks = 0; ks < 8; ks++) {
        uint32_t ah[4];
        ldmx4(ah, aB2 + (uint32_t)(ks * 32));
        uint32_t bh2[16];
        #pragma unroll
        for (int nj = 0; nj < 4; nj++)
            ldmx4(&bh2[nj * 4], bB2 + (uint32_t)(nj * 16 * CROWB + ks * 32));
        #pragma unroll
        for (int j = 0; j < 8; j++) {
            int bi = (j >> 1) * 4 + (j & 1) * 2;
            mma16816(accc[j], ah, bh2[bi], bh2[bi + 1]);
        }
    }

    __half* dst = part + ((long)split * BH_TOT + bh_idx) * 4096;
    const int cr = c_off + (lane >> 2);
    const int dc = (lane & 3) * 2;
    #pragma unroll
    for (int j = 0; j < 8; j++) {
        int d = dc + j * 8;
        *(__half2*)&dst[cr * 64 + d] =
            __floats2half2_rn(accc[j][0], accc[j][1]);
        *(__half2*)&dst[(cr + 8) * 64 + d] =
            __floats2half2_rn(accc[j][2], accc[j][3]);
    }
}

// ======== generic fp16 HMMA GEMM: C[z] = A[z] @ B[z] (+bias), B is [k][n] ====
template<typename OutT>
__global__ __launch_bounds__(128, 2) void gemm_g_kernel(
    const __half* __restrict__ A_, const __half* __restrict__ B_,
    OutT* __restrict__ C, const float* __restrict__ bias,
    int M, int N, int K, long sA, long sB, long sC)
{
    extern __shared__ char smem[];
    const uint32_t sb = smem_u32(smem);

    const int t = threadIdx.x;
    const int lane = t & 31, wid = t >> 5;
    const int m_off = (wid & 1) * 64, n_off = (wid >> 1) * 64;
    const int m0 = blockIdx.y * 128, n0 = blockIdx.x * 128;
    const long z = blockIdx.z;
    const __half* Ah = A_ + z * sA;
    const __half* Bh = B_ + z * sB;

    const uint32_t aBase = sb + (uint32_t)((m_off + (lane & 15)) * AROWB + (lane >> 4) * 16);
    const uint32_t bBase = sb + A_TILE +
        (uint32_t)(((lane & 7) + ((lane >> 3) & 1) * 8) * BROWB +
                   ((lane >> 4) & 1) * 16 + n_off * 2);

    float acc[4][8][4];
    #pragma unroll
    for (int i = 0; i < 4; i++)
        #pragma unroll
        for (int j = 0; j < 8; j++)
            #pragma unroll
            for (int r = 0; r < 4; r++) acc[i][j][r] = 0.f;

    const int nst = K / 32;

    auto load_stage = [&](int s) {
        const int k0 = s * 32;
        const uint32_t bufb = sb + (uint32_t)((s % NSTAGE) * STAGE_BYTES);
        #pragma unroll
        for (int p = 0; p < 4; p++) {
            int row = (t >> 2) + p * 32;
            cp_async16(bufb + (uint32_t)(row * AROWB + (t & 3) * 16),
                       Ah + (long)(m0 + row) * K + k0 + (t & 3) * 8);
        }
        #pragma unroll
        for (int p = 0; p < 4; p++) {
            int idx = t + p * 128;
            int krow = idx >> 4, nch = idx & 15;
            cp_async16(bufb + A_TILE + (uint32_t)(krow * BROWB + nch * 16),
                       Bh + (long)(k0 + krow) * N + n0 + nch * 8);
        }
        CP_COMMIT();
    };

    #pragma unroll
    for (int s = 0; s < NSTAGE - 1; s++) load_stage(s);

    for (int s = 0; s < nst; s++) {
        if (s + NSTAGE - 1 < nst) { load_stage(s + NSTAGE - 1); CP_WAIT(NSTAGE - 2); }
        else                      { CP_WAIT(0); }
        __syncthreads();

        const uint32_t bufo = (uint32_t)((s % NSTAGE) * STAGE_BYTES);
        #pragma unroll
        for (int ks = 0; ks < 2; ks++) {
            uint32_t bh[16];
            #pragma unroll
            for (int nj = 0; nj < 4; nj++)
                ldmx4t(&bh[nj * 4], bBase + bufo + (uint32_t)(ks * 16 * BROWB + nj * 32));
            #pragma unroll
            for (int mi = 0; mi < 4; mi++) {
                uint32_t ah[4];
                ldmx4(ah, aBase + bufo + (uint32_t)(mi * 16 * AROWB + ks * 32));
                #pragma unroll
                for (int j = 0; j < 8; j++) {
                    int bi = (j >> 1) * 4 + (j & 1) * 2;
                    mma16816(acc[mi][j], ah, bh[bi], bh[bi + 1]);
                }
            }
        }
        __syncthreads();
    }

    OutT* Cz = C + z * sC;
    const int mrow = m0 + m_off + (lane >> 2);
    const int ncol = n0 + n_off + (lane & 3) * 2;
    #pragma unroll
    for (int mi = 0; mi < 4; mi++) {
        int r0 = mrow + mi * 16;
        float bv0 = bias ? bias[r0] : 0.f;
        float bv1 = bias ? bias[r0 + 8] : 0.f;
        #pragma unroll
        for (int j = 0; j < 8; j++) {
            int cc = ncol + j * 8;
            if constexpr (sizeof(OutT) == 4) {
                *(float2*)(Cz + (long)r0 * N + cc) =
                    make_float2(acc[mi][j][0] + bv0, acc[mi][j][1] + bv0);
                *(float2*)(Cz + (long)(r0 + 8) * N + cc) =
                    make_float2(acc[mi][j][2] + bv1, acc[mi][j][3] + bv1);
            } else {
                *(__half2*)(Cz + (long)r0 * N + cc) =
                    __floats2half2_rn(acc[mi][j][0] + bv0, acc[mi][j][1] + bv0);
                *(__half2*)(Cz + (long)(r0 + 8) * N + cc) =
                    __floats2half2_rn(acc[mi][j][2] + bv1, acc[mi][j][3] + bv1);
            }
        }
    }
}

// ================= conversion kernels =================
__global__ __launch_bounds__(256) void convx_kernel(
    const float* __restrict__ in, __half* __restrict__ out)
{
    long i = ((long)blockIdx.x * 256 + threadIdx.x) * 8;
    float4 a = *(const float4*)(in + i);
    float4 b = *(const float4*)(in + i + 4);
    __half2 h0 = __floats2half2_rn(a.x, a.y), h1 = __floats2half2_rn(a.z, a.w);
    __half2 h2 = __floats2half2_rn(b.x, b.y), h3 = __floats2half2_rn(b.z, b.w);
    uint4 o;
    o.x = *(uint32_t*)&h0; o.y = *(uint32_t*)&h1;
    o.z = *(uint32_t*)&h2; o.w = *(uint32_t*)&h3;
    *(uint4*)(out + i) = o;
}

// w_qkv k/v rows -> head-blocked fp16: row h*128 + {0..63: k_h, 64..127: v_h}
__global__ __launch_bounds__(256) void conv_wkv_kernel(
    const float* __restrict__ w, __half* __restrict__ wkv)
{
    int i = blockIdx.x * 256 + threadIdx.x;
    int r_new = i >> 7;
    int colg = i & 127;
    int h = r_new >> 7, wr = r_new & 127;
    int src_row = (wr < 64) ? (HIDDEN + h * 64 + wr)
                            : (2 * HIDDEN + h * 64 + (wr - 64));
    float4 a = *(const float4*)(w + (long)src_row * CDIM + colg * 4);
    __half2 h0 = __floats2half2_rn(a.x, a.y), h1 = __floats2half2_rn(a.z, a.w);
    *(__half2*)(wkv + (long)r_new * CDIM + colg * 4)     = h0;
    *(__half2*)(wkv + (long)r_new * CDIM + colg * 4 + 2) = h1;
}

// == Mcat[b][o][h*64+c] = sum_d w_out[o][h*64+d] * ctx_norm[b][h][c][d] ==
__global__ __launch_bounds__(256) void mcat_kernel(const float* __restrict__ wo,
                                                   const __half* __restrict__ part,
                                                   const float* __restrict__ sums,
                                                   __half* __restrict__ mcat)
{
    __shared__ float ctxs[64][66];
    __shared__ float wos[64][66];
    __shared__ float invs[64];
    int bh = blockIdx.x;
    int b = bh >> 3, h = bh & 7;
    int t = threadIdx.x;
    int og = (t >> 4) * 4, cg = (t & 15) * 4;

    if (t < 64) {
        float s = 0.f;
        #pragma unroll 8
        for (int sp = 0; sp < NSPLIT; sp++)
            s += sums[((long)sp * BH_TOT + bh) * 64 + t];
        invs[t] = 1.0f / s;
    }
    __syncthreads();
    for (int i0 = t * 2; i0 < 4096; i0 += 512) {
        float sx = 0.f, sy = 0.f;
        #pragma unroll 8
        for (int sp = 0; sp < NSPLIT; sp++) {
            __half2 hp = *(const __half2*)&part[((long)sp * BH_TOT + bh) * 4096 + i0];
            float2 f = __half22float2(hp);
            sx += f.x; sy += f.y;
        }
        int c = i0 >> 6, d = i0 & 63;
        ctxs[c][d]     = sx * invs[c];
        ctxs[c][d + 1] = sy * invs[c];
    }

    for (int o0 = 0; o0 < HIDDEN; o0 += 64) {
        __syncthreads();
        for (int i = t; i < 4096; i += 256)
            wos[i >> 6][i & 63] = wo[(long)(o0 + (i >> 6)) * HIDDEN + h * 64 + (i & 63)];
        __syncthreads();

        unsigned long long acc2[4][4];
        #pragma unroll
        for (int i = 0; i < 4; i++)
            #pragma unroll
            for (int j = 0; j < 4; j++) acc2[i][j] = 0ull;

        #pragma unroll 8
        for (int d2 = 0; d2 < 64; d2 += 2) {
            unsigned long long av[4], bv[4];
            #pragma unroll
            for (int i = 0; i < 4; i++)
                av[i] = *(const unsigned long long*)&wos[og + i][d2];
            #pragma unroll
            for (int j = 0; j < 4; j++)
                bv[j] = *(const unsigned long long*)&ctxs[cg + j][d2];
            #pragma unroll
            for (int i = 0; i < 4; i++)
                #pragma unroll
                for (int j = 0; j < 4; j++)
                    acc2[i][j] = f32x2_fma(av[i], bv[j], acc2[i][j]);
        }
        #pragma unroll
        for (int i = 0; i < 4; i++) {
            float r[4];
            #pragma unroll
            for (int j = 0; j < 4; j++) {
                float2 p = f32x2_unpack(acc2[i][j]);
                r[j] = p.x + p.y;
            }
            __half* dp = mcat + ((long)b * HIDDEN + o0 + og + i) * HIDDEN + h * 64 + cg;
            *(__half2*)(dp)     = __floats2half2_rn(r[0], r[1]);
            *(__half2*)(dp + 2) = __floats2half2_rn(r[2], r[3]);
        }
    }
}

// ================= launch =================
extern "C" void kernel_launch(void* const* d_in, const int* in_sizes, int n_in,
                              void* d_out, int out_size)
{
    const float* x     = (const float*)d_in[0];   // (16,512,64,64)
    const float* w_qkv = (const float*)d_in[1];   // (1536,512): [q;k;v]
    const float* w_out = (const float*)d_in[2];   // (512,512)
    const float* b_out = (const float*)d_in[3];   // (512,)
    float* y = (float*)d_out;

    float* sums;
    __half *x16, *part, *mcat, *mcomb, *wkv, *wq16;
    cudaGetSymbolAddress((void**)&x16,   g_x16);
    cudaGetSymbolAddress((void**)&part,  g_part);
    cudaGetSymbolAddress((void**)&sums,  g_sums);
    cudaGetSymbolAddress((void**)&mcat,  g_mcat);
    cudaGetSymbolAddress((void**)&mcomb, g_mcomb);
    cudaGetSymbolAddress((void**)&wkv,   g_wkv);
    cudaGetSymbolAddress((void**)&wq16,  g_wq16);

    cudaFuncSetAttribute(gemm1ctx_kernel,
                         cudaFuncAttributeMaxDynamicSharedMemorySize, GEMM_SMEM);
    cudaFuncSetAttribute(gemm_g_kernel<__half>,
                         cudaFuncAttributeMaxDynamicSharedMemorySize, GEMM_SMEM);
    cudaFuncSetAttribute(gemm_g_kernel<float>,
                         cudaFuncAttributeMaxDynamicSharedMemorySize, GEMM_SMEM);

    // 0. conversions
    convx_kernel<<<(int)(((long)BATCH * CDIM * HW) / 2048), 256>>>(x, x16);
    convx_kernel<<<(HIDDEN * CDIM) / 2048, 256>>>(w_qkv, wq16);     // Wq natural
    conv_wkv_kernel<<<(2 * HIDDEN * CDIM / 4) / 256, 256>>>(w_qkv, wkv);

    // 1. fused [k;v] GEMM + exp + ctx partials (HMMA) + row sums
    gemm1ctx_kernel<<<dim3(NSPLIT, HEADS, BATCH), 128, GEMM_SMEM>>>(
        wkv, x16, part, sums);

    // 2. Mcat = (W_out per-head) @ normalize(ctx)^T  (split-reduce fused)
    mcat_kernel<<<BH_TOT, 256>>>(w_out, part, sums, mcat);

    // 3. Mcomb[b] = Mcat[b] @ Wq   (B = Wq natural [k][n])
    gemm_g_kernel<__half><<<dim3(CDIM / 128, HIDDEN / 128, BATCH), 128, GEMM_SMEM>>>(
        mcat, wq16, mcomb, nullptr,
        HIDDEN, CDIM, HIDDEN,
        (long)HIDDEN * HIDDEN, 0L, (long)HIDDEN * CDIM);

    // 4. y = Mcomb @ x + b_out   (B = x16 natural [c][n])
    gemm_g_kernel<float><<<dim3(HW / 128, HIDDEN / 128, BATCH), 128, GEMM_SMEM>>>(
        mcomb, x16, y, b_out,
        HIDDEN, HW, CDIM,
        (long)HIDDEN * CDIM, (long)CDIM * HW, (long)HIDDEN * HW);
}